// round 10
// baseline (speedup 1.0000x reference)
#include <cuda_runtime.h>
#include <cuda_bf16.h>
#include <math.h>
#include <stdint.h>

#define S_LEN   2048
#define BATCH   2
#define NHEADS  32
#define NKV     8
#define HDIM    128
#define HID     4096
#define KVDIM   1024
#define M_ROWS  4096   // B*S
#define WINDOW  512    // SLIDING_WINDOW // 2
#define GK      4096   // GEMM K
#define NC      (GK/64)

// ======================== scratch buffers ==================================
__device__ __nv_bfloat16 g_Xhi[(size_t)M_ROWS * HID];
__device__ __nv_bfloat16 g_Xlo[(size_t)M_ROWS * HID];
__device__ __nv_bfloat16 g_WqThi[(size_t)HID * HID];
__device__ __nv_bfloat16 g_WqTlo[(size_t)HID * HID];
__device__ __nv_bfloat16 g_WkThi[(size_t)KVDIM * HID];
__device__ __nv_bfloat16 g_WkTlo[(size_t)KVDIM * HID];
__device__ __nv_bfloat16 g_WvThi[(size_t)KVDIM * HID];
__device__ __nv_bfloat16 g_WvTlo[(size_t)KVDIM * HID];
__device__ __nv_bfloat16 g_WoThi[(size_t)HID * HID];
__device__ __nv_bfloat16 g_WoTlo[(size_t)HID * HID];
__device__ __nv_bfloat16 g_Ohi[(size_t)M_ROWS * HID];
__device__ __nv_bfloat16 g_Olo[(size_t)M_ROWS * HID];

// bf16 attention operands (RoPE'd)
__device__ __nv_bfloat16 g_Qbh[(size_t)BATCH * NHEADS * S_LEN * HDIM];
__device__ __nv_bfloat16 g_Qbl[(size_t)BATCH * NHEADS * S_LEN * HDIM];
__device__ __nv_bfloat16 g_Kbh[(size_t)BATCH * NKV * S_LEN * HDIM];
__device__ __nv_bfloat16 g_Kbl[(size_t)BATCH * NKV * S_LEN * HDIM];
__device__ __nv_bfloat16 g_Vth[(size_t)BATCH * NKV * HDIM * S_LEN];  // [b,hk,d,s]
__device__ __nv_bfloat16 g_Vtl[(size_t)BATCH * NKV * HDIM * S_LEN];

// ======================= low-level helpers =================================
__device__ __forceinline__ uint32_t smem_u32(const void* p) {
    uint32_t a;
    asm("{ .reg .u64 t; cvta.to.shared.u64 t, %1; cvt.u32.u64 %0, t; }"
        : "=r"(a) : "l"(p));
    return a;
}
__device__ __forceinline__ void cpasync16(uint32_t saddr, const void* g) {
    asm volatile("cp.async.cg.shared.global [%0], [%1], 16;"
                 :: "r"(saddr), "l"(g) : "memory");
}
#define SWZ(o) ((o) ^ (((o) >> 3) & 0x70))

__device__ __forceinline__ void ldmx4(uint32_t* r, uint32_t addr) {
    asm volatile("ldmatrix.sync.aligned.m8n8.x4.shared.b16 {%0,%1,%2,%3}, [%4];"
                 : "=r"(r[0]), "=r"(r[1]), "=r"(r[2]), "=r"(r[3]) : "r"(addr));
}
__device__ __forceinline__ void mma16816(float* d, const uint32_t* a, const uint32_t* b) {
    asm volatile("mma.sync.aligned.m16n8k16.row.col.f32.bf16.bf16.f32 "
                 "{%0,%1,%2,%3}, {%4,%5,%6,%7}, {%8,%9}, {%0,%1,%2,%3};"
                 : "+f"(d[0]), "+f"(d[1]), "+f"(d[2]), "+f"(d[3])
                 : "r"(a[0]), "r"(a[1]), "r"(a[2]), "r"(a[3]),
                   "r"(b[0]), "r"(b[1]));
}

// fast exp on FMA pipe
__device__ __forceinline__ float fast_exp(float x) {
    float y = x * 1.4426950408889634f;
    float r = rintf(y);
    float f = y - r;
    float p = 1.3697664e-3f;
    p = fmaf(p, f, 9.6784195e-3f);
    p = fmaf(p, f, 5.5503454e-2f);
    p = fmaf(p, f, 2.4022652e-1f);
    p = fmaf(p, f, 6.9314718e-1f);
    p = fmaf(p, f, 1.0f);
    int ri = (int)r;
    ri = ri < -126 ? -126 : (ri > 126 ? 126 : ri);
    float s = __int_as_float((uint32_t)(ri + 127) << 23);
    return p * s;
}

__device__ __forceinline__ void split1(float f, __nv_bfloat16& h, __nv_bfloat16& l) {
    h = __float2bfloat16_rn(f);
    l = __float2bfloat16_rn(f - __bfloat162float(h));
}

// ===================== split / transpose preprocessing =====================
__global__ void split_rowmajor_kernel(const float* __restrict__ X,
                                      __nv_bfloat16* __restrict__ hi,
                                      __nv_bfloat16* __restrict__ lo, int n4)
{
    int i = blockIdx.x * blockDim.x + threadIdx.x;
    if (i >= n4) return;
    float4 v = reinterpret_cast<const float4*>(X)[i];
    __nv_bfloat16 h0, h1, h2, h3, l0, l1, l2, l3;
    split1(v.x, h0, l0); split1(v.y, h1, l1);
    split1(v.z, h2, l2); split1(v.w, h3, l3);
    __nv_bfloat162* hp = reinterpret_cast<__nv_bfloat162*>(hi) + 2 * i;
    __nv_bfloat162* lp = reinterpret_cast<__nv_bfloat162*>(lo) + 2 * i;
    hp[0] = __halves2bfloat162(h0, h1); hp[1] = __halves2bfloat162(h2, h3);
    lp[0] = __halves2bfloat162(l0, l1); lp[1] = __halves2bfloat162(l2, l3);
}

__global__ void transpose_split_kernel(const float* __restrict__ W,
                                       __nv_bfloat16* __restrict__ hi,
                                       __nv_bfloat16* __restrict__ lo,
                                       int K, int N)
{
    __shared__ float t[32][33];
    int k0 = blockIdx.y * 32, n0 = blockIdx.x * 32;
    int c = threadIdx.x & 31, r = threadIdx.x >> 5;
#pragma unroll
    for (int p = 0; p < 32; p += 8)
        t[r + p][c] = W[(size_t)(k0 + r + p) * N + n0 + c];
    __syncthreads();
#pragma unroll
    for (int p = 0; p < 32; p += 8) {
        float f = t[c][r + p];
        __nv_bfloat16 h, l;
        split1(f, h, l);
        size_t o = (size_t)(n0 + r + p) * K + k0 + c;
        hi[o] = h; lo[o] = l;
    }
}

// =================== mma.sync bf16-split GEMM ==============================
// C[M,N] = (Ahi+Alo)[M,GK] @ (Bhi+Blo)^T, B stored [N,GK] K-major.
// CTA 128x128, 512 threads (16 warps 4x4), warp tile 32x32, K-chunk 64.
// 3-stage cp.async pipeline, single sync per chunk, register double-buffered
// fragments, term-major MMA ordering (breaks same-acc RAW chains).
// EMODE 0: C row-major fp32 [M,N].
// EMODE 2: RoPE + scale + bf16 hi/lo split, scatter to Chi/Clo [b,nH,s,d].
// EMODE 3: transpose to Vt hi/lo [b,NKV,d,s].  (tile = one head)
#define TILE_BYTES  16384
#define STAGE_BYTES (4 * TILE_BYTES)
#define GEMM_SMEM   (3 * STAGE_BYTES)   // 192 KB
#define SPAD        132

__device__ __forceinline__ void load_stage_gemm(
    uint32_t stage_base, int tid, int mBase, int nBase, int kb,
    const __nv_bfloat16* __restrict__ Ahi, const __nv_bfloat16* __restrict__ Alo,
    const __nv_bfloat16* __restrict__ Bhi, const __nv_bfloat16* __restrict__ Blo)
{
#pragma unroll
    for (int u = 0; u < 2; ++u) {
        int unit = tid + u * 512;              // 0..1023
        int r = unit >> 3, c16 = unit & 7;
        uint32_t sw = SWZ((uint32_t)(r * 128 + c16 * 16));
        size_t ga = (size_t)(mBase + r) * GK + kb + c16 * 8;
        size_t gb = (size_t)(nBase + r) * GK + kb + c16 * 8;
        cpasync16(stage_base + sw,                  Ahi + ga);
        cpasync16(stage_base + TILE_BYTES + sw,     Alo + ga);
        cpasync16(stage_base + 2 * TILE_BYTES + sw, Bhi + gb);
        cpasync16(stage_base + 3 * TILE_BYTES + sw, Blo + gb);
    }
    asm volatile("cp.async.commit_group;" ::: "memory");
}

__global__ void __launch_bounds__(512, 1) mma_gemm_kernel(
    const __nv_bfloat16* __restrict__ Ahi, const __nv_bfloat16* __restrict__ Alo,
    const __nv_bfloat16* __restrict__ Bhi, const __nv_bfloat16* __restrict__ Blo,
    float* __restrict__ C,
    __nv_bfloat16* __restrict__ Chi, __nv_bfloat16* __restrict__ Clo,
    float ropeScale, int N, int nH, int EMODE)
{
    extern __shared__ __align__(1024) char smem_raw[];
    const uint32_t sbase = smem_u32(smem_raw);
    const int tid  = threadIdx.x;
    const int wid  = tid >> 5, lane = tid & 31;
    const int wm   = wid >> 2;            // 0..3 (32 rows)
    const int wn   = wid & 3;             // 0..3 (32 cols)
    const int mBase = blockIdx.y * 128;
    const int nBase = blockIdx.x * 128;

    float acc[2][4][4];
#pragma unroll
    for (int mt = 0; mt < 2; mt++)
#pragma unroll
        for (int nt = 0; nt < 4; nt++)
#pragma unroll
            for (int e = 0; e < 4; e++) acc[mt][nt][e] = 0.f;

    // prologue: 2 stages in flight
    load_stage_gemm(sbase + 0 * STAGE_BYTES, tid, mBase, nBase, 0,  Ahi, Alo, Bhi, Blo);
    load_stage_gemm(sbase + 1 * STAGE_BYTES, tid, mBase, nBase, 64, Ahi, Alo, Bhi, Blo);

    const int aRow = wm * 32 + (lane & 15);
    const int aK8  = (lane >> 4);
    const int bm   = lane >> 3;            // x4 matrix slot 0..3
    const int bRowIn = lane & 7;

    // double-buffered fragments
    uint32_t ahb[2][2][4], alb[2][2][4];   // [buf][mt][reg]
    uint32_t bhb[2][4][2], blb[2][4][2];   // [buf][nt][reg]

    for (int c2 = 0; c2 < NC; ++c2) {
        if (c2 + 1 < NC) asm volatile("cp.async.wait_group 1;" ::: "memory");
        else             asm volatile("cp.async.wait_group 0;" ::: "memory");
        __syncthreads();   // single barrier per chunk

        if (c2 + 2 < NC)
            load_stage_gemm(sbase + ((c2 + 2) % 3) * STAGE_BYTES, tid,
                            mBase, nBase, (c2 + 2) * 64, Ahi, Alo, Bhi, Blo);

        const uint32_t st   = sbase + (c2 % 3) * STAGE_BYTES;
        const uint32_t aHiB = st;
        const uint32_t aLoB = st + TILE_BYTES;
        const uint32_t bHiB = st + 2 * TILE_BYTES;
        const uint32_t bLoB = st + 3 * TILE_BYTES;

        // fragment loader for a given ks into buffer bf
#define LOAD_FRAGS(ks, bf) do {                                                 \
        _Pragma("unroll")                                                        \
        for (int np = 0; np < 2; np++) {                                         \
            int nf2 = np * 2 + (bm >> 1);                                        \
            int brow = wn * 32 + nf2 * 8 + bRowIn;                               \
            int dl = (ks) * 16 + (bm & 1) * 8;                                   \
            uint32_t sw = SWZ((uint32_t)(brow * 128 + dl * 2));                  \
            uint32_t r4[4];                                                      \
            ldmx4(r4, bHiB + sw);                                                \
            bhb[bf][np * 2][0] = r4[0];     bhb[bf][np * 2][1] = r4[1];          \
            bhb[bf][np * 2 + 1][0] = r4[2]; bhb[bf][np * 2 + 1][1] = r4[3];      \
            ldmx4(r4, bLoB + sw);                                                \
            blb[bf][np * 2][0] = r4[0];     blb[bf][np * 2][1] = r4[1];          \
            blb[bf][np * 2 + 1][0] = r4[2]; blb[bf][np * 2 + 1][1] = r4[3];      \
        }                                                                        \
        {                                                                        \
            int ak = (ks) * 16 + aK8 * 8;                                        \
            _Pragma("unroll")                                                    \
            for (int mt = 0; mt < 2; mt++) {                                     \
                uint32_t sw = SWZ((uint32_t)((aRow + mt * 16) * 128 + ak * 2));  \
                ldmx4(ahb[bf][mt], aHiB + sw);                                   \
                ldmx4(alb[bf][mt], aLoB + sw);                                   \
            }                                                                    \
        }                                                                        \
    } while (0)

        LOAD_FRAGS(0, 0);
#pragma unroll
        for (int ks = 0; ks < 4; ks++) {
            const int cur = ks & 1;
            if (ks < 3) LOAD_FRAGS(ks + 1, (ks + 1) & 1);
            // term-major ordering: max distance between same-acc MMAs
#pragma unroll
            for (int mt = 0; mt < 2; mt++)
#pragma unroll
                for (int nt = 0; nt < 4; nt++)
                    mma16816(acc[mt][nt], ahb[cur][mt], bhb[cur][nt]);
#pragma unroll
            for (int mt = 0; mt < 2; mt++)
#pragma unroll
                for (int nt = 0; nt < 4; nt++)
                    mma16816(acc[mt][nt], ahb[cur][mt], blb[cur][nt]);
#pragma unroll
            for (int mt = 0; mt < 2; mt++)
#pragma unroll
                for (int nt = 0; nt < 4; nt++)
                    mma16816(acc[mt][nt], alb[cur][mt], bhb[cur][nt]);
        }
#undef LOAD_FRAGS
    }

    const int row0 = wm * 32 + (lane >> 2);
    const int col0 = wn * 32 + (lane & 3) * 2;

    if (EMODE == 0) {
#pragma unroll
        for (int mt = 0; mt < 2; mt++)
#pragma unroll
            for (int half = 0; half < 2; half++) {
                int grow = mBase + row0 + mt * 16 + half * 8;
#pragma unroll
                for (int nt = 0; nt < 4; nt++) {
                    int gcol = nBase + col0 + nt * 8;
                    *reinterpret_cast<float2*>(C + (size_t)grow * N + gcol) =
                        make_float2(acc[mt][nt][half * 2], acc[mt][nt][half * 2 + 1]);
                }
            }
        return;
    }

    // stage accumulators to smem [128][SPAD]
    __syncthreads();
    float* stage = reinterpret_cast<float*>(smem_raw);
#pragma unroll
    for (int mt = 0; mt < 2; mt++)
#pragma unroll
        for (int half = 0; half < 2; half++) {
            int r = row0 + mt * 16 + half * 8;
#pragma unroll
            for (int nt = 0; nt < 4; nt++) {
                int c = col0 + nt * 8;
                stage[r * SPAD + c]     = acc[mt][nt][half * 2];
                stage[r * SPAD + c + 1] = acc[mt][nt][half * 2 + 1];
            }
        }
    __syncthreads();

    const int b = mBase >> 11;
    const int sBase = mBase & 2047;
    const int h = nBase >> 7;               // one head per 128-wide tile

    if (EMODE == 2) {
        const size_t headBase = ((size_t)(b * nH + h) * S_LEN) * HDIM;
#pragma unroll
        for (int it = 0; it < 16; it++) {
            int pr = tid + it * 512;           // 0..8191
            int r = pr >> 6, dp = pr & 63;
            float x1 = stage[r * SPAD + dp];
            float x2 = stage[r * SPAD + dp + 64];
            int srow = sBase + r;
            float inv_freq = exp2f(-(float)dp * (13.287712379549449f / 64.0f));
            float ang = (float)srow * inv_freq;
            float c, sn;
            sincosf(ang, &sn, &c);
            float y1 = (x1 * c - x2 * sn) * ropeScale;
            float y2 = (x2 * c + x1 * sn) * ropeScale;
            size_t base = headBase + (size_t)srow * HDIM;
            __nv_bfloat16 hh, ll;
            split1(y1, hh, ll); Chi[base + dp] = hh;      Clo[base + dp] = ll;
            split1(y2, hh, ll); Chi[base + dp + 64] = hh; Clo[base + dp + 64] = ll;
        }
        return;
    }

    // EMODE 3: transpose to Vt [b,NKV,d,s] hi/lo (tile = one head)
    {
        int s2 = (tid & 63) * 2;
        int g  = tid >> 6;                  // 0..7
#pragma unroll
        for (int it = 0; it < 16; it++) {
            int d = g * 16 + it;            // 0..127
            float f0 = stage[s2 * SPAD + d];
            float f1 = stage[(s2 + 1) * SPAD + d];
            size_t base = ((size_t)(b * NKV + h) * HDIM + d) * S_LEN + sBase + s2;
            __nv_bfloat16 h0b, l0b, h1b, l1b;
            split1(f0, h0b, l0b);
            split1(f1, h1b, l1b);
            *reinterpret_cast<__nv_bfloat162*>(g_Vth + base) = __halves2bfloat162(h0b, h1b);
            *reinterpret_cast<__nv_bfloat162*>(g_Vtl + base) = __halves2bfloat162(l0b, l1b);
        }
    }
}

// ================= tensor-core flash attention (bf16 hi/lo) ================
#define AT_STAGE 65536
#define ATTN_SMEM (2 * AT_STAGE)

__global__ void __launch_bounds__(256, 1) attn_mma_kernel()
{
    extern __shared__ __align__(1024) char smem_raw[];
    const uint32_t sb = smem_u32(smem_raw);
    const int tid = threadIdx.x, wid = tid >> 5, lane = tid & 31;
    const int qt = blockIdx.x, h = blockIdx.y, b = blockIdx.z;
    const int hk = h >> 2;
    const int q0 = qt * 128;
    const int bh = b * NHEADS + h, bhk = b * NKV + hk;

    const __nv_bfloat16* Qhg = g_Qbh + ((size_t)bh * S_LEN + q0) * HDIM;
    const __nv_bfloat16* Qlg = g_Qbl + ((size_t)bh * S_LEN + q0) * HDIM;
    const __nv_bfloat16* Khg = g_Kbh + (size_t)bhk * S_LEN * HDIM;
    const __nv_bfloat16* Klg = g_Kbl + (size_t)bhk * S_LEN * HDIM;
    const __nv_bfloat16* Vhg = g_Vth + (size_t)bhk * HDIM * S_LEN;
    const __nv_bfloat16* Vlg = g_Vtl + (size_t)bhk * HDIM * S_LEN;

    // ---- stage Q ----
#pragma unroll
    for (int it = 0; it < 16; it++) {
        int u = tid + it * 256;
        int bf = u >> 11;
        int w  = u & 2047;
        int r = w >> 4, c16 = w & 15;
        int sub = c16 >> 3;
        uint32_t off = (uint32_t)(bf * 32768 + sub * 16384 + r * 128 + (c16 & 7) * 16);
        const __nv_bfloat16* g = (bf ? Qlg : Qhg) + (size_t)r * HDIM + c16 * 8;
        cpasync16(sb + SWZ(off), g);
    }
    asm volatile("cp.async.commit_group;" ::: "memory");
    asm volatile("cp.async.wait_group 0;" ::: "memory");
    __syncthreads();

    uint32_t qh[8][4], ql[8][4];
    {
        int row = wid * 16 + (lane & 15);
        int k8 = lane >> 4;
#pragma unroll
        for (int kf = 0; kf < 8; kf++) {
            int sub = kf >> 2;
            uint32_t off = (uint32_t)(sub * 16384 + row * 128 + ((kf & 3) * 16 + k8 * 8) * 2);
            uint32_t sw = SWZ(off);
            ldmx4(qh[kf], sb + sw);
            ldmx4(ql[kf], sb + 32768 + sw);
        }
    }
    __syncthreads();

    float o[16][4];
#pragma unroll
    for (int nf = 0; nf < 16; nf++)
#pragma unroll
        for (int e = 0; e < 4; e++) o[nf][e] = 0.f;

    float m0 = -1e30f, m1 = -1e30f, l0 = 0.f, l1 = 0.f;
    const int g0row = q0 + wid * 16 + (lane >> 2);

    int kt_lo = 2 * qt - 8; if (kt_lo < 0) kt_lo = 0;
    const int nt = 2 * qt + 1 - kt_lo + 1;

    auto load_kv = [&](int stage, int kt) {
        const int k0 = kt * 64;
        const uint32_t stb = sb + (uint32_t)stage * AT_STAGE;
#pragma unroll
        for (int it = 0; it < 16; it++) {
            int u = tid + it * 256;
            int buf = u >> 10;
            int w = u & 1023;
            int r = w >> 3, c16 = w & 7;
            uint32_t off = (uint32_t)(buf * 16384 + r * 128 + c16 * 16);
            const __nv_bfloat16* g;
            if (buf < 2) {
                int key = r & 63, sub = r >> 6;
                g = (buf ? Klg : Khg) + (size_t)(k0 + key) * HDIM + sub * 64 + c16 * 8;
            } else {
                g = (buf == 3 ? Vlg : Vhg) + (size_t)r * S_LEN + k0 + c16 * 8;
            }
            cpasync16(stb + SWZ(off), g);
        }
        asm volatile("cp.async.commit_group;" ::: "memory");
    };

    load_kv(0, kt_lo);
    load_kv(1, kt_lo + 1);

    for (int i = 0; i < nt; i++) {
        const int kt = kt_lo + i;
        const int k0 = kt * 64;
        if (i + 1 < nt) asm volatile("cp.async.wait_group 1;" ::: "memory");
        else            asm volatile("cp.async.wait_group 0;" ::: "memory");
        __syncthreads();
        const uint32_t stb = sb + (uint32_t)(i & 1) * AT_STAGE;

        float s[8][4];
#pragma unroll
        for (int nf = 0; nf < 8; nf++)
#pragma unroll
            for (int e = 0; e < 4; e++) s[nf][e] = 0.f;

#pragma unroll
        for (int kf = 0; kf < 8; kf++) {
            const int sub = kf >> 2;
            const int klocal = (kf & 3) * 16;
            uint32_t kbh[8][2], kbl[8][2];
#pragma unroll
            for (int np = 0; np < 4; np++) {
                int m = lane >> 3;
                int nf2 = np * 2 + (m >> 1);
                int key = nf2 * 8 + (lane & 7);
                int dl = klocal + (m & 1) * 8;
                uint32_t off = (uint32_t)((sub * 64 + key) * 128 + dl * 2);
                uint32_t sw = SWZ(off);
                uint32_t r4[4];
                ldmx4(r4, stb + sw);
                kbh[np * 2][0] = r4[0]; kbh[np * 2][1] = r4[1];
                kbh[np * 2 + 1][0] = r4[2]; kbh[np * 2 + 1][1] = r4[3];
                ldmx4(r4, stb + 16384 + sw);
                kbl[np * 2][0] = r4[0]; kbl[np * 2][1] = r4[1];
                kbl[np * 2 + 1][0] = r4[2]; kbl[np * 2 + 1][1] = r4[3];
            }
#pragma unroll
            for (int nf = 0; nf < 8; nf++) {
                mma16816(s[nf], qh[kf], kbh[nf]);
                mma16816(s[nf], qh[kf], kbl[nf]);
                mma16816(s[nf], ql[kf], kbh[nf]);
            }
        }

        if ((k0 + 63 > q0) || (q0 + 127 - k0 > WINDOW)) {
#pragma unroll
            for (int nf = 0; nf < 8; nf++)
#pragma unroll
                for (int e = 0; e < 4; e++) {
                    int row = g0row + ((e >= 2) ? 8 : 0);
                    int col = k0 + nf * 8 + (lane & 3) * 2 + (e & 1);
                    if (col > row || row - col > WINDOW) s[nf][e] = -1e30f;
                }
        }

        float mx0 = -1e30f, mx1 = -1e30f;
#pragma unroll
        for (int nf = 0; nf < 8; nf++) {
            mx0 = fmaxf(mx0, fmaxf(s[nf][0], s[nf][1]));
            mx1 = fmaxf(mx1, fmaxf(s[nf][2], s[nf][3]));
        }
        mx0 = fmaxf(mx0, __shfl_xor_sync(0xffffffffu, mx0, 1));
        mx0 = fmaxf(mx0, __shfl_xor_sync(0xffffffffu, mx0, 2));
        mx1 = fmaxf(mx1, __shfl_xor_sync(0xffffffffu, mx1, 1));
        mx1 = fmaxf(mx1, __shfl_xor_sync(0xffffffffu, mx1, 2));
        float mn0 = fmaxf(m0, mx0), mn1 = fmaxf(m1, mx1);
        float fac0 = fast_exp(m0 - mn0), fac1 = fast_exp(m1 - mn1);
        m0 = mn0; m1 = mn1;

        uint32_t ph[8][2], pl[8][2];
        float ps0 = 0.f, ps1 = 0.f;
#pragma unroll
        for (int nf = 0; nf < 8; nf++) {
            float p0 = fast_exp(s[nf][0] - mn0);
            float p1 = fast_exp(s[nf][1] - mn0);
            float p2 = fast_exp(s[nf][2] - mn1);
            float p3 = fast_exp(s[nf][3] - mn1);
            ps0 += p0 + p1; ps1 += p2 + p3;
            __nv_bfloat16 h0b, lo0, h1b, lo1, h2b, lo2, h3b, lo3;
            split1(p0, h0b, lo0); split1(p1, h1b, lo1);
            split1(p2, h2b, lo2); split1(p3, h3b, lo3);
            __nv_bfloat162 t;
            t = __halves2bfloat162(h0b, h1b);  ph[nf][0] = *reinterpret_cast<uint32_t*>(&t);
            t = __halves2bfloat162(h2b, h3b);  ph[nf][1] = *reinterpret_cast<uint32_t*>(&t);
            t = __halves2bfloat162(lo0, lo1);  pl[nf][0] = *reinterpret_cast<uint32_t*>(&t);
            t = __halves2bfloat162(lo2, lo3);  pl[nf][1] = *reinterpret_cast<uint32_t*>(&t);
        }
        ps0 += __shfl_xor_sync(0xffffffffu, ps0, 1);
        ps0 += __shfl_xor_sync(0xffffffffu, ps0, 2);
        ps1 += __shfl_xor_sync(0xffffffffu, ps1, 1);
        ps1 += __shfl_xor_sync(0xffffffffu, ps1, 2);
        l0 = l0 * fac0 + ps0;
        l1 = l1 * fac1 + ps1;

#pragma unroll
        for (int nf = 0; nf < 16; nf++) {
            o[nf][0] *= fac0; o[nf][1] *= fac0;
            o[nf][2] *= fac1; o[nf][3] *= fac1;
        }

#pragma unroll
        for (int kf2 = 0; kf2 < 4; kf2++) {
            uint32_t pah[4] = { ph[2 * kf2][0], ph[2 * kf2][1],
                                ph[2 * kf2 + 1][0], ph[2 * kf2 + 1][1] };
            uint32_t pal[4] = { pl[2 * kf2][0], pl[2 * kf2][1],
                                pl[2 * kf2 + 1][0], pl[2 * kf2 + 1][1] };
#pragma unroll
            for (int np = 0; np < 8; np++) {
                int m = lane >> 3;
                int drow = (np * 2 + (m >> 1)) * 8 + (lane & 7);
                int kl = kf2 * 16 + (m & 1) * 8;
                uint32_t off = (uint32_t)(32768 + drow * 128 + kl * 2);
                uint32_t sw = SWZ(off);
                uint32_t r4[4], r4l[4];
                ldmx4(r4,  stb + sw);
                ldmx4(r4l, stb + 16384 + sw);
                uint32_t vb0[2] = { r4[0], r4[1] },  vb1[2] = { r4[2], r4[3] };
                uint32_t vl0[2] = { r4l[0], r4l[1] }, vl1[2] = { r4l[2], r4l[3] };
                mma16816(o[np * 2],     pah, vb0);
                mma16816(o[np * 2],     pah, vl0);
                mma16816(o[np * 2],     pal, vb0);
                mma16816(o[np * 2 + 1], pah, vb1);
                mma16816(o[np * 2 + 1], pah, vl1);
                mma16816(o[np * 2 + 1], pal, vb1);
            }
        }
        __syncthreads();
        if (i + 2 < nt) load_kv(i & 1, kt + 2);
    }

    // ---- write O as bf16 hi/lo row-major [m, h*128+d] ----
    const float inv0 = 1.f / l0, inv1 = 1.f / l1;
    const int r0 = wid * 16 + (lane >> 2);
    const int c0 = (lane & 3) * 2;
    const size_t rowA = ((size_t)(b * S_LEN + q0 + r0)) * HID + h * HDIM;
    const size_t rowB = ((size_t)(b * S_LEN + q0 + r0 + 8)) * HID + h * HDIM;
#pragma unroll
    for (int nf = 0; nf < 16; nf++) {
        int d = nf * 8 + c0;
        __nv_bfloat16 h0b, l0b, h1b, l1b;
        split1(o[nf][0] * inv0, h0b, l0b);
        split1(o[nf][1] * inv0, h1b, l1b);
        *reinterpret_cast<__nv_bfloat162*>(g_Ohi + rowA + d) = __halves2bfloat162(h0b, h1b);
        *reinterpret_cast<__nv_bfloat162*>(g_Olo + rowA + d) = __halves2bfloat162(l0b, l1b);
        split1(o[nf][2] * inv1, h0b, l0b);
        split1(o[nf][3] * inv1, h1b, l1b);
        *reinterpret_cast<__nv_bfloat162*>(g_Ohi + rowB + d) = __halves2bfloat162(h0b, h1b);
        *reinterpret_cast<__nv_bfloat162*>(g_Olo + rowB + d) = __halves2bfloat162(l0b, l1b);
    }
}

// ---------------------------------------------------------------------------
extern "C" void kernel_launch(void* const* d_in, const int* in_sizes, int n_in,
                              void* d_out, int out_size)
{
    (void)in_sizes; (void)n_in; (void)out_size;
    const float* hidden = (const float*)d_in[0];
    const float* Wq     = (const float*)d_in[1];
    const float* Wk     = (const float*)d_in[2];
    const float* Wv     = (const float*)d_in[3];
    const float* Wo     = (const float*)d_in[4];
    float* out          = (float*)d_out;

    __nv_bfloat16 *xhi, *xlo, *wqh, *wql, *wkh, *wkl, *wvh, *wvl, *woh, *wol, *ohi, *olo;
    __nv_bfloat16 *qbh, *qbl, *kbh, *kbl;
    cudaGetSymbolAddress((void**)&xhi, g_Xhi);  cudaGetSymbolAddress((void**)&xlo, g_Xlo);
    cudaGetSymbolAddress((void**)&wqh, g_WqThi); cudaGetSymbolAddress((void**)&wql, g_WqTlo);
    cudaGetSymbolAddress((void**)&wkh, g_WkThi); cudaGetSymbolAddress((void**)&wkl, g_WkTlo);
    cudaGetSymbolAddress((void**)&wvh, g_WvThi); cudaGetSymbolAddress((void**)&wvl, g_WvTlo);
    cudaGetSymbolAddress((void**)&woh, g_WoThi); cudaGetSymbolAddress((void**)&wol, g_WoTlo);
    cudaGetSymbolAddress((void**)&ohi, g_Ohi);   cudaGetSymbolAddress((void**)&olo, g_Olo);
    cudaGetSymbolAddress((void**)&qbh, g_Qbh);   cudaGetSymbolAddress((void**)&qbl, g_Qbl);
    cudaGetSymbolAddress((void**)&kbh, g_Kbh);   cudaGetSymbolAddress((void**)&kbl, g_Kbl);

    cudaFuncSetAttribute(mma_gemm_kernel,
                         cudaFuncAttributeMaxDynamicSharedMemorySize, GEMM_SMEM);
    cudaFuncSetAttribute(attn_mma_kernel,
                         cudaFuncAttributeMaxDynamicSharedMemorySize, ATTN_SMEM);

    const float qscale = 1.0f / sqrtf((float)HDIM);

    // 0: transpose Wq
    {
        dim3 gq(HID / 32, HID / 32);
        transpose_split_kernel<<<gq, 256>>>(Wq, wqh, wql, HID, HID);
    }
    // 1: split X
    {
        int n4 = (M_ROWS * HID) / 4;
        split_rowmajor_kernel<<<(n4 + 255) / 256, 256>>>(hidden, xhi, xlo, n4);
    }
    // 2: transpose Wk
    {
        dim3 gkv(KVDIM / 32, HID / 32);
        transpose_split_kernel<<<gkv, 256>>>(Wk, wkh, wkl, HID, KVDIM);
    }
    // 3 (ncu slot): Q projection (+RoPE +scale +split)
    {
        dim3 g(HID / 128, M_ROWS / 128);
        mma_gemm_kernel<<<g, 512, GEMM_SMEM>>>(xhi, xlo, wqh, wql,
                                               nullptr, qbh, qbl, qscale,
                                               HID, NHEADS, 2);
    }
    // 4: transpose Wv
    {
        dim3 gkv(KVDIM / 32, HID / 32);
        transpose_split_kernel<<<gkv, 256>>>(Wv, wvh, wvl, HID, KVDIM);
    }
    // 5: K projection (+RoPE +split)
    {
        dim3 g(KVDIM / 128, M_ROWS / 128);
        mma_gemm_kernel<<<g, 512, GEMM_SMEM>>>(xhi, xlo, wkh, wkl,
                                               nullptr, kbh, kbl, 1.0f,
                                               KVDIM, NKV, 2);
    }
    // 6: transpose Wo
    {
        dim3 go(HID / 32, HID / 32);
        transpose_split_kernel<<<go, 256>>>(Wo, woh, wol, HID, HID);
    }
    // 7: V projection (+transpose to Vt hi/lo)
    {
        dim3 g(KVDIM / 128, M_ROWS / 128);
        mma_gemm_kernel<<<g, 512, GEMM_SMEM>>>(xhi, xlo, wvh, wvl,
                                               nullptr, nullptr, nullptr, 0.f,
                                               KVDIM, NKV, 3);
    }
    // 8: attention (writes Ohi/Olo bf16 directly)
    {
        dim3 g(S_LEN / 128, NHEADS, BATCH);
        attn_mma_kernel<<<g, 256, ATTN_SMEM>>>();
    }
    // 9: output projection
    {
        dim3 go(HID / 128, M_ROWS / 128);
        mma_gemm_kernel<<<go, 512, GEMM_SMEM>>>(ohi, olo, woh, wol,
                                                out, nullptr, nullptr, 0.f,
                                                HID, NHEADS, 0);
    }
}

// round 11
// speedup vs baseline: 1.0377x; 1.0377x over previous
#include <cuda_runtime.h>
#include <cuda_bf16.h>
#include <math.h>
#include <stdint.h>

#define S_LEN   2048
#define BATCH   2
#define NHEADS  32
#define NKV     8
#define HDIM    128
#define HID     4096
#define KVDIM   1024
#define M_ROWS  4096   // B*S
#define WINDOW  512    // SLIDING_WINDOW // 2
#define GK      4096   // GEMM K
#define NC      (GK/64)

// ======================== scratch buffers ==================================
__device__ __nv_bfloat16 g_Xhi[(size_t)M_ROWS * HID];
__device__ __nv_bfloat16 g_Xlo[(size_t)M_ROWS * HID];
__device__ __nv_bfloat16 g_WqThi[(size_t)HID * HID];
__device__ __nv_bfloat16 g_WqTlo[(size_t)HID * HID];
__device__ __nv_bfloat16 g_WkThi[(size_t)KVDIM * HID];
__device__ __nv_bfloat16 g_WkTlo[(size_t)KVDIM * HID];
__device__ __nv_bfloat16 g_WvThi[(size_t)KVDIM * HID];
__device__ __nv_bfloat16 g_WvTlo[(size_t)KVDIM * HID];
__device__ __nv_bfloat16 g_WoThi[(size_t)HID * HID];
__device__ __nv_bfloat16 g_WoTlo[(size_t)HID * HID];
__device__ __nv_bfloat16 g_Ohi[(size_t)M_ROWS * HID];
__device__ __nv_bfloat16 g_Olo[(size_t)M_ROWS * HID];

// bf16 attention operands (RoPE'd)
__device__ __nv_bfloat16 g_Qbh[(size_t)BATCH * NHEADS * S_LEN * HDIM];
__device__ __nv_bfloat16 g_Qbl[(size_t)BATCH * NHEADS * S_LEN * HDIM];
__device__ __nv_bfloat16 g_Kbh[(size_t)BATCH * NKV * S_LEN * HDIM];
__device__ __nv_bfloat16 g_Kbl[(size_t)BATCH * NKV * S_LEN * HDIM];
__device__ __nv_bfloat16 g_Vth[(size_t)BATCH * NKV * HDIM * S_LEN];  // [b,hk,d,s]
__device__ __nv_bfloat16 g_Vtl[(size_t)BATCH * NKV * HDIM * S_LEN];

// ======================= low-level helpers =================================
__device__ __forceinline__ uint32_t smem_u32(const void* p) {
    uint32_t a;
    asm("{ .reg .u64 t; cvta.to.shared.u64 t, %1; cvt.u32.u64 %0, t; }"
        : "=r"(a) : "l"(p));
    return a;
}
__device__ __forceinline__ void cpasync16(uint32_t saddr, const void* g) {
    asm volatile("cp.async.cg.shared.global [%0], [%1], 16;"
                 :: "r"(saddr), "l"(g) : "memory");
}
#define SWZ(o) ((o) ^ (((o) >> 3) & 0x70))

__device__ __forceinline__ void ldmx4(uint32_t* r, uint32_t addr) {
    asm volatile("ldmatrix.sync.aligned.m8n8.x4.shared.b16 {%0,%1,%2,%3}, [%4];"
                 : "=r"(r[0]), "=r"(r[1]), "=r"(r[2]), "=r"(r[3]) : "r"(addr));
}
__device__ __forceinline__ void mma16816(float* d, const uint32_t* a, const uint32_t* b) {
    asm volatile("mma.sync.aligned.m16n8k16.row.col.f32.bf16.bf16.f32 "
                 "{%0,%1,%2,%3}, {%4,%5,%6,%7}, {%8,%9}, {%0,%1,%2,%3};"
                 : "+f"(d[0]), "+f"(d[1]), "+f"(d[2]), "+f"(d[3])
                 : "r"(a[0]), "r"(a[1]), "r"(a[2]), "r"(a[3]),
                   "r"(b[0]), "r"(b[1]));
}

// fast exp on FMA pipe
__device__ __forceinline__ float fast_exp(float x) {
    float y = x * 1.4426950408889634f;
    float r = rintf(y);
    float f = y - r;
    float p = 1.3697664e-3f;
    p = fmaf(p, f, 9.6784195e-3f);
    p = fmaf(p, f, 5.5503454e-2f);
    p = fmaf(p, f, 2.4022652e-1f);
    p = fmaf(p, f, 6.9314718e-1f);
    p = fmaf(p, f, 1.0f);
    int ri = (int)r;
    ri = ri < -126 ? -126 : (ri > 126 ? 126 : ri);
    float s = __int_as_float((uint32_t)(ri + 127) << 23);
    return p * s;
}

__device__ __forceinline__ void split1(float f, __nv_bfloat16& h, __nv_bfloat16& l) {
    h = __float2bfloat16_rn(f);
    l = __float2bfloat16_rn(f - __bfloat162float(h));
}

// ===================== split / transpose preprocessing =====================
__global__ void split_rowmajor_kernel(const float* __restrict__ X,
                                      __nv_bfloat16* __restrict__ hi,
                                      __nv_bfloat16* __restrict__ lo, int n4)
{
    int i = blockIdx.x * blockDim.x + threadIdx.x;
    if (i >= n4) return;
    float4 v = reinterpret_cast<const float4*>(X)[i];
    __nv_bfloat16 h0, h1, h2, h3, l0, l1, l2, l3;
    split1(v.x, h0, l0); split1(v.y, h1, l1);
    split1(v.z, h2, l2); split1(v.w, h3, l3);
    __nv_bfloat162* hp = reinterpret_cast<__nv_bfloat162*>(hi) + 2 * i;
    __nv_bfloat162* lp = reinterpret_cast<__nv_bfloat162*>(lo) + 2 * i;
    hp[0] = __halves2bfloat162(h0, h1); hp[1] = __halves2bfloat162(h2, h3);
    lp[0] = __halves2bfloat162(l0, l1); lp[1] = __halves2bfloat162(l2, l3);
}

__global__ void transpose_split_kernel(const float* __restrict__ W,
                                       __nv_bfloat16* __restrict__ hi,
                                       __nv_bfloat16* __restrict__ lo,
                                       int K, int N)
{
    __shared__ float t[32][33];
    int k0 = blockIdx.y * 32, n0 = blockIdx.x * 32;
    int c = threadIdx.x & 31, r = threadIdx.x >> 5;
#pragma unroll
    for (int p = 0; p < 32; p += 8)
        t[r + p][c] = W[(size_t)(k0 + r + p) * N + n0 + c];
    __syncthreads();
#pragma unroll
    for (int p = 0; p < 32; p += 8) {
        float f = t[c][r + p];
        __nv_bfloat16 h, l;
        split1(f, h, l);
        size_t o = (size_t)(n0 + r + p) * K + k0 + c;
        hi[o] = h; lo[o] = l;
    }
}

// =================== mma.sync bf16-split GEMM (R8 best) ====================
// CTA 128x128, 256 threads (8 warps 2x4), warp tile 64x32, K-chunk 64.
// 3-stage cp.async pipeline, single sync per chunk.
#define TILE_BYTES  16384
#define STAGE_BYTES (4 * TILE_BYTES)
#define GEMM_SMEM   (3 * STAGE_BYTES)   // 192 KB
#define SPAD        132

__device__ __forceinline__ void load_stage_gemm(
    uint32_t stage_base, int tid, int mBase, int nBase, int kb,
    const __nv_bfloat16* __restrict__ Ahi, const __nv_bfloat16* __restrict__ Alo,
    const __nv_bfloat16* __restrict__ Bhi, const __nv_bfloat16* __restrict__ Blo)
{
#pragma unroll
    for (int u = 0; u < 4; ++u) {
        int unit = tid + u * 256;
        int r = unit >> 3, c16 = unit & 7;
        uint32_t sw = SWZ((uint32_t)(r * 128 + c16 * 16));
        size_t ga = (size_t)(mBase + r) * GK + kb + c16 * 8;
        size_t gb = (size_t)(nBase + r) * GK + kb + c16 * 8;
        cpasync16(stage_base + sw,                  Ahi + ga);
        cpasync16(stage_base + TILE_BYTES + sw,     Alo + ga);
        cpasync16(stage_base + 2 * TILE_BYTES + sw, Bhi + gb);
        cpasync16(stage_base + 3 * TILE_BYTES + sw, Blo + gb);
    }
    asm volatile("cp.async.commit_group;" ::: "memory");
}

__global__ void __launch_bounds__(256, 1) mma_gemm_kernel(
    const __nv_bfloat16* __restrict__ Ahi, const __nv_bfloat16* __restrict__ Alo,
    const __nv_bfloat16* __restrict__ Bhi, const __nv_bfloat16* __restrict__ Blo,
    float* __restrict__ C,
    __nv_bfloat16* __restrict__ Chi, __nv_bfloat16* __restrict__ Clo,
    float ropeScale, int N, int nH, int EMODE)
{
    extern __shared__ __align__(1024) char smem_raw[];
    const uint32_t sbase = smem_u32(smem_raw);
    const int tid  = threadIdx.x;
    const int wid  = tid >> 5, lane = tid & 31;
    const int wm   = wid >> 2;            // 0..1 (64 rows)
    const int wn   = wid & 3;             // 0..3 (32 cols)
    const int mBase = blockIdx.y * 128;
    const int nBase = blockIdx.x * 128;

    float acc[4][4][4];
#pragma unroll
    for (int mt = 0; mt < 4; mt++)
#pragma unroll
        for (int nt = 0; nt < 4; nt++)
#pragma unroll
            for (int e = 0; e < 4; e++) acc[mt][nt][e] = 0.f;

    load_stage_gemm(sbase + 0 * STAGE_BYTES, tid, mBase, nBase, 0,  Ahi, Alo, Bhi, Blo);
    load_stage_gemm(sbase + 1 * STAGE_BYTES, tid, mBase, nBase, 64, Ahi, Alo, Bhi, Blo);

    const int aRow = wm * 64 + (lane & 15);
    const int aK8  = (lane >> 4);
    const int bm   = lane >> 3;            // x4 matrix slot 0..3
    const int bRowIn = lane & 7;

    for (int c2 = 0; c2 < NC; ++c2) {
        if (c2 + 1 < NC) asm volatile("cp.async.wait_group 1;" ::: "memory");
        else             asm volatile("cp.async.wait_group 0;" ::: "memory");
        __syncthreads();   // single barrier per chunk

        if (c2 + 2 < NC)
            load_stage_gemm(sbase + ((c2 + 2) % 3) * STAGE_BYTES, tid,
                            mBase, nBase, (c2 + 2) * 64, Ahi, Alo, Bhi, Blo);

        const uint32_t st   = sbase + (c2 % 3) * STAGE_BYTES;
        const uint32_t aHiB = st;
        const uint32_t aLoB = st + TILE_BYTES;
        const uint32_t bHiB = st + 2 * TILE_BYTES;
        const uint32_t bLoB = st + 3 * TILE_BYTES;

#pragma unroll
        for (int ks = 0; ks < 4; ks++) {
            uint32_t bh[4][2], bl[4][2];
#pragma unroll
            for (int np = 0; np < 2; np++) {
                int nf2 = np * 2 + (bm >> 1);
                int brow = wn * 32 + nf2 * 8 + bRowIn;
                int dl = ks * 16 + (bm & 1) * 8;
                uint32_t sw = SWZ((uint32_t)(brow * 128 + dl * 2));
                uint32_t r4[4];
                ldmx4(r4, bHiB + sw);
                bh[np * 2][0] = r4[0];     bh[np * 2][1] = r4[1];
                bh[np * 2 + 1][0] = r4[2]; bh[np * 2 + 1][1] = r4[3];
                ldmx4(r4, bLoB + sw);
                bl[np * 2][0] = r4[0];     bl[np * 2][1] = r4[1];
                bl[np * 2 + 1][0] = r4[2]; bl[np * 2 + 1][1] = r4[3];
            }
            const int ak = ks * 16 + aK8 * 8;
#pragma unroll
            for (int mt = 0; mt < 4; mt++) {
                uint32_t sw = SWZ((uint32_t)((aRow + mt * 16) * 128 + ak * 2));
                uint32_t ah[4], al[4];
                ldmx4(ah, aHiB + sw);
                ldmx4(al, aLoB + sw);
#pragma unroll
                for (int nt = 0; nt < 4; nt++) {
                    mma16816(acc[mt][nt], ah, bh[nt]);
                    mma16816(acc[mt][nt], ah, bl[nt]);
                    mma16816(acc[mt][nt], al, bh[nt]);
                }
            }
        }
    }

    const int row0 = wm * 64 + (lane >> 2);
    const int col0 = wn * 32 + (lane & 3) * 2;

    if (EMODE == 0) {
#pragma unroll
        for (int mt = 0; mt < 4; mt++)
#pragma unroll
            for (int half = 0; half < 2; half++) {
                int grow = mBase + row0 + mt * 16 + half * 8;
#pragma unroll
                for (int nt = 0; nt < 4; nt++) {
                    int gcol = nBase + col0 + nt * 8;
                    *reinterpret_cast<float2*>(C + (size_t)grow * N + gcol) =
                        make_float2(acc[mt][nt][half * 2], acc[mt][nt][half * 2 + 1]);
                }
            }
        return;
    }

    // stage accumulators to smem [128][SPAD]
    __syncthreads();
    float* stage = reinterpret_cast<float*>(smem_raw);
#pragma unroll
    for (int mt = 0; mt < 4; mt++)
#pragma unroll
        for (int half = 0; half < 2; half++) {
            int r = row0 + mt * 16 + half * 8;
#pragma unroll
            for (int nt = 0; nt < 4; nt++) {
                int c = col0 + nt * 8;
                stage[r * SPAD + c]     = acc[mt][nt][half * 2];
                stage[r * SPAD + c + 1] = acc[mt][nt][half * 2 + 1];
            }
        }
    __syncthreads();

    const int b = mBase >> 11;
    const int sBase = mBase & 2047;
    const int h = nBase >> 7;               // one head per 128-wide tile

    if (EMODE == 2) {
        const size_t headBase = ((size_t)(b * nH + h) * S_LEN) * HDIM;
#pragma unroll
        for (int it = 0; it < 32; it++) {
            int pr = tid + it * 256;           // 0..8191
            int r = pr >> 6, dp = pr & 63;
            float x1 = stage[r * SPAD + dp];
            float x2 = stage[r * SPAD + dp + 64];
            int srow = sBase + r;
            float inv_freq = exp2f(-(float)dp * (13.287712379549449f / 64.0f));
            float ang = (float)srow * inv_freq;
            float c, sn;
            sincosf(ang, &sn, &c);
            float y1 = (x1 * c - x2 * sn) * ropeScale;
            float y2 = (x2 * c + x1 * sn) * ropeScale;
            size_t base = headBase + (size_t)srow * HDIM;
            __nv_bfloat16 hh, ll;
            split1(y1, hh, ll); Chi[base + dp] = hh;      Clo[base + dp] = ll;
            split1(y2, hh, ll); Chi[base + dp + 64] = hh; Clo[base + dp + 64] = ll;
        }
        return;
    }

    // EMODE 3: transpose to Vt [b,NKV,d,s] hi/lo (tile = one head)
    {
        int s2 = (tid & 63) * 2;
        int g  = tid >> 6;                  // 0..3
#pragma unroll
        for (int it = 0; it < 32; it++) {
            int d = g * 32 + it;            // 0..127
            float f0 = stage[s2 * SPAD + d];
            float f1 = stage[(s2 + 1) * SPAD + d];
            size_t base = ((size_t)(b * NKV + h) * HDIM + d) * S_LEN + sBase + s2;
            __nv_bfloat16 h0b, l0b, h1b, l1b;
            split1(f0, h0b, l0b);
            split1(f1, h1b, l1b);
            *reinterpret_cast<__nv_bfloat162*>(g_Vth + base) = __halves2bfloat162(h0b, h1b);
            *reinterpret_cast<__nv_bfloat162*>(g_Vtl + base) = __halves2bfloat162(l0b, l1b);
        }
    }
}

// ================= tensor-core flash attention (bf16 hi/lo) ================
#define AT_STAGE 65536
#define ATTN_SMEM (2 * AT_STAGE)

__global__ void __launch_bounds__(256, 1) attn_mma_kernel()
{
    extern __shared__ __align__(1024) char smem_raw[];
    const uint32_t sb = smem_u32(smem_raw);
    const int tid = threadIdx.x, wid = tid >> 5, lane = tid & 31;
    const int qt = blockIdx.x, h = blockIdx.y, b = blockIdx.z;
    const int hk = h >> 2;
    const int q0 = qt * 128;
    const int bh = b * NHEADS + h, bhk = b * NKV + hk;

    const __nv_bfloat16* Qhg = g_Qbh + ((size_t)bh * S_LEN + q0) * HDIM;
    const __nv_bfloat16* Qlg = g_Qbl + ((size_t)bh * S_LEN + q0) * HDIM;
    const __nv_bfloat16* Khg = g_Kbh + (size_t)bhk * S_LEN * HDIM;
    const __nv_bfloat16* Klg = g_Kbl + (size_t)bhk * S_LEN * HDIM;
    const __nv_bfloat16* Vhg = g_Vth + (size_t)bhk * HDIM * S_LEN;
    const __nv_bfloat16* Vlg = g_Vtl + (size_t)bhk * HDIM * S_LEN;

    // ---- stage Q ----
#pragma unroll
    for (int it = 0; it < 16; it++) {
        int u = tid + it * 256;
        int bf = u >> 11;
        int w  = u & 2047;
        int r = w >> 4, c16 = w & 15;
        int sub = c16 >> 3;
        uint32_t off = (uint32_t)(bf * 32768 + sub * 16384 + r * 128 + (c16 & 7) * 16);
        const __nv_bfloat16* g = (bf ? Qlg : Qhg) + (size_t)r * HDIM + c16 * 8;
        cpasync16(sb + SWZ(off), g);
    }
    asm volatile("cp.async.commit_group;" ::: "memory");
    asm volatile("cp.async.wait_group 0;" ::: "memory");
    __syncthreads();

    uint32_t qh[8][4], ql[8][4];
    {
        int row = wid * 16 + (lane & 15);
        int k8 = lane >> 4;
#pragma unroll
        for (int kf = 0; kf < 8; kf++) {
            int sub = kf >> 2;
            uint32_t off = (uint32_t)(sub * 16384 + row * 128 + ((kf & 3) * 16 + k8 * 8) * 2);
            uint32_t sw = SWZ(off);
            ldmx4(qh[kf], sb + sw);
            ldmx4(ql[kf], sb + 32768 + sw);
        }
    }
    __syncthreads();

    float o[16][4];
#pragma unroll
    for (int nf = 0; nf < 16; nf++)
#pragma unroll
        for (int e = 0; e < 4; e++) o[nf][e] = 0.f;

    float m0 = -1e30f, m1 = -1e30f, l0 = 0.f, l1 = 0.f;
    const int g0row = q0 + wid * 16 + (lane >> 2);

    int kt_lo = 2 * qt - 8; if (kt_lo < 0) kt_lo = 0;
    const int nt = 2 * qt + 1 - kt_lo + 1;

    auto load_kv = [&](int stage, int kt) {
        const int k0 = kt * 64;
        const uint32_t stb = sb + (uint32_t)stage * AT_STAGE;
#pragma unroll
        for (int it = 0; it < 16; it++) {
            int u = tid + it * 256;
            int buf = u >> 10;
            int w = u & 1023;
            int r = w >> 3, c16 = w & 7;
            uint32_t off = (uint32_t)(buf * 16384 + r * 128 + c16 * 16);
            const __nv_bfloat16* g;
            if (buf < 2) {
                int key = r & 63, sub = r >> 6;
                g = (buf ? Klg : Khg) + (size_t)(k0 + key) * HDIM + sub * 64 + c16 * 8;
            } else {
                g = (buf == 3 ? Vlg : Vhg) + (size_t)r * S_LEN + k0 + c16 * 8;
            }
            cpasync16(stb + SWZ(off), g);
        }
        asm volatile("cp.async.commit_group;" ::: "memory");
    };

    load_kv(0, kt_lo);
    load_kv(1, kt_lo + 1);

    for (int i = 0; i < nt; i++) {
        const int kt = kt_lo + i;
        const int k0 = kt * 64;
        if (i + 1 < nt) asm volatile("cp.async.wait_group 1;" ::: "memory");
        else            asm volatile("cp.async.wait_group 0;" ::: "memory");
        __syncthreads();
        const uint32_t stb = sb + (uint32_t)(i & 1) * AT_STAGE;

        float s[8][4];
#pragma unroll
        for (int nf = 0; nf < 8; nf++)
#pragma unroll
            for (int e = 0; e < 4; e++) s[nf][e] = 0.f;

#pragma unroll
        for (int kf = 0; kf < 8; kf++) {
            const int sub = kf >> 2;
            const int klocal = (kf & 3) * 16;
            uint32_t kbh[8][2], kbl[8][2];
#pragma unroll
            for (int np = 0; np < 4; np++) {
                int m = lane >> 3;
                int nf2 = np * 2 + (m >> 1);
                int key = nf2 * 8 + (lane & 7);
                int dl = klocal + (m & 1) * 8;
                uint32_t off = (uint32_t)((sub * 64 + key) * 128 + dl * 2);
                uint32_t sw = SWZ(off);
                uint32_t r4[4];
                ldmx4(r4, stb + sw);
                kbh[np * 2][0] = r4[0]; kbh[np * 2][1] = r4[1];
                kbh[np * 2 + 1][0] = r4[2]; kbh[np * 2 + 1][1] = r4[3];
                ldmx4(r4, stb + 16384 + sw);
                kbl[np * 2][0] = r4[0]; kbl[np * 2][1] = r4[1];
                kbl[np * 2 + 1][0] = r4[2]; kbl[np * 2 + 1][1] = r4[3];
            }
#pragma unroll
            for (int nf = 0; nf < 8; nf++) {
                mma16816(s[nf], qh[kf], kbh[nf]);
                mma16816(s[nf], qh[kf], kbl[nf]);
                mma16816(s[nf], ql[kf], kbh[nf]);
            }
        }

        if ((k0 + 63 > q0) || (q0 + 127 - k0 > WINDOW)) {
#pragma unroll
            for (int nf = 0; nf < 8; nf++)
#pragma unroll
                for (int e = 0; e < 4; e++) {
                    int row = g0row + ((e >= 2) ? 8 : 0);
                    int col = k0 + nf * 8 + (lane & 3) * 2 + (e & 1);
                    if (col > row || row - col > WINDOW) s[nf][e] = -1e30f;
                }
        }

        float mx0 = -1e30f, mx1 = -1e30f;
#pragma unroll
        for (int nf = 0; nf < 8; nf++) {
            mx0 = fmaxf(mx0, fmaxf(s[nf][0], s[nf][1]));
            mx1 = fmaxf(mx1, fmaxf(s[nf][2], s[nf][3]));
        }
        mx0 = fmaxf(mx0, __shfl_xor_sync(0xffffffffu, mx0, 1));
        mx0 = fmaxf(mx0, __shfl_xor_sync(0xffffffffu, mx0, 2));
        mx1 = fmaxf(mx1, __shfl_xor_sync(0xffffffffu, mx1, 1));
        mx1 = fmaxf(mx1, __shfl_xor_sync(0xffffffffu, mx1, 2));
        float mn0 = fmaxf(m0, mx0), mn1 = fmaxf(m1, mx1);
        float fac0 = fast_exp(m0 - mn0), fac1 = fast_exp(m1 - mn1);
        m0 = mn0; m1 = mn1;

        uint32_t ph[8][2], pl[8][2];
        float ps0 = 0.f, ps1 = 0.f;
#pragma unroll
        for (int nf = 0; nf < 8; nf++) {
            float p0 = fast_exp(s[nf][0] - mn0);
            float p1 = fast_exp(s[nf][1] - mn0);
            float p2 = fast_exp(s[nf][2] - mn1);
            float p3 = fast_exp(s[nf][3] - mn1);
            ps0 += p0 + p1; ps1 += p2 + p3;
            __nv_bfloat16 h0b, lo0, h1b, lo1, h2b, lo2, h3b, lo3;
            split1(p0, h0b, lo0); split1(p1, h1b, lo1);
            split1(p2, h2b, lo2); split1(p3, h3b, lo3);
            __nv_bfloat162 t;
            t = __halves2bfloat162(h0b, h1b);  ph[nf][0] = *reinterpret_cast<uint32_t*>(&t);
            t = __halves2bfloat162(h2b, h3b);  ph[nf][1] = *reinterpret_cast<uint32_t*>(&t);
            t = __halves2bfloat162(lo0, lo1);  pl[nf][0] = *reinterpret_cast<uint32_t*>(&t);
            t = __halves2bfloat162(lo2, lo3);  pl[nf][1] = *reinterpret_cast<uint32_t*>(&t);
        }
        ps0 += __shfl_xor_sync(0xffffffffu, ps0, 1);
        ps0 += __shfl_xor_sync(0xffffffffu, ps0, 2);
        ps1 += __shfl_xor_sync(0xffffffffu, ps1, 1);
        ps1 += __shfl_xor_sync(0xffffffffu, ps1, 2);
        l0 = l0 * fac0 + ps0;
        l1 = l1 * fac1 + ps1;

#pragma unroll
        for (int nf = 0; nf < 16; nf++) {
            o[nf][0] *= fac0; o[nf][1] *= fac0;
            o[nf][2] *= fac1; o[nf][3] *= fac1;
        }

#pragma unroll
        for (int kf2 = 0; kf2 < 4; kf2++) {
            uint32_t pah[4] = { ph[2 * kf2][0], ph[2 * kf2][1],
                                ph[2 * kf2 + 1][0], ph[2 * kf2 + 1][1] };
            uint32_t pal[4] = { pl[2 * kf2][0], pl[2 * kf2][1],
                                pl[2 * kf2 + 1][0], pl[2 * kf2 + 1][1] };
#pragma unroll
            for (int np = 0; np < 8; np++) {
                int m = lane >> 3;
                int drow = (np * 2 + (m >> 1)) * 8 + (lane & 7);
                int kl = kf2 * 16 + (m & 1) * 8;
                uint32_t off = (uint32_t)(32768 + drow * 128 + kl * 2);
                uint32_t sw = SWZ(off);
                uint32_t r4[4], r4l[4];
                ldmx4(r4,  stb + sw);
                ldmx4(r4l, stb + 16384 + sw);
                uint32_t vb0[2] = { r4[0], r4[1] },  vb1[2] = { r4[2], r4[3] };
                uint32_t vl0[2] = { r4l[0], r4l[1] }, vl1[2] = { r4l[2], r4l[3] };
                mma16816(o[np * 2],     pah, vb0);
                mma16816(o[np * 2],     pah, vl0);
                mma16816(o[np * 2],     pal, vb0);
                mma16816(o[np * 2 + 1], pah, vb1);
                mma16816(o[np * 2 + 1], pah, vl1);
                mma16816(o[np * 2 + 1], pal, vb1);
            }
        }
        __syncthreads();
        if (i + 2 < nt) load_kv(i & 1, kt + 2);
    }

    // ---- write O as bf16 hi/lo row-major [m, h*128+d] ----
    const float inv0 = 1.f / l0, inv1 = 1.f / l1;
    const int r0 = wid * 16 + (lane >> 2);
    const int c0 = (lane & 3) * 2;
    const size_t rowA = ((size_t)(b * S_LEN + q0 + r0)) * HID + h * HDIM;
    const size_t rowB = ((size_t)(b * S_LEN + q0 + r0 + 8)) * HID + h * HDIM;
#pragma unroll
    for (int nf = 0; nf < 16; nf++) {
        int d = nf * 8 + c0;
        __nv_bfloat16 h0b, l0b, h1b, l1b;
        split1(o[nf][0] * inv0, h0b, l0b);
        split1(o[nf][1] * inv0, h1b, l1b);
        *reinterpret_cast<__nv_bfloat162*>(g_Ohi + rowA + d) = __halves2bfloat162(h0b, h1b);
        *reinterpret_cast<__nv_bfloat162*>(g_Olo + rowA + d) = __halves2bfloat162(l0b, l1b);
        split1(o[nf][2] * inv1, h0b, l0b);
        split1(o[nf][3] * inv1, h1b, l1b);
        *reinterpret_cast<__nv_bfloat162*>(g_Ohi + rowB + d) = __halves2bfloat162(h0b, h1b);
        *reinterpret_cast<__nv_bfloat162*>(g_Olo + rowB + d) = __halves2bfloat162(l0b, l1b);
    }
}

// ---------------------------------------------------------------------------
extern "C" void kernel_launch(void* const* d_in, const int* in_sizes, int n_in,
                              void* d_out, int out_size)
{
    (void)in_sizes; (void)n_in; (void)out_size;
    const float* hidden = (const float*)d_in[0];
    const float* Wq     = (const float*)d_in[1];
    const float* Wk     = (const float*)d_in[2];
    const float* Wv     = (const float*)d_in[3];
    const float* Wo     = (const float*)d_in[4];
    float* out          = (float*)d_out;

    __nv_bfloat16 *xhi, *xlo, *wqh, *wql, *wkh, *wkl, *wvh, *wvl, *woh, *wol, *ohi, *olo;
    __nv_bfloat16 *qbh, *qbl, *kbh, *kbl;
    cudaGetSymbolAddress((void**)&xhi, g_Xhi);  cudaGetSymbolAddress((void**)&xlo, g_Xlo);
    cudaGetSymbolAddress((void**)&wqh, g_WqThi); cudaGetSymbolAddress((void**)&wql, g_WqTlo);
    cudaGetSymbolAddress((void**)&wkh, g_WkThi); cudaGetSymbolAddress((void**)&wkl, g_WkTlo);
    cudaGetSymbolAddress((void**)&wvh, g_WvThi); cudaGetSymbolAddress((void**)&wvl, g_WvTlo);
    cudaGetSymbolAddress((void**)&woh, g_WoThi); cudaGetSymbolAddress((void**)&wol, g_WoTlo);
    cudaGetSymbolAddress((void**)&ohi, g_Ohi);   cudaGetSymbolAddress((void**)&olo, g_Olo);
    cudaGetSymbolAddress((void**)&qbh, g_Qbh);   cudaGetSymbolAddress((void**)&qbl, g_Qbl);
    cudaGetSymbolAddress((void**)&kbh, g_Kbh);   cudaGetSymbolAddress((void**)&kbl, g_Kbl);

    cudaFuncSetAttribute(mma_gemm_kernel,
                         cudaFuncAttributeMaxDynamicSharedMemorySize, GEMM_SMEM);
    cudaFuncSetAttribute(attn_mma_kernel,
                         cudaFuncAttributeMaxDynamicSharedMemorySize, ATTN_SMEM);

    // lazy one-time creation of streams/events (host-side only; first call is
    // the uncaptured correctness run, so creation never happens during capture)
    static bool inited = false;
    static cudaStream_t s1, s2;
    static cudaEvent_t evRoot, evWq, evX, evK, evV;
    if (!inited) {
        cudaStreamCreateWithFlags(&s1, cudaStreamNonBlocking);
        cudaStreamCreateWithFlags(&s2, cudaStreamNonBlocking);
        cudaEventCreateWithFlags(&evRoot, cudaEventDisableTiming);
        cudaEventCreateWithFlags(&evWq,   cudaEventDisableTiming);
        cudaEventCreateWithFlags(&evX,    cudaEventDisableTiming);
        cudaEventCreateWithFlags(&evK,    cudaEventDisableTiming);
        cudaEventCreateWithFlags(&evV,    cudaEventDisableTiming);
        inited = true;
    }

    const float qscale = 1.0f / sqrtf((float)HDIM);

    // fork side streams from the main (captured) stream
    cudaEventRecord(evRoot, 0);
    cudaStreamWaitEvent(s1, evRoot, 0);
    cudaStreamWaitEvent(s2, evRoot, 0);

    // s1: Wq transpose -> evWq ; Wk transpose
    {
        dim3 gq(HID / 32, HID / 32);
        transpose_split_kernel<<<gq, 256, 0, s1>>>(Wq, wqh, wql, HID, HID);
        cudaEventRecord(evWq, s1);
        dim3 gkv(KVDIM / 32, HID / 32);
        transpose_split_kernel<<<gkv, 256, 0, s1>>>(Wk, wkh, wkl, HID, KVDIM);
    }
    // s2: Wv transpose ; Wo transpose
    {
        dim3 gkv(KVDIM / 32, HID / 32);
        transpose_split_kernel<<<gkv, 256, 0, s2>>>(Wv, wvh, wvl, HID, KVDIM);
        dim3 go(HID / 32, HID / 32);
        transpose_split_kernel<<<go, 256, 0, s2>>>(Wo, woh, wol, HID, HID);
    }
    // s0: split X -> evX
    {
        int n4 = (M_ROWS * HID) / 4;
        split_rowmajor_kernel<<<(n4 + 255) / 256, 256>>>(hidden, xhi, xlo, n4);
        cudaEventRecord(evX, 0);
    }
    // s0: Q projection (needs Wq + X)
    {
        cudaStreamWaitEvent(0, evWq, 0);
        dim3 g(HID / 128, M_ROWS / 128);
        mma_gemm_kernel<<<g, 256, GEMM_SMEM>>>(xhi, xlo, wqh, wql,
                                               nullptr, qbh, qbl, qscale,
                                               HID, NHEADS, 2);
    }
    // s1: K projection (needs Wk [s1-ordered] + X)
    {
        cudaStreamWaitEvent(s1, evX, 0);
        dim3 g(KVDIM / 128, M_ROWS / 128);
        mma_gemm_kernel<<<g, 256, GEMM_SMEM, s1>>>(xhi, xlo, wkh, wkl,
                                                   nullptr, kbh, kbl, 1.0f,
                                                   KVDIM, NKV, 2);
        cudaEventRecord(evK, s1);
    }
    // s2: V projection (needs Wv [s2-ordered] + X)
    {
        cudaStreamWaitEvent(s2, evX, 0);
        dim3 g(KVDIM / 128, M_ROWS / 128);
        mma_gemm_kernel<<<g, 256, GEMM_SMEM, s2>>>(xhi, xlo, wvh, wvl,
                                                   nullptr, nullptr, nullptr, 0.f,
                                                   KVDIM, NKV, 3);
        cudaEventRecord(evV, s2);
    }
    // s0: attention (needs Q [s0-ordered], K, V) — joins s1, s2
    {
        cudaStreamWaitEvent(0, evK, 0);
        cudaStreamWaitEvent(0, evV, 0);
        dim3 g(S_LEN / 128, NHEADS, BATCH);
        attn_mma_kernel<<<g, 256, ATTN_SMEM>>>();
    }
    // s0: output projection (Wo transpose ordered before evV on s2)
    {
        dim3 go(HID / 128, M_ROWS / 128);
        mma_gemm_kernel<<<go, 256, GEMM_SMEM>>>(ohi, olo, woh, wol,
                                                out, nullptr, nullptr, 0.f,
                                                HID, NHEADS, 0);
    }
}

// round 12
// speedup vs baseline: 1.3780x; 1.3280x over previous
#include <cuda_runtime.h>
#include <cuda_bf16.h>
#include <cuda_fp16.h>
#include <math.h>
#include <stdint.h>

#define S_LEN   2048
#define BATCH   2
#define NHEADS  32
#define NKV     8
#define HDIM    128
#define HID     4096
#define KVDIM   1024
#define M_ROWS  4096   // B*S
#define WINDOW  512    // SLIDING_WINDOW // 2
#define GK      4096   // GEMM K
#define NC      (GK/64)

// ======================== scratch buffers ==================================
__device__ __half g_Xhi[(size_t)M_ROWS * HID];
__device__ __half g_Xlo[(size_t)M_ROWS * HID];
__device__ __half g_WqT[(size_t)HID * HID];
__device__ __half g_WkT[(size_t)KVDIM * HID];
__device__ __half g_WvT[(size_t)KVDIM * HID];
__device__ __half g_WoT[(size_t)HID * HID];
__device__ __half g_Ohi[(size_t)M_ROWS * HID];
__device__ __half g_Olo[(size_t)M_ROWS * HID];

// bf16 attention operands (RoPE'd)
__device__ __nv_bfloat16 g_Qbh[(size_t)BATCH * NHEADS * S_LEN * HDIM];
__device__ __nv_bfloat16 g_Qbl[(size_t)BATCH * NHEADS * S_LEN * HDIM];
__device__ __nv_bfloat16 g_Kbh[(size_t)BATCH * NKV * S_LEN * HDIM];
__device__ __nv_bfloat16 g_Kbl[(size_t)BATCH * NKV * S_LEN * HDIM];
__device__ __nv_bfloat16 g_Vth[(size_t)BATCH * NKV * HDIM * S_LEN];  // [b,hk,d,s]
__device__ __nv_bfloat16 g_Vtl[(size_t)BATCH * NKV * HDIM * S_LEN];

// ======================= low-level helpers =================================
__device__ __forceinline__ uint32_t smem_u32(const void* p) {
    uint32_t a;
    asm("{ .reg .u64 t; cvta.to.shared.u64 t, %1; cvt.u32.u64 %0, t; }"
        : "=r"(a) : "l"(p));
    return a;
}
__device__ __forceinline__ void cpasync16(uint32_t saddr, const void* g) {
    asm volatile("cp.async.cg.shared.global [%0], [%1], 16;"
                 :: "r"(saddr), "l"(g) : "memory");
}
#define SWZ(o) ((o) ^ (((o) >> 3) & 0x70))

__device__ __forceinline__ void ldmx4(uint32_t* r, uint32_t addr) {
    asm volatile("ldmatrix.sync.aligned.m8n8.x4.shared.b16 {%0,%1,%2,%3}, [%4];"
                 : "=r"(r[0]), "=r"(r[1]), "=r"(r[2]), "=r"(r[3]) : "r"(addr));
}
// bf16 MMA (attention)
__device__ __forceinline__ void mma16816(float* d, const uint32_t* a, const uint32_t* b) {
    asm volatile("mma.sync.aligned.m16n8k16.row.col.f32.bf16.bf16.f32 "
                 "{%0,%1,%2,%3}, {%4,%5,%6,%7}, {%8,%9}, {%0,%1,%2,%3};"
                 : "+f"(d[0]), "+f"(d[1]), "+f"(d[2]), "+f"(d[3])
                 : "r"(a[0]), "r"(a[1]), "r"(a[2]), "r"(a[3]),
                   "r"(b[0]), "r"(b[1]));
}
// fp16 MMA (projections)
__device__ __forceinline__ void mma16816h(float* d, const uint32_t* a, const uint32_t* b) {
    asm volatile("mma.sync.aligned.m16n8k16.row.col.f32.f16.f16.f32 "
                 "{%0,%1,%2,%3}, {%4,%5,%6,%7}, {%8,%9}, {%0,%1,%2,%3};"
                 : "+f"(d[0]), "+f"(d[1]), "+f"(d[2]), "+f"(d[3])
                 : "r"(a[0]), "r"(a[1]), "r"(a[2]), "r"(a[3]),
                   "r"(b[0]), "r"(b[1]));
}

// fast exp on FMA pipe
__device__ __forceinline__ float fast_exp(float x) {
    float y = x * 1.4426950408889634f;
    float r = rintf(y);
    float f = y - r;
    float p = 1.3697664e-3f;
    p = fmaf(p, f, 9.6784195e-3f);
    p = fmaf(p, f, 5.5503454e-2f);
    p = fmaf(p, f, 2.4022652e-1f);
    p = fmaf(p, f, 6.9314718e-1f);
    p = fmaf(p, f, 1.0f);
    int ri = (int)r;
    ri = ri < -126 ? -126 : (ri > 126 ? 126 : ri);
    float s = __int_as_float((uint32_t)(ri + 127) << 23);
    return p * s;
}

__device__ __forceinline__ void split1(float f, __nv_bfloat16& h, __nv_bfloat16& l) {
    h = __float2bfloat16_rn(f);
    l = __float2bfloat16_rn(f - __bfloat162float(h));
}
__device__ __forceinline__ void split1h(float f, __half& h, __half& l) {
    h = __float2half_rn(f);
    l = __float2half_rn(f - __half2float(h));
}

// ===================== split / transpose preprocessing =====================
__global__ void split_rowmajor_kernel(const float* __restrict__ X,
                                      __half* __restrict__ hi,
                                      __half* __restrict__ lo, int n4)
{
    int i = blockIdx.x * blockDim.x + threadIdx.x;
    if (i >= n4) return;
    float4 v = reinterpret_cast<const float4*>(X)[i];
    __half h0, h1, h2, h3, l0, l1, l2, l3;
    split1h(v.x, h0, l0); split1h(v.y, h1, l1);
    split1h(v.z, h2, l2); split1h(v.w, h3, l3);
    __half2* hp = reinterpret_cast<__half2*>(hi) + 2 * i;
    __half2* lp = reinterpret_cast<__half2*>(lo) + 2 * i;
    hp[0] = __halves2half2(h0, h1); hp[1] = __halves2half2(h2, h3);
    lp[0] = __halves2half2(l0, l1); lp[1] = __halves2half2(l2, l3);
}

// W [K, N] fp32 -> T [N, K] fp16 (single)
__global__ void transpose_half_kernel(const float* __restrict__ W,
                                      __half* __restrict__ T,
                                      int K, int N)
{
    __shared__ float t[32][33];
    int k0 = blockIdx.y * 32, n0 = blockIdx.x * 32;
    int c = threadIdx.x & 31, r = threadIdx.x >> 5;
#pragma unroll
    for (int p = 0; p < 32; p += 8)
        t[r + p][c] = W[(size_t)(k0 + r + p) * N + n0 + c];
    __syncthreads();
#pragma unroll
    for (int p = 0; p < 32; p += 8) {
        size_t o = (size_t)(n0 + r + p) * K + k0 + c;
        T[o] = __float2half_rn(t[c][r + p]);
    }
}

// =============== fp16 2-pass GEMM: C = (Ahi+Alo) @ Bh^T ====================
// CTA 128x128, 256 threads (8 warps 2x4), warp tile 64x32, K-chunk 64.
// 3-stage cp.async pipeline (48KB/stage), single sync per chunk.
// EMODE 0: C row-major fp32 [M,N].
// EMODE 2: RoPE + scale + bf16 hi/lo split, scatter to Chi/Clo [b,nH,s,d].
// EMODE 3: transpose to Vt hi/lo [b,NKV,d,s].  (tile = one head)
#define TILE_BYTES  16384
#define STAGE_BYTES (3 * TILE_BYTES)    // Ahi, Alo, Bh
#define GEMM_SMEM   (3 * STAGE_BYTES)   // 144 KB
#define SPAD        132

__device__ __forceinline__ void load_stage_gemm(
    uint32_t stage_base, int tid, int mBase, int nBase, int kb,
    const __half* __restrict__ Ahi, const __half* __restrict__ Alo,
    const __half* __restrict__ Bh)
{
#pragma unroll
    for (int u = 0; u < 4; ++u) {
        int unit = tid + u * 256;
        int r = unit >> 3, c16 = unit & 7;
        uint32_t sw = SWZ((uint32_t)(r * 128 + c16 * 16));
        size_t ga = (size_t)(mBase + r) * GK + kb + c16 * 8;
        size_t gb = (size_t)(nBase + r) * GK + kb + c16 * 8;
        cpasync16(stage_base + sw,                  Ahi + ga);
        cpasync16(stage_base + TILE_BYTES + sw,     Alo + ga);
        cpasync16(stage_base + 2 * TILE_BYTES + sw, Bh + gb);
    }
    asm volatile("cp.async.commit_group;" ::: "memory");
}

__global__ void __launch_bounds__(256, 1) mma_gemm_kernel(
    const __half* __restrict__ Ahi, const __half* __restrict__ Alo,
    const __half* __restrict__ Bh,
    float* __restrict__ C,
    __nv_bfloat16* __restrict__ Chi, __nv_bfloat16* __restrict__ Clo,
    float ropeScale, int N, int nH, int EMODE)
{
    extern __shared__ __align__(1024) char smem_raw[];
    const uint32_t sbase = smem_u32(smem_raw);
    const int tid  = threadIdx.x;
    const int wid  = tid >> 5, lane = tid & 31;
    const int wm   = wid >> 2;            // 0..1 (64 rows)
    const int wn   = wid & 3;             // 0..3 (32 cols)
    const int mBase = blockIdx.y * 128;
    const int nBase = blockIdx.x * 128;

    float acc[4][4][4];
#pragma unroll
    for (int mt = 0; mt < 4; mt++)
#pragma unroll
        for (int nt = 0; nt < 4; nt++)
#pragma unroll
            for (int e = 0; e < 4; e++) acc[mt][nt][e] = 0.f;

    load_stage_gemm(sbase + 0 * STAGE_BYTES, tid, mBase, nBase, 0,  Ahi, Alo, Bh);
    load_stage_gemm(sbase + 1 * STAGE_BYTES, tid, mBase, nBase, 64, Ahi, Alo, Bh);

    const int aRow = wm * 64 + (lane & 15);
    const int aK8  = (lane >> 4);
    const int bm   = lane >> 3;            // x4 matrix slot 0..3
    const int bRowIn = lane & 7;

    for (int c2 = 0; c2 < NC; ++c2) {
        if (c2 + 1 < NC) asm volatile("cp.async.wait_group 1;" ::: "memory");
        else             asm volatile("cp.async.wait_group 0;" ::: "memory");
        __syncthreads();   // single barrier per chunk

        if (c2 + 2 < NC)
            load_stage_gemm(sbase + ((c2 + 2) % 3) * STAGE_BYTES, tid,
                            mBase, nBase, (c2 + 2) * 64, Ahi, Alo, Bh);

        const uint32_t st   = sbase + (c2 % 3) * STAGE_BYTES;
        const uint32_t aHiB = st;
        const uint32_t aLoB = st + TILE_BYTES;
        const uint32_t bHiB = st + 2 * TILE_BYTES;

#pragma unroll
        for (int ks = 0; ks < 4; ks++) {
            uint32_t bh[4][2];
#pragma unroll
            for (int np = 0; np < 2; np++) {
                int nf2 = np * 2 + (bm >> 1);
                int brow = wn * 32 + nf2 * 8 + bRowIn;
                int dl = ks * 16 + (bm & 1) * 8;
                uint32_t sw = SWZ((uint32_t)(brow * 128 + dl * 2));
                uint32_t r4[4];
                ldmx4(r4, bHiB + sw);
                bh[np * 2][0] = r4[0];     bh[np * 2][1] = r4[1];
                bh[np * 2 + 1][0] = r4[2]; bh[np * 2 + 1][1] = r4[3];
            }
            const int ak = ks * 16 + aK8 * 8;
#pragma unroll
            for (int mt = 0; mt < 4; mt++) {
                uint32_t sw = SWZ((uint32_t)((aRow + mt * 16) * 128 + ak * 2));
                uint32_t ah[4], al[4];
                ldmx4(ah, aHiB + sw);
                ldmx4(al, aLoB + sw);
#pragma unroll
                for (int nt = 0; nt < 4; nt++) {
                    mma16816h(acc[mt][nt], ah, bh[nt]);
                    mma16816h(acc[mt][nt], al, bh[nt]);
                }
            }
        }
    }

    const int row0 = wm * 64 + (lane >> 2);
    const int col0 = wn * 32 + (lane & 3) * 2;

    if (EMODE == 0) {
#pragma unroll
        for (int mt = 0; mt < 4; mt++)
#pragma unroll
            for (int half = 0; half < 2; half++) {
                int grow = mBase + row0 + mt * 16 + half * 8;
#pragma unroll
                for (int nt = 0; nt < 4; nt++) {
                    int gcol = nBase + col0 + nt * 8;
                    *reinterpret_cast<float2*>(C + (size_t)grow * N + gcol) =
                        make_float2(acc[mt][nt][half * 2], acc[mt][nt][half * 2 + 1]);
                }
            }
        return;
    }

    // stage accumulators to smem [128][SPAD]
    __syncthreads();
    float* stage = reinterpret_cast<float*>(smem_raw);
#pragma unroll
    for (int mt = 0; mt < 4; mt++)
#pragma unroll
        for (int half = 0; half < 2; half++) {
            int r = row0 + mt * 16 + half * 8;
#pragma unroll
            for (int nt = 0; nt < 4; nt++) {
                int c = col0 + nt * 8;
                stage[r * SPAD + c]     = acc[mt][nt][half * 2];
                stage[r * SPAD + c + 1] = acc[mt][nt][half * 2 + 1];
            }
        }
    __syncthreads();

    const int b = mBase >> 11;
    const int sBase = mBase & 2047;
    const int h = nBase >> 7;               // one head per 128-wide tile

    if (EMODE == 2) {
        const size_t headBase = ((size_t)(b * nH + h) * S_LEN) * HDIM;
#pragma unroll
        for (int it = 0; it < 32; it++) {
            int pr = tid + it * 256;           // 0..8191
            int r = pr >> 6, dp = pr & 63;
            float x1 = stage[r * SPAD + dp];
            float x2 = stage[r * SPAD + dp + 64];
            int srow = sBase + r;
            float inv_freq = exp2f(-(float)dp * (13.287712379549449f / 64.0f));
            float ang = (float)srow * inv_freq;
            float c, sn;
            sincosf(ang, &sn, &c);
            float y1 = (x1 * c - x2 * sn) * ropeScale;
            float y2 = (x2 * c + x1 * sn) * ropeScale;
            size_t base = headBase + (size_t)srow * HDIM;
            __nv_bfloat16 hh, ll;
            split1(y1, hh, ll); Chi[base + dp] = hh;      Clo[base + dp] = ll;
            split1(y2, hh, ll); Chi[base + dp + 64] = hh; Clo[base + dp + 64] = ll;
        }
        return;
    }

    // EMODE 3: transpose to Vt [b,NKV,d,s] hi/lo (tile = one head)
    {
        int s2 = (tid & 63) * 2;
        int g  = tid >> 6;                  // 0..3
#pragma unroll
        for (int it = 0; it < 32; it++) {
            int d = g * 32 + it;            // 0..127
            float f0 = stage[s2 * SPAD + d];
            float f1 = stage[(s2 + 1) * SPAD + d];
            size_t base = ((size_t)(b * NKV + h) * HDIM + d) * S_LEN + sBase + s2;
            __nv_bfloat16 h0b, l0b, h1b, l1b;
            split1(f0, h0b, l0b);
            split1(f1, h1b, l1b);
            *reinterpret_cast<__nv_bfloat162*>(g_Vth + base) = __halves2bfloat162(h0b, h1b);
            *reinterpret_cast<__nv_bfloat162*>(g_Vtl + base) = __halves2bfloat162(l0b, l1b);
        }
    }
}

// ================= tensor-core flash attention (bf16 hi/lo) ================
#define AT_STAGE 65536
#define ATTN_SMEM (2 * AT_STAGE)

__global__ void __launch_bounds__(256, 1) attn_mma_kernel()
{
    extern __shared__ __align__(1024) char smem_raw[];
    const uint32_t sb = smem_u32(smem_raw);
    const int tid = threadIdx.x, wid = tid >> 5, lane = tid & 31;
    const int qt = blockIdx.x, h = blockIdx.y, b = blockIdx.z;
    const int hk = h >> 2;
    const int q0 = qt * 128;
    const int bh = b * NHEADS + h, bhk = b * NKV + hk;

    const __nv_bfloat16* Qhg = g_Qbh + ((size_t)bh * S_LEN + q0) * HDIM;
    const __nv_bfloat16* Qlg = g_Qbl + ((size_t)bh * S_LEN + q0) * HDIM;
    const __nv_bfloat16* Khg = g_Kbh + (size_t)bhk * S_LEN * HDIM;
    const __nv_bfloat16* Klg = g_Kbl + (size_t)bhk * S_LEN * HDIM;
    const __nv_bfloat16* Vhg = g_Vth + (size_t)bhk * HDIM * S_LEN;
    const __nv_bfloat16* Vlg = g_Vtl + (size_t)bhk * HDIM * S_LEN;

    // ---- stage Q ----
#pragma unroll
    for (int it = 0; it < 16; it++) {
        int u = tid + it * 256;
        int bf = u >> 11;
        int w  = u & 2047;
        int r = w >> 4, c16 = w & 15;
        int sub = c16 >> 3;
        uint32_t off = (uint32_t)(bf * 32768 + sub * 16384 + r * 128 + (c16 & 7) * 16);
        const __nv_bfloat16* g = (bf ? Qlg : Qhg) + (size_t)r * HDIM + c16 * 8;
        cpasync16(sb + SWZ(off), g);
    }
    asm volatile("cp.async.commit_group;" ::: "memory");
    asm volatile("cp.async.wait_group 0;" ::: "memory");
    __syncthreads();

    uint32_t qh[8][4], ql[8][4];
    {
        int row = wid * 16 + (lane & 15);
        int k8 = lane >> 4;
#pragma unroll
        for (int kf = 0; kf < 8; kf++) {
            int sub = kf >> 2;
            uint32_t off = (uint32_t)(sub * 16384 + row * 128 + ((kf & 3) * 16 + k8 * 8) * 2);
            uint32_t sw = SWZ(off);
            ldmx4(qh[kf], sb + sw);
            ldmx4(ql[kf], sb + 32768 + sw);
        }
    }
    __syncthreads();

    float o[16][4];
#pragma unroll
    for (int nf = 0; nf < 16; nf++)
#pragma unroll
        for (int e = 0; e < 4; e++) o[nf][e] = 0.f;

    float m0 = -1e30f, m1 = -1e30f, l0 = 0.f, l1 = 0.f;
    const int g0row = q0 + wid * 16 + (lane >> 2);

    int kt_lo = 2 * qt - 8; if (kt_lo < 0) kt_lo = 0;
    const int nt = 2 * qt + 1 - kt_lo + 1;

    auto load_kv = [&](int stage, int kt) {
        const int k0 = kt * 64;
        const uint32_t stb = sb + (uint32_t)stage * AT_STAGE;
#pragma unroll
        for (int it = 0; it < 16; it++) {
            int u = tid + it * 256;
            int buf = u >> 10;
            int w = u & 1023;
            int r = w >> 3, c16 = w & 7;
            uint32_t off = (uint32_t)(buf * 16384 + r * 128 + c16 * 16);
            const __nv_bfloat16* g;
            if (buf < 2) {
                int key = r & 63, sub = r >> 6;
                g = (buf ? Klg : Khg) + (size_t)(k0 + key) * HDIM + sub * 64 + c16 * 8;
            } else {
                g = (buf == 3 ? Vlg : Vhg) + (size_t)r * S_LEN + k0 + c16 * 8;
            }
            cpasync16(stb + SWZ(off), g);
        }
        asm volatile("cp.async.commit_group;" ::: "memory");
    };

    load_kv(0, kt_lo);
    load_kv(1, kt_lo + 1);

    for (int i = 0; i < nt; i++) {
        const int kt = kt_lo + i;
        const int k0 = kt * 64;
        if (i + 1 < nt) asm volatile("cp.async.wait_group 1;" ::: "memory");
        else            asm volatile("cp.async.wait_group 0;" ::: "memory");
        __syncthreads();
        const uint32_t stb = sb + (uint32_t)(i & 1) * AT_STAGE;

        float s[8][4];
#pragma unroll
        for (int nf = 0; nf < 8; nf++)
#pragma unroll
            for (int e = 0; e < 4; e++) s[nf][e] = 0.f;

#pragma unroll
        for (int kf = 0; kf < 8; kf++) {
            const int sub = kf >> 2;
            const int klocal = (kf & 3) * 16;
            uint32_t kbh[8][2], kbl[8][2];
#pragma unroll
            for (int np = 0; np < 4; np++) {
                int m = lane >> 3;
                int nf2 = np * 2 + (m >> 1);
                int key = nf2 * 8 + (lane & 7);
                int dl = klocal + (m & 1) * 8;
                uint32_t off = (uint32_t)((sub * 64 + key) * 128 + dl * 2);
                uint32_t sw = SWZ(off);
                uint32_t r4[4];
                ldmx4(r4, stb + sw);
                kbh[np * 2][0] = r4[0]; kbh[np * 2][1] = r4[1];
                kbh[np * 2 + 1][0] = r4[2]; kbh[np * 2 + 1][1] = r4[3];
                ldmx4(r4, stb + 16384 + sw);
                kbl[np * 2][0] = r4[0]; kbl[np * 2][1] = r4[1];
                kbl[np * 2 + 1][0] = r4[2]; kbl[np * 2 + 1][1] = r4[3];
            }
#pragma unroll
            for (int nf = 0; nf < 8; nf++) {
                mma16816(s[nf], qh[kf], kbh[nf]);
                mma16816(s[nf], qh[kf], kbl[nf]);
                mma16816(s[nf], ql[kf], kbh[nf]);
            }
        }

        if ((k0 + 63 > q0) || (q0 + 127 - k0 > WINDOW)) {
#pragma unroll
            for (int nf = 0; nf < 8; nf++)
#pragma unroll
                for (int e = 0; e < 4; e++) {
                    int row = g0row + ((e >= 2) ? 8 : 0);
                    int col = k0 + nf * 8 + (lane & 3) * 2 + (e & 1);
                    if (col > row || row - col > WINDOW) s[nf][e] = -1e30f;
                }
        }

        float mx0 = -1e30f, mx1 = -1e30f;
#pragma unroll
        for (int nf = 0; nf < 8; nf++) {
            mx0 = fmaxf(mx0, fmaxf(s[nf][0], s[nf][1]));
            mx1 = fmaxf(mx1, fmaxf(s[nf][2], s[nf][3]));
        }
        mx0 = fmaxf(mx0, __shfl_xor_sync(0xffffffffu, mx0, 1));
        mx0 = fmaxf(mx0, __shfl_xor_sync(0xffffffffu, mx0, 2));
        mx1 = fmaxf(mx1, __shfl_xor_sync(0xffffffffu, mx1, 1));
        mx1 = fmaxf(mx1, __shfl_xor_sync(0xffffffffu, mx1, 2));
        float mn0 = fmaxf(m0, mx0), mn1 = fmaxf(m1, mx1);
        float fac0 = fast_exp(m0 - mn0), fac1 = fast_exp(m1 - mn1);
        m0 = mn0; m1 = mn1;

        uint32_t ph[8][2], pl[8][2];
        float ps0 = 0.f, ps1 = 0.f;
#pragma unroll
        for (int nf = 0; nf < 8; nf++) {
            float p0 = fast_exp(s[nf][0] - mn0);
            float p1 = fast_exp(s[nf][1] - mn0);
            float p2 = fast_exp(s[nf][2] - mn1);
            float p3 = fast_exp(s[nf][3] - mn1);
            ps0 += p0 + p1; ps1 += p2 + p3;
            __nv_bfloat16 h0b, lo0, h1b, lo1, h2b, lo2, h3b, lo3;
            split1(p0, h0b, lo0); split1(p1, h1b, lo1);
            split1(p2, h2b, lo2); split1(p3, h3b, lo3);
            __nv_bfloat162 t;
            t = __halves2bfloat162(h0b, h1b);  ph[nf][0] = *reinterpret_cast<uint32_t*>(&t);
            t = __halves2bfloat162(h2b, h3b);  ph[nf][1] = *reinterpret_cast<uint32_t*>(&t);
            t = __halves2bfloat162(lo0, lo1);  pl[nf][0] = *reinterpret_cast<uint32_t*>(&t);
            t = __halves2bfloat162(lo2, lo3);  pl[nf][1] = *reinterpret_cast<uint32_t*>(&t);
        }
        ps0 += __shfl_xor_sync(0xffffffffu, ps0, 1);
        ps0 += __shfl_xor_sync(0xffffffffu, ps0, 2);
        ps1 += __shfl_xor_sync(0xffffffffu, ps1, 1);
        ps1 += __shfl_xor_sync(0xffffffffu, ps1, 2);
        l0 = l0 * fac0 + ps0;
        l1 = l1 * fac1 + ps1;

#pragma unroll
        for (int nf = 0; nf < 16; nf++) {
            o[nf][0] *= fac0; o[nf][1] *= fac0;
            o[nf][2] *= fac1; o[nf][3] *= fac1;
        }

#pragma unroll
        for (int kf2 = 0; kf2 < 4; kf2++) {
            uint32_t pah[4] = { ph[2 * kf2][0], ph[2 * kf2][1],
                                ph[2 * kf2 + 1][0], ph[2 * kf2 + 1][1] };
            uint32_t pal[4] = { pl[2 * kf2][0], pl[2 * kf2][1],
                                pl[2 * kf2 + 1][0], pl[2 * kf2 + 1][1] };
#pragma unroll
            for (int np = 0; np < 8; np++) {
                int m = lane >> 3;
                int drow = (np * 2 + (m >> 1)) * 8 + (lane & 7);
                int kl = kf2 * 16 + (m & 1) * 8;
                uint32_t off = (uint32_t)(32768 + drow * 128 + kl * 2);
                uint32_t sw = SWZ(off);
                uint32_t r4[4], r4l[4];
                ldmx4(r4,  stb + sw);
                ldmx4(r4l, stb + 16384 + sw);
                uint32_t vb0[2] = { r4[0], r4[1] },  vb1[2] = { r4[2], r4[3] };
                uint32_t vl0[2] = { r4l[0], r4l[1] }, vl1[2] = { r4l[2], r4l[3] };
                mma16816(o[np * 2],     pah, vb0);
                mma16816(o[np * 2],     pah, vl0);
                mma16816(o[np * 2],     pal, vb0);
                mma16816(o[np * 2 + 1], pah, vb1);
                mma16816(o[np * 2 + 1], pah, vl1);
                mma16816(o[np * 2 + 1], pal, vb1);
            }
        }
        __syncthreads();
        if (i + 2 < nt) load_kv(i & 1, kt + 2);
    }

    // ---- write O as fp16 hi/lo row-major [m, h*128+d] ----
    const float inv0 = 1.f / l0, inv1 = 1.f / l1;
    const int r0 = wid * 16 + (lane >> 2);
    const int c0 = (lane & 3) * 2;
    const size_t rowA = ((size_t)(b * S_LEN + q0 + r0)) * HID + h * HDIM;
    const size_t rowB = ((size_t)(b * S_LEN + q0 + r0 + 8)) * HID + h * HDIM;
#pragma unroll
    for (int nf = 0; nf < 16; nf++) {
        int d = nf * 8 + c0;
        __half h0h, l0h, h1h, l1h;
        split1h(o[nf][0] * inv0, h0h, l0h);
        split1h(o[nf][1] * inv0, h1h, l1h);
        *reinterpret_cast<__half2*>(g_Ohi + rowA + d) = __halves2half2(h0h, h1h);
        *reinterpret_cast<__half2*>(g_Olo + rowA + d) = __halves2half2(l0h, l1h);
        split1h(o[nf][2] * inv1, h0h, l0h);
        split1h(o[nf][3] * inv1, h1h, l1h);
        *reinterpret_cast<__half2*>(g_Ohi + rowB + d) = __halves2half2(h0h, h1h);
        *reinterpret_cast<__half2*>(g_Olo + rowB + d) = __halves2half2(l0h, l1h);
    }
}

// ---------------------------------------------------------------------------
extern "C" void kernel_launch(void* const* d_in, const int* in_sizes, int n_in,
                              void* d_out, int out_size)
{
    (void)in_sizes; (void)n_in; (void)out_size;
    const float* hidden = (const float*)d_in[0];
    const float* Wq     = (const float*)d_in[1];
    const float* Wk     = (const float*)d_in[2];
    const float* Wv     = (const float*)d_in[3];
    const float* Wo     = (const float*)d_in[4];
    float* out          = (float*)d_out;

    __half *xhi, *xlo, *wq, *wk, *wv, *wo, *ohi, *olo;
    __nv_bfloat16 *qbh, *qbl, *kbh, *kbl;
    cudaGetSymbolAddress((void**)&xhi, g_Xhi);  cudaGetSymbolAddress((void**)&xlo, g_Xlo);
    cudaGetSymbolAddress((void**)&wq, g_WqT);   cudaGetSymbolAddress((void**)&wk, g_WkT);
    cudaGetSymbolAddress((void**)&wv, g_WvT);   cudaGetSymbolAddress((void**)&wo, g_WoT);
    cudaGetSymbolAddress((void**)&ohi, g_Ohi);  cudaGetSymbolAddress((void**)&olo, g_Olo);
    cudaGetSymbolAddress((void**)&qbh, g_Qbh);  cudaGetSymbolAddress((void**)&qbl, g_Qbl);
    cudaGetSymbolAddress((void**)&kbh, g_Kbh);  cudaGetSymbolAddress((void**)&kbl, g_Kbl);

    cudaFuncSetAttribute(mma_gemm_kernel,
                         cudaFuncAttributeMaxDynamicSharedMemorySize, GEMM_SMEM);
    cudaFuncSetAttribute(attn_mma_kernel,
                         cudaFuncAttributeMaxDynamicSharedMemorySize, ATTN_SMEM);

    static bool inited = false;
    static cudaStream_t s1, s2;
    static cudaEvent_t evRoot, evWq, evX, evK, evV;
    if (!inited) {
        cudaStreamCreateWithFlags(&s1, cudaStreamNonBlocking);
        cudaStreamCreateWithFlags(&s2, cudaStreamNonBlocking);
        cudaEventCreateWithFlags(&evRoot, cudaEventDisableTiming);
        cudaEventCreateWithFlags(&evWq,   cudaEventDisableTiming);
        cudaEventCreateWithFlags(&evX,    cudaEventDisableTiming);
        cudaEventCreateWithFlags(&evK,    cudaEventDisableTiming);
        cudaEventCreateWithFlags(&evV,    cudaEventDisableTiming);
        inited = true;
    }

    const float qscale = 1.0f / sqrtf((float)HDIM);

    cudaEventRecord(evRoot, 0);
    cudaStreamWaitEvent(s1, evRoot, 0);
    cudaStreamWaitEvent(s2, evRoot, 0);

    // s1: Wq transpose -> evWq ; Wk transpose
    {
        dim3 gq(HID / 32, HID / 32);
        transpose_half_kernel<<<gq, 256, 0, s1>>>(Wq, wq, HID, HID);
        cudaEventRecord(evWq, s1);
        dim3 gkv(KVDIM / 32, HID / 32);
        transpose_half_kernel<<<gkv, 256, 0, s1>>>(Wk, wk, HID, KVDIM);
    }
    // s2: Wv transpose ; Wo transpose
    {
        dim3 gkv(KVDIM / 32, HID / 32);
        transpose_half_kernel<<<gkv, 256, 0, s2>>>(Wv, wv, HID, KVDIM);
        dim3 go(HID / 32, HID / 32);
        transpose_half_kernel<<<go, 256, 0, s2>>>(Wo, wo, HID, HID);
    }
    // s0: split X -> evX
    {
        int n4 = (M_ROWS * HID) / 4;
        split_rowmajor_kernel<<<(n4 + 255) / 256, 256>>>(hidden, xhi, xlo, n4);
        cudaEventRecord(evX, 0);
    }
    // s0: Q projection
    {
        cudaStreamWaitEvent(0, evWq, 0);
        dim3 g(HID / 128, M_ROWS / 128);
        mma_gemm_kernel<<<g, 256, GEMM_SMEM>>>(xhi, xlo, wq,
                                               nullptr, qbh, qbl, qscale,
                                               HID, NHEADS, 2);
    }
    // s1: K projection
    {
        cudaStreamWaitEvent(s1, evX, 0);
        dim3 g(KVDIM / 128, M_ROWS / 128);
        mma_gemm_kernel<<<g, 256, GEMM_SMEM, s1>>>(xhi, xlo, wk,
                                                   nullptr, kbh, kbl, 1.0f,
                                                   KVDIM, NKV, 2);
        cudaEventRecord(evK, s1);
    }
    // s2: V projection
    {
        cudaStreamWaitEvent(s2, evX, 0);
        dim3 g(KVDIM / 128, M_ROWS / 128);
        mma_gemm_kernel<<<g, 256, GEMM_SMEM, s2>>>(xhi, xlo, wv,
                                                   nullptr, nullptr, nullptr, 0.f,
                                                   KVDIM, NKV, 3);
        cudaEventRecord(evV, s2);
    }
    // s0: attention
    {
        cudaStreamWaitEvent(0, evK, 0);
        cudaStreamWaitEvent(0, evV, 0);
        dim3 g(S_LEN / 128, NHEADS, BATCH);
        attn_mma_kernel<<<g, 256, ATTN_SMEM>>>();
    }
    // s0: output projection
    {
        dim3 go(HID / 128, M_ROWS / 128);
        mma_gemm_kernel<<<go, 256, GEMM_SMEM>>>(ohi, olo, wo,
                                                out, nullptr, nullptr, 0.f,
                                                HID, NHEADS, 0);
    }
}

// round 13
// speedup vs baseline: 1.4214x; 1.0315x over previous
#include <cuda_runtime.h>
#include <cuda_bf16.h>
#include <cuda_fp16.h>
#include <math.h>
#include <stdint.h>

#define S_LEN   2048
#define BATCH   2
#define NHEADS  32
#define NKV     8
#define HDIM    128
#define HID     4096
#define KVDIM   1024
#define M_ROWS  4096   // B*S
#define WINDOW  512    // SLIDING_WINDOW // 2
#define GK      4096   // GEMM K
#define NC      (GK/64)

// ======================== scratch buffers ==================================
__device__ __half g_Xhi[(size_t)M_ROWS * HID];
__device__ __half g_Xlo[(size_t)M_ROWS * HID];
__device__ __half g_WqT[(size_t)HID * HID];
__device__ __half g_WkT[(size_t)KVDIM * HID];
__device__ __half g_WvT[(size_t)KVDIM * HID];
__device__ __half g_WoT[(size_t)HID * HID];
__device__ __half g_Ohi[(size_t)M_ROWS * HID];
__device__ __half g_Olo[(size_t)M_ROWS * HID];

// fp16 attention operands (RoPE'd)
__device__ __half g_Qbh[(size_t)BATCH * NHEADS * S_LEN * HDIM];
__device__ __half g_Qbl[(size_t)BATCH * NHEADS * S_LEN * HDIM];
__device__ __half g_Kb[(size_t)BATCH * NKV * S_LEN * HDIM];          // single fp16
__device__ __half g_Vt[(size_t)BATCH * NKV * HDIM * S_LEN];          // single fp16 [b,hk,d,s]

// ======================= low-level helpers =================================
__device__ __forceinline__ uint32_t smem_u32(const void* p) {
    uint32_t a;
    asm("{ .reg .u64 t; cvta.to.shared.u64 t, %1; cvt.u32.u64 %0, t; }"
        : "=r"(a) : "l"(p));
    return a;
}
__device__ __forceinline__ void cpasync16(uint32_t saddr, const void* g) {
    asm volatile("cp.async.cg.shared.global [%0], [%1], 16;"
                 :: "r"(saddr), "l"(g) : "memory");
}
#define SWZ(o) ((o) ^ (((o) >> 3) & 0x70))

__device__ __forceinline__ void ldmx4(uint32_t* r, uint32_t addr) {
    asm volatile("ldmatrix.sync.aligned.m8n8.x4.shared.b16 {%0,%1,%2,%3}, [%4];"
                 : "=r"(r[0]), "=r"(r[1]), "=r"(r[2]), "=r"(r[3]) : "r"(addr));
}
// fp16 MMA
__device__ __forceinline__ void mma16816h(float* d, const uint32_t* a, const uint32_t* b) {
    asm volatile("mma.sync.aligned.m16n8k16.row.col.f32.f16.f16.f32 "
                 "{%0,%1,%2,%3}, {%4,%5,%6,%7}, {%8,%9}, {%0,%1,%2,%3};"
                 : "+f"(d[0]), "+f"(d[1]), "+f"(d[2]), "+f"(d[3])
                 : "r"(a[0]), "r"(a[1]), "r"(a[2]), "r"(a[3]),
                   "r"(b[0]), "r"(b[1]));
}

// fast exp on FMA pipe
__device__ __forceinline__ float fast_exp(float x) {
    float y = x * 1.4426950408889634f;
    float r = rintf(y);
    float f = y - r;
    float p = 1.3697664e-3f;
    p = fmaf(p, f, 9.6784195e-3f);
    p = fmaf(p, f, 5.5503454e-2f);
    p = fmaf(p, f, 2.4022652e-1f);
    p = fmaf(p, f, 6.9314718e-1f);
    p = fmaf(p, f, 1.0f);
    int ri = (int)r;
    ri = ri < -126 ? -126 : (ri > 126 ? 126 : ri);
    float s = __int_as_float((uint32_t)(ri + 127) << 23);
    return p * s;
}

__device__ __forceinline__ void split1h(float f, __half& h, __half& l) {
    h = __float2half_rn(f);
    l = __float2half_rn(f - __half2float(h));
}

// ===================== split / transpose preprocessing =====================
__global__ void split_rowmajor_kernel(const float* __restrict__ X,
                                      __half* __restrict__ hi,
                                      __half* __restrict__ lo, int n4)
{
    int i = blockIdx.x * blockDim.x + threadIdx.x;
    if (i >= n4) return;
    float4 v = reinterpret_cast<const float4*>(X)[i];
    __half h0, h1, h2, h3, l0, l1, l2, l3;
    split1h(v.x, h0, l0); split1h(v.y, h1, l1);
    split1h(v.z, h2, l2); split1h(v.w, h3, l3);
    __half2* hp = reinterpret_cast<__half2*>(hi) + 2 * i;
    __half2* lp = reinterpret_cast<__half2*>(lo) + 2 * i;
    hp[0] = __halves2half2(h0, h1); hp[1] = __halves2half2(h2, h3);
    lp[0] = __halves2half2(l0, l1); lp[1] = __halves2half2(l2, l3);
}

// W [K, N] fp32 -> T [N, K] fp16 (single)
__global__ void transpose_half_kernel(const float* __restrict__ W,
                                      __half* __restrict__ T,
                                      int K, int N)
{
    __shared__ float t[32][33];
    int k0 = blockIdx.y * 32, n0 = blockIdx.x * 32;
    int c = threadIdx.x & 31, r = threadIdx.x >> 5;
#pragma unroll
    for (int p = 0; p < 32; p += 8)
        t[r + p][c] = W[(size_t)(k0 + r + p) * N + n0 + c];
    __syncthreads();
#pragma unroll
    for (int p = 0; p < 32; p += 8) {
        size_t o = (size_t)(n0 + r + p) * K + k0 + c;
        T[o] = __float2half_rn(t[c][r + p]);
    }
}

// =============== fp16 2-pass GEMM: C = (Ahi+Alo) @ Bh^T ====================
// CTA 128x128, 256 threads (8 warps 2x4), warp tile 64x32, K-chunk 64.
// 3-stage cp.async pipeline (48KB/stage), single sync per chunk.
// EMODE 0: C row-major fp32 [M,N].
// EMODE 2: RoPE + scale + fp16 hi/lo split, scatter to Chi/Clo [b,nH,s,d].
// EMODE 3: transpose to Vt single fp16 [b,NKV,d,s].  (tile = one head)
// EMODE 4: RoPE + single fp16, scatter to Chi [b,nH,s,d].
#define TILE_BYTES  16384
#define STAGE_BYTES (3 * TILE_BYTES)    // Ahi, Alo, Bh
#define GEMM_SMEM   (3 * STAGE_BYTES)   // 144 KB
#define SPAD        132

__device__ __forceinline__ void load_stage_gemm(
    uint32_t stage_base, int tid, int mBase, int nBase, int kb,
    const __half* __restrict__ Ahi, const __half* __restrict__ Alo,
    const __half* __restrict__ Bh)
{
#pragma unroll
    for (int u = 0; u < 4; ++u) {
        int unit = tid + u * 256;
        int r = unit >> 3, c16 = unit & 7;
        uint32_t sw = SWZ((uint32_t)(r * 128 + c16 * 16));
        size_t ga = (size_t)(mBase + r) * GK + kb + c16 * 8;
        size_t gb = (size_t)(nBase + r) * GK + kb + c16 * 8;
        cpasync16(stage_base + sw,                  Ahi + ga);
        cpasync16(stage_base + TILE_BYTES + sw,     Alo + ga);
        cpasync16(stage_base + 2 * TILE_BYTES + sw, Bh + gb);
    }
    asm volatile("cp.async.commit_group;" ::: "memory");
}

__global__ void __launch_bounds__(256, 1) mma_gemm_kernel(
    const __half* __restrict__ Ahi, const __half* __restrict__ Alo,
    const __half* __restrict__ Bh,
    float* __restrict__ C,
    __half* __restrict__ Chi, __half* __restrict__ Clo,
    float ropeScale, int N, int nH, int EMODE)
{
    extern __shared__ __align__(1024) char smem_raw[];
    const uint32_t sbase = smem_u32(smem_raw);
    const int tid  = threadIdx.x;
    const int wid  = tid >> 5, lane = tid & 31;
    const int wm   = wid >> 2;            // 0..1 (64 rows)
    const int wn   = wid & 3;             // 0..3 (32 cols)
    const int mBase = blockIdx.y * 128;
    const int nBase = blockIdx.x * 128;

    float acc[4][4][4];
#pragma unroll
    for (int mt = 0; mt < 4; mt++)
#pragma unroll
        for (int nt = 0; nt < 4; nt++)
#pragma unroll
            for (int e = 0; e < 4; e++) acc[mt][nt][e] = 0.f;

    load_stage_gemm(sbase + 0 * STAGE_BYTES, tid, mBase, nBase, 0,  Ahi, Alo, Bh);
    load_stage_gemm(sbase + 1 * STAGE_BYTES, tid, mBase, nBase, 64, Ahi, Alo, Bh);

    const int aRow = wm * 64 + (lane & 15);
    const int aK8  = (lane >> 4);
    const int bm   = lane >> 3;            // x4 matrix slot 0..3
    const int bRowIn = lane & 7;

    for (int c2 = 0; c2 < NC; ++c2) {
        if (c2 + 1 < NC) asm volatile("cp.async.wait_group 1;" ::: "memory");
        else             asm volatile("cp.async.wait_group 0;" ::: "memory");
        __syncthreads();

        if (c2 + 2 < NC)
            load_stage_gemm(sbase + ((c2 + 2) % 3) * STAGE_BYTES, tid,
                            mBase, nBase, (c2 + 2) * 64, Ahi, Alo, Bh);

        const uint32_t st   = sbase + (c2 % 3) * STAGE_BYTES;
        const uint32_t aHiB = st;
        const uint32_t aLoB = st + TILE_BYTES;
        const uint32_t bHiB = st + 2 * TILE_BYTES;

#pragma unroll
        for (int ks = 0; ks < 4; ks++) {
            uint32_t bh[4][2];
#pragma unroll
            for (int np = 0; np < 2; np++) {
                int nf2 = np * 2 + (bm >> 1);
                int brow = wn * 32 + nf2 * 8 + bRowIn;
                int dl = ks * 16 + (bm & 1) * 8;
                uint32_t sw = SWZ((uint32_t)(brow * 128 + dl * 2));
                uint32_t r4[4];
                ldmx4(r4, bHiB + sw);
                bh[np * 2][0] = r4[0];     bh[np * 2][1] = r4[1];
                bh[np * 2 + 1][0] = r4[2]; bh[np * 2 + 1][1] = r4[3];
            }
            const int ak = ks * 16 + aK8 * 8;
#pragma unroll
            for (int mt = 0; mt < 4; mt++) {
                uint32_t sw = SWZ((uint32_t)((aRow + mt * 16) * 128 + ak * 2));
                uint32_t ah[4], al[4];
                ldmx4(ah, aHiB + sw);
                ldmx4(al, aLoB + sw);
#pragma unroll
                for (int nt = 0; nt < 4; nt++) {
                    mma16816h(acc[mt][nt], ah, bh[nt]);
                    mma16816h(acc[mt][nt], al, bh[nt]);
                }
            }
        }
    }

    const int row0 = wm * 64 + (lane >> 2);
    const int col0 = wn * 32 + (lane & 3) * 2;

    if (EMODE == 0) {
#pragma unroll
        for (int mt = 0; mt < 4; mt++)
#pragma unroll
            for (int half = 0; half < 2; half++) {
                int grow = mBase + row0 + mt * 16 + half * 8;
#pragma unroll
                for (int nt = 0; nt < 4; nt++) {
                    int gcol = nBase + col0 + nt * 8;
                    *reinterpret_cast<float2*>(C + (size_t)grow * N + gcol) =
                        make_float2(acc[mt][nt][half * 2], acc[mt][nt][half * 2 + 1]);
                }
            }
        return;
    }

    // stage accumulators to smem [128][SPAD]
    __syncthreads();
    float* stage = reinterpret_cast<float*>(smem_raw);
#pragma unroll
    for (int mt = 0; mt < 4; mt++)
#pragma unroll
        for (int half = 0; half < 2; half++) {
            int r = row0 + mt * 16 + half * 8;
#pragma unroll
            for (int nt = 0; nt < 4; nt++) {
                int c = col0 + nt * 8;
                stage[r * SPAD + c]     = acc[mt][nt][half * 2];
                stage[r * SPAD + c + 1] = acc[mt][nt][half * 2 + 1];
            }
        }
    __syncthreads();

    const int b = mBase >> 11;
    const int sBase = mBase & 2047;
    const int h = nBase >> 7;               // one head per 128-wide tile

    if (EMODE == 2 || EMODE == 4) {
        const size_t headBase = ((size_t)(b * nH + h) * S_LEN) * HDIM;
#pragma unroll
        for (int it = 0; it < 32; it++) {
            int pr = tid + it * 256;           // 0..8191
            int r = pr >> 6, dp = pr & 63;
            float x1 = stage[r * SPAD + dp];
            float x2 = stage[r * SPAD + dp + 64];
            int srow = sBase + r;
            float inv_freq = exp2f(-(float)dp * (13.287712379549449f / 64.0f));
            float ang = (float)srow * inv_freq;
            float c, sn;
            sincosf(ang, &sn, &c);
            float y1 = (x1 * c - x2 * sn) * ropeScale;
            float y2 = (x2 * c + x1 * sn) * ropeScale;
            size_t base = headBase + (size_t)srow * HDIM;
            if (EMODE == 2) {
                __half hh, ll;
                split1h(y1, hh, ll); Chi[base + dp] = hh;      Clo[base + dp] = ll;
                split1h(y2, hh, ll); Chi[base + dp + 64] = hh; Clo[base + dp + 64] = ll;
            } else {
                Chi[base + dp]      = __float2half_rn(y1);
                Chi[base + dp + 64] = __float2half_rn(y2);
            }
        }
        return;
    }

    // EMODE 3: transpose to Vt single fp16 [b,NKV,d,s] (tile = one head)
    {
        int s2 = (tid & 63) * 2;
        int g  = tid >> 6;                  // 0..3
#pragma unroll
        for (int it = 0; it < 32; it++) {
            int d = g * 32 + it;            // 0..127
            float f0 = stage[s2 * SPAD + d];
            float f1 = stage[(s2 + 1) * SPAD + d];
            size_t base = ((size_t)(b * NKV + h) * HDIM + d) * S_LEN + sBase + s2;
            *reinterpret_cast<__half2*>(g_Vt + base) =
                __halves2half2(__float2half_rn(f0), __float2half_rn(f1));
        }
    }
}

// ============ tensor-core flash attention (fp16, Q/P hi/lo) ================
// Stage = [K 16KB][Vt 16KB] = 32KB, 2 stages. Q staged in same 64KB first.
#define AT_STAGE 32768
#define ATTN_SMEM 65536

__global__ void __launch_bounds__(256, 1) attn_mma_kernel()
{
    extern __shared__ __align__(1024) char smem_raw[];
    const uint32_t sb = smem_u32(smem_raw);
    const int tid = threadIdx.x, wid = tid >> 5, lane = tid & 31;
    const int qt = blockIdx.x, h = blockIdx.y, b = blockIdx.z;
    const int hk = h >> 2;
    const int q0 = qt * 128;
    const int bh = b * NHEADS + h, bhk = b * NKV + hk;

    const __half* Qhg = g_Qbh + ((size_t)bh * S_LEN + q0) * HDIM;
    const __half* Qlg = g_Qbl + ((size_t)bh * S_LEN + q0) * HDIM;
    const __half* Kg  = g_Kb + (size_t)bhk * S_LEN * HDIM;
    const __half* Vg  = g_Vt + (size_t)bhk * HDIM * S_LEN;

    // ---- stage Q (hi at sb+0, lo at sb+32768; consumed before KV stages) ----
#pragma unroll
    for (int it = 0; it < 16; it++) {
        int u = tid + it * 256;
        int bf = u >> 11;
        int w  = u & 2047;
        int r = w >> 4, c16 = w & 15;
        int sub = c16 >> 3;
        uint32_t off = (uint32_t)(bf * 32768 + sub * 16384 + r * 128 + (c16 & 7) * 16);
        const __half* g = (bf ? Qlg : Qhg) + (size_t)r * HDIM + c16 * 8;
        cpasync16(sb + SWZ(off), g);
    }
    asm volatile("cp.async.commit_group;" ::: "memory");
    asm volatile("cp.async.wait_group 0;" ::: "memory");
    __syncthreads();

    uint32_t qh[8][4], ql[8][4];
    {
        int row = wid * 16 + (lane & 15);
        int k8 = lane >> 4;
#pragma unroll
        for (int kf = 0; kf < 8; kf++) {
            int sub = kf >> 2;
            uint32_t off = (uint32_t)(sub * 16384 + row * 128 + ((kf & 3) * 16 + k8 * 8) * 2);
            uint32_t sw = SWZ(off);
            ldmx4(qh[kf], sb + sw);
            ldmx4(ql[kf], sb + 32768 + sw);
        }
    }
    __syncthreads();

    float o[16][4];
#pragma unroll
    for (int nf = 0; nf < 16; nf++)
#pragma unroll
        for (int e = 0; e < 4; e++) o[nf][e] = 0.f;

    float m0 = -1e30f, m1 = -1e30f, l0 = 0.f, l1 = 0.f;
    const int g0row = q0 + wid * 16 + (lane >> 2);

    int kt_lo = 2 * qt - 8; if (kt_lo < 0) kt_lo = 0;
    const int nt = 2 * qt + 1 - kt_lo + 1;

    auto load_kv = [&](int stage, int kt) {
        const int k0 = kt * 64;
        const uint32_t stb = sb + (uint32_t)stage * AT_STAGE;
#pragma unroll
        for (int it = 0; it < 8; it++) {
            int u = tid + it * 256;            // 0..2047
            int buf = u >> 10;                 // 0 = K, 1 = Vt
            int w = u & 1023;
            int r = w >> 3, c16 = w & 7;
            uint32_t off = (uint32_t)(buf * 16384 + r * 128 + c16 * 16);
            const __half* g;
            if (buf == 0) {
                int key = r & 63, sub = r >> 6;
                g = Kg + (size_t)(k0 + key) * HDIM + sub * 64 + c16 * 8;
            } else {
                g = Vg + (size_t)r * S_LEN + k0 + c16 * 8;
            }
            cpasync16(stb + SWZ(off), g);
        }
        asm volatile("cp.async.commit_group;" ::: "memory");
    };

    load_kv(0, kt_lo);
    load_kv(1, kt_lo + 1);

    for (int i = 0; i < nt; i++) {
        const int kt = kt_lo + i;
        const int k0 = kt * 64;
        if (i + 1 < nt) asm volatile("cp.async.wait_group 1;" ::: "memory");
        else            asm volatile("cp.async.wait_group 0;" ::: "memory");
        __syncthreads();
        const uint32_t stb = sb + (uint32_t)(i & 1) * AT_STAGE;

        // ---- S = Q K^T (2-pass: qh·k + ql·k) ----
        float s[8][4];
#pragma unroll
        for (int nf = 0; nf < 8; nf++)
#pragma unroll
            for (int e = 0; e < 4; e++) s[nf][e] = 0.f;

#pragma unroll
        for (int kf = 0; kf < 8; kf++) {
            const int sub = kf >> 2;
            const int klocal = (kf & 3) * 16;
            uint32_t kb[8][2];
#pragma unroll
            for (int np = 0; np < 4; np++) {
                int m = lane >> 3;
                int nf2 = np * 2 + (m >> 1);
                int key = nf2 * 8 + (lane & 7);
                int dl = klocal + (m & 1) * 8;
                uint32_t off = (uint32_t)((sub * 64 + key) * 128 + dl * 2);
                uint32_t sw = SWZ(off);
                uint32_t r4[4];
                ldmx4(r4, stb + sw);
                kb[np * 2][0] = r4[0]; kb[np * 2][1] = r4[1];
                kb[np * 2 + 1][0] = r4[2]; kb[np * 2 + 1][1] = r4[3];
            }
#pragma unroll
            for (int nf = 0; nf < 8; nf++) {
                mma16816h(s[nf], qh[kf], kb[nf]);
                mma16816h(s[nf], ql[kf], kb[nf]);
            }
        }

        if ((k0 + 63 > q0) || (q0 + 127 - k0 > WINDOW)) {
#pragma unroll
            for (int nf = 0; nf < 8; nf++)
#pragma unroll
                for (int e = 0; e < 4; e++) {
                    int row = g0row + ((e >= 2) ? 8 : 0);
                    int col = k0 + nf * 8 + (lane & 3) * 2 + (e & 1);
                    if (col > row || row - col > WINDOW) s[nf][e] = -1e30f;
                }
        }

        float mx0 = -1e30f, mx1 = -1e30f;
#pragma unroll
        for (int nf = 0; nf < 8; nf++) {
            mx0 = fmaxf(mx0, fmaxf(s[nf][0], s[nf][1]));
            mx1 = fmaxf(mx1, fmaxf(s[nf][2], s[nf][3]));
        }
        mx0 = fmaxf(mx0, __shfl_xor_sync(0xffffffffu, mx0, 1));
        mx0 = fmaxf(mx0, __shfl_xor_sync(0xffffffffu, mx0, 2));
        mx1 = fmaxf(mx1, __shfl_xor_sync(0xffffffffu, mx1, 1));
        mx1 = fmaxf(mx1, __shfl_xor_sync(0xffffffffu, mx1, 2));
        float mn0 = fmaxf(m0, mx0), mn1 = fmaxf(m1, mx1);
        float fac0 = fast_exp(m0 - mn0), fac1 = fast_exp(m1 - mn1);
        m0 = mn0; m1 = mn1;

        uint32_t ph[8][2], pl[8][2];
        float ps0 = 0.f, ps1 = 0.f;
#pragma unroll
        for (int nf = 0; nf < 8; nf++) {
            float p0 = fast_exp(s[nf][0] - mn0);
            float p1 = fast_exp(s[nf][1] - mn0);
            float p2 = fast_exp(s[nf][2] - mn1);
            float p3 = fast_exp(s[nf][3] - mn1);
            ps0 += p0 + p1; ps1 += p2 + p3;
            __half h0h, lo0, h1h, lo1, h2h, lo2, h3h, lo3;
            split1h(p0, h0h, lo0); split1h(p1, h1h, lo1);
            split1h(p2, h2h, lo2); split1h(p3, h3h, lo3);
            __half2 t;
            t = __halves2half2(h0h, h1h);  ph[nf][0] = *reinterpret_cast<uint32_t*>(&t);
            t = __halves2half2(h2h, h3h);  ph[nf][1] = *reinterpret_cast<uint32_t*>(&t);
            t = __halves2half2(lo0, lo1);  pl[nf][0] = *reinterpret_cast<uint32_t*>(&t);
            t = __halves2half2(lo2, lo3);  pl[nf][1] = *reinterpret_cast<uint32_t*>(&t);
        }
        ps0 += __shfl_xor_sync(0xffffffffu, ps0, 1);
        ps0 += __shfl_xor_sync(0xffffffffu, ps0, 2);
        ps1 += __shfl_xor_sync(0xffffffffu, ps1, 1);
        ps1 += __shfl_xor_sync(0xffffffffu, ps1, 2);
        l0 = l0 * fac0 + ps0;
        l1 = l1 * fac1 + ps1;

#pragma unroll
        for (int nf = 0; nf < 16; nf++) {
            o[nf][0] *= fac0; o[nf][1] *= fac0;
            o[nf][2] *= fac1; o[nf][3] *= fac1;
        }

        // ---- O += P @ Vt (2-pass: ph·v + pl·v) ----
#pragma unroll
        for (int kf2 = 0; kf2 < 4; kf2++) {
            uint32_t pah[4] = { ph[2 * kf2][0], ph[2 * kf2][1],
                                ph[2 * kf2 + 1][0], ph[2 * kf2 + 1][1] };
            uint32_t pal[4] = { pl[2 * kf2][0], pl[2 * kf2][1],
                                pl[2 * kf2 + 1][0], pl[2 * kf2 + 1][1] };
#pragma unroll
            for (int np = 0; np < 8; np++) {
                int m = lane >> 3;
                int drow = (np * 2 + (m >> 1)) * 8 + (lane & 7);
                int kl = kf2 * 16 + (m & 1) * 8;
                uint32_t off = (uint32_t)(16384 + drow * 128 + kl * 2);
                uint32_t sw = SWZ(off);
                uint32_t r4[4];
                ldmx4(r4, stb + sw);
                uint32_t vb0[2] = { r4[0], r4[1] }, vb1[2] = { r4[2], r4[3] };
                mma16816h(o[np * 2],     pah, vb0);
                mma16816h(o[np * 2],     pal, vb0);
                mma16816h(o[np * 2 + 1], pah, vb1);
                mma16816h(o[np * 2 + 1], pal, vb1);
            }
        }
        __syncthreads();
        if (i + 2 < nt) load_kv(i & 1, kt + 2);
    }

    // ---- write O as fp16 hi/lo row-major [m, h*128+d] ----
    const float inv0 = 1.f / l0, inv1 = 1.f / l1;
    const int r0 = wid * 16 + (lane >> 2);
    const int c0 = (lane & 3) * 2;
    const size_t rowA = ((size_t)(b * S_LEN + q0 + r0)) * HID + h * HDIM;
    const size_t rowB = ((size_t)(b * S_LEN + q0 + r0 + 8)) * HID + h * HDIM;
#pragma unroll
    for (int nf = 0; nf < 16; nf++) {
        int d = nf * 8 + c0;
        __half h0h, l0h, h1h, l1h;
        split1h(o[nf][0] * inv0, h0h, l0h);
        split1h(o[nf][1] * inv0, h1h, l1h);
        *reinterpret_cast<__half2*>(g_Ohi + rowA + d) = __halves2half2(h0h, h1h);
        *reinterpret_cast<__half2*>(g_Olo + rowA + d) = __halves2half2(l0h, l1h);
        split1h(o[nf][2] * inv1, h0h, l0h);
        split1h(o[nf][3] * inv1, h1h, l1h);
        *reinterpret_cast<__half2*>(g_Ohi + rowB + d) = __halves2half2(h0h, h1h);
        *reinterpret_cast<__half2*>(g_Olo + rowB + d) = __halves2half2(l0h, l1h);
    }
}

// ---------------------------------------------------------------------------
extern "C" void kernel_launch(void* const* d_in, const int* in_sizes, int n_in,
                              void* d_out, int out_size)
{
    (void)in_sizes; (void)n_in; (void)out_size;
    const float* hidden = (const float*)d_in[0];
    const float* Wq     = (const float*)d_in[1];
    const float* Wk     = (const float*)d_in[2];
    const float* Wv     = (const float*)d_in[3];
    const float* Wo     = (const float*)d_in[4];
    float* out          = (float*)d_out;

    __half *xhi, *xlo, *wq, *wk, *wv, *wo, *ohi, *olo;
    __half *qbh, *qbl, *kb;
    cudaGetSymbolAddress((void**)&xhi, g_Xhi);  cudaGetSymbolAddress((void**)&xlo, g_Xlo);
    cudaGetSymbolAddress((void**)&wq, g_WqT);   cudaGetSymbolAddress((void**)&wk, g_WkT);
    cudaGetSymbolAddress((void**)&wv, g_WvT);   cudaGetSymbolAddress((void**)&wo, g_WoT);
    cudaGetSymbolAddress((void**)&ohi, g_Ohi);  cudaGetSymbolAddress((void**)&olo, g_Olo);
    cudaGetSymbolAddress((void**)&qbh, g_Qbh);  cudaGetSymbolAddress((void**)&qbl, g_Qbl);
    cudaGetSymbolAddress((void**)&kb, g_Kb);

    cudaFuncSetAttribute(mma_gemm_kernel,
                         cudaFuncAttributeMaxDynamicSharedMemorySize, GEMM_SMEM);
    cudaFuncSetAttribute(attn_mma_kernel,
                         cudaFuncAttributeMaxDynamicSharedMemorySize, ATTN_SMEM);

    static bool inited = false;
    static cudaStream_t s1, s2;
    static cudaEvent_t evRoot, evWq, evX, evK, evV;
    if (!inited) {
        cudaStreamCreateWithFlags(&s1, cudaStreamNonBlocking);
        cudaStreamCreateWithFlags(&s2, cudaStreamNonBlocking);
        cudaEventCreateWithFlags(&evRoot, cudaEventDisableTiming);
        cudaEventCreateWithFlags(&evWq,   cudaEventDisableTiming);
        cudaEventCreateWithFlags(&evX,    cudaEventDisableTiming);
        cudaEventCreateWithFlags(&evK,    cudaEventDisableTiming);
        cudaEventCreateWithFlags(&evV,    cudaEventDisableTiming);
        inited = true;
    }

    const float qscale = 1.0f / sqrtf((float)HDIM);

    cudaEventRecord(evRoot, 0);
    cudaStreamWaitEvent(s1, evRoot, 0);
    cudaStreamWaitEvent(s2, evRoot, 0);

    // s1: Wq transpose -> evWq ; Wk transpose
    {
        dim3 gq(HID / 32, HID / 32);
        transpose_half_kernel<<<gq, 256, 0, s1>>>(Wq, wq, HID, HID);
        cudaEventRecord(evWq, s1);
        dim3 gkv(KVDIM / 32, HID / 32);
        transpose_half_kernel<<<gkv, 256, 0, s1>>>(Wk, wk, HID, KVDIM);
    }
    // s2: Wv transpose ; Wo transpose
    {
        dim3 gkv(KVDIM / 32, HID / 32);
        transpose_half_kernel<<<gkv, 256, 0, s2>>>(Wv, wv, HID, KVDIM);
        dim3 go(HID / 32, HID / 32);
        transpose_half_kernel<<<go, 256, 0, s2>>>(Wo, wo, HID, HID);
    }
    // s0: split X -> evX
    {
        int n4 = (M_ROWS * HID) / 4;
        split_rowmajor_kernel<<<(n4 + 255) / 256, 256>>>(hidden, xhi, xlo, n4);
        cudaEventRecord(evX, 0);
    }
    // s0: Q projection (EMODE 2: fp16 hi/lo + RoPE + scale)
    {
        cudaStreamWaitEvent(0, evWq, 0);
        dim3 g(HID / 128, M_ROWS / 128);
        mma_gemm_kernel<<<g, 256, GEMM_SMEM>>>(xhi, xlo, wq,
                                               nullptr, qbh, qbl, qscale,
                                               HID, NHEADS, 2);
    }
    // s1: K projection (EMODE 4: single fp16 + RoPE)
    {
        cudaStreamWaitEvent(s1, evX, 0);
        dim3 g(KVDIM / 128, M_ROWS / 128);
        mma_gemm_kernel<<<g, 256, GEMM_SMEM, s1>>>(xhi, xlo, wk,
                                                   nullptr, kb, nullptr, 1.0f,
                                                   KVDIM, NKV, 4);
        cudaEventRecord(evK, s1);
    }
    // s2: V projection (EMODE 3: single fp16 Vt)
    {
        cudaStreamWaitEvent(s2, evX, 0);
        dim3 g(KVDIM / 128, M_ROWS / 128);
        mma_gemm_kernel<<<g, 256, GEMM_SMEM, s2>>>(xhi, xlo, wv,
                                                   nullptr, nullptr, nullptr, 0.f,
                                                   KVDIM, NKV, 3);
        cudaEventRecord(evV, s2);
    }
    // s0: attention
    {
        cudaStreamWaitEvent(0, evK, 0);
        cudaStreamWaitEvent(0, evV, 0);
        dim3 g(S_LEN / 128, NHEADS, BATCH);
        attn_mma_kernel<<<g, 256, ATTN_SMEM>>>();
    }
    // s0: output projection
    {
        dim3 go(HID / 128, M_ROWS / 128);
        mma_gemm_kernel<<<go, 256, GEMM_SMEM>>>(ohi, olo, wo,
                                                out, nullptr, nullptr, 0.f,
                                                HID, NHEADS, 0);
    }
}

// round 14
// speedup vs baseline: 1.4756x; 1.0381x over previous
#include <cuda_runtime.h>
#include <cuda_fp16.h>
#include <math.h>
#include <stdint.h>

#define S_LEN   2048
#define BATCH   2
#define NHEADS  32
#define NKV     8
#define HDIM    128
#define HID     4096
#define KVDIM   1024
#define M_ROWS  4096   // B*S
#define WINDOW  512    // SLIDING_WINDOW // 2
#define GK      4096   // GEMM K
#define NC      (GK/64)

// ======================== scratch buffers ==================================
__device__ __half g_Xhi[(size_t)M_ROWS * HID];
__device__ __half g_Xlo[(size_t)M_ROWS * HID];
__device__ __half g_WqT[(size_t)HID * HID];
__device__ __half g_WkT[(size_t)KVDIM * HID];
__device__ __half g_WvT[(size_t)KVDIM * HID];
__device__ __half g_WoT[(size_t)HID * HID];
__device__ __half g_Ohi[(size_t)M_ROWS * HID];
__device__ __half g_Olo[(size_t)M_ROWS * HID];

// fp16 attention operands (RoPE'd), all single precision
__device__ __half g_Qb[(size_t)BATCH * NHEADS * S_LEN * HDIM];
__device__ __half g_Kb[(size_t)BATCH * NKV * S_LEN * HDIM];
__device__ __half g_Vt[(size_t)BATCH * NKV * HDIM * S_LEN];   // [b,hk,d,s]

// ======================= low-level helpers =================================
__device__ __forceinline__ uint32_t smem_u32(const void* p) {
    uint32_t a;
    asm("{ .reg .u64 t; cvta.to.shared.u64 t, %1; cvt.u32.u64 %0, t; }"
        : "=r"(a) : "l"(p));
    return a;
}
__device__ __forceinline__ void cpasync16(uint32_t saddr, const void* g) {
    asm volatile("cp.async.cg.shared.global [%0], [%1], 16;"
                 :: "r"(saddr), "l"(g) : "memory");
}
#define SWZ(o) ((o) ^ (((o) >> 3) & 0x70))

__device__ __forceinline__ void ldmx4(uint32_t* r, uint32_t addr) {
    asm volatile("ldmatrix.sync.aligned.m8n8.x4.shared.b16 {%0,%1,%2,%3}, [%4];"
                 : "=r"(r[0]), "=r"(r[1]), "=r"(r[2]), "=r"(r[3]) : "r"(addr));
}
// fp16 MMA
__device__ __forceinline__ void mma16816h(float* d, const uint32_t* a, const uint32_t* b) {
    asm volatile("mma.sync.aligned.m16n8k16.row.col.f32.f16.f16.f32 "
                 "{%0,%1,%2,%3}, {%4,%5,%6,%7}, {%8,%9}, {%0,%1,%2,%3};"
                 : "+f"(d[0]), "+f"(d[1]), "+f"(d[2]), "+f"(d[3])
                 : "r"(a[0]), "r"(a[1]), "r"(a[2]), "r"(a[3]),
                   "r"(b[0]), "r"(b[1]));
}

// fast exp on FMA pipe
__device__ __forceinline__ float fast_exp(float x) {
    float y = x * 1.4426950408889634f;
    float r = rintf(y);
    float f = y - r;
    float p = 1.3697664e-3f;
    p = fmaf(p, f, 9.6784195e-3f);
    p = fmaf(p, f, 5.5503454e-2f);
    p = fmaf(p, f, 2.4022652e-1f);
    p = fmaf(p, f, 6.9314718e-1f);
    p = fmaf(p, f, 1.0f);
    int ri = (int)r;
    ri = ri < -126 ? -126 : (ri > 126 ? 126 : ri);
    float s = __int_as_float((uint32_t)(ri + 127) << 23);
    return p * s;
}

__device__ __forceinline__ void split1h(float f, __half& h, __half& l) {
    h = __float2half_rn(f);
    l = __float2half_rn(f - __half2float(h));
}

// ===================== split / transpose preprocessing =====================
__global__ void split_rowmajor_kernel(const float* __restrict__ X,
                                      __half* __restrict__ hi,
                                      __half* __restrict__ lo, int n4)
{
    int i = blockIdx.x * blockDim.x + threadIdx.x;
    if (i >= n4) return;
    float4 v = reinterpret_cast<const float4*>(X)[i];
    __half h0, h1, h2, h3, l0, l1, l2, l3;
    split1h(v.x, h0, l0); split1h(v.y, h1, l1);
    split1h(v.z, h2, l2); split1h(v.w, h3, l3);
    __half2* hp = reinterpret_cast<__half2*>(hi) + 2 * i;
    __half2* lp = reinterpret_cast<__half2*>(lo) + 2 * i;
    hp[0] = __halves2half2(h0, h1); hp[1] = __halves2half2(h2, h3);
    lp[0] = __halves2half2(l0, l1); lp[1] = __halves2half2(l2, l3);
}

// W [K, N] fp32 -> T [N, K] fp16 (single)
__global__ void transpose_half_kernel(const float* __restrict__ W,
                                      __half* __restrict__ T,
                                      int K, int N)
{
    __shared__ float t[32][33];
    int k0 = blockIdx.y * 32, n0 = blockIdx.x * 32;
    int c = threadIdx.x & 31, r = threadIdx.x >> 5;
#pragma unroll
    for (int p = 0; p < 32; p += 8)
        t[r + p][c] = W[(size_t)(k0 + r + p) * N + n0 + c];
    __syncthreads();
#pragma unroll
    for (int p = 0; p < 32; p += 8) {
        size_t o = (size_t)(n0 + r + p) * K + k0 + c;
        T[o] = __float2half_rn(t[c][r + p]);
    }
}

// ======= fp16 GEMM: C = (Ahi [+ Alo]) @ Bh^T  (Alo==nullptr -> 1-pass) =====
// CTA 128x128, 256 threads (8 warps 2x4), warp tile 64x32, K-chunk 64.
// 3-stage cp.async pipeline, single sync per chunk.
// EMODE 0: C row-major fp32 [M,N].
// EMODE 2: RoPE + scale + fp16 hi/lo split, scatter to Chi/Clo [b,nH,s,d].
// EMODE 3: transpose to Vt single fp16 [b,NKV,d,s].  (tile = one head)
// EMODE 4: RoPE + single fp16, scatter to Chi [b,nH,s,d].
#define TILE_BYTES  16384
#define STAGE_BYTES (3 * TILE_BYTES)    // Ahi, Alo, Bh
#define GEMM_SMEM   (3 * STAGE_BYTES)   // 144 KB
#define SPAD        132

__device__ __forceinline__ void load_stage_gemm(
    uint32_t stage_base, int tid, int mBase, int nBase, int kb,
    const __half* __restrict__ Ahi, const __half* __restrict__ Alo,
    const __half* __restrict__ Bh)
{
#pragma unroll
    for (int u = 0; u < 4; ++u) {
        int unit = tid + u * 256;
        int r = unit >> 3, c16 = unit & 7;
        uint32_t sw = SWZ((uint32_t)(r * 128 + c16 * 16));
        size_t ga = (size_t)(mBase + r) * GK + kb + c16 * 8;
        size_t gb = (size_t)(nBase + r) * GK + kb + c16 * 8;
        cpasync16(stage_base + sw,                  Ahi + ga);
        if (Alo) cpasync16(stage_base + TILE_BYTES + sw, Alo + ga);
        cpasync16(stage_base + 2 * TILE_BYTES + sw, Bh + gb);
    }
    asm volatile("cp.async.commit_group;" ::: "memory");
}

__global__ void __launch_bounds__(256, 1) mma_gemm_kernel(
    const __half* __restrict__ Ahi, const __half* __restrict__ Alo,
    const __half* __restrict__ Bh,
    float* __restrict__ C,
    __half* __restrict__ Chi, __half* __restrict__ Clo,
    float ropeScale, int N, int nH, int EMODE)
{
    extern __shared__ __align__(1024) char smem_raw[];
    const uint32_t sbase = smem_u32(smem_raw);
    const int tid  = threadIdx.x;
    const int wid  = tid >> 5, lane = tid & 31;
    const int wm   = wid >> 2;            // 0..1 (64 rows)
    const int wn   = wid & 3;             // 0..3 (32 cols)
    const int mBase = blockIdx.y * 128;
    const int nBase = blockIdx.x * 128;

    float acc[4][4][4];
#pragma unroll
    for (int mt = 0; mt < 4; mt++)
#pragma unroll
        for (int nt = 0; nt < 4; nt++)
#pragma unroll
            for (int e = 0; e < 4; e++) acc[mt][nt][e] = 0.f;

    load_stage_gemm(sbase + 0 * STAGE_BYTES, tid, mBase, nBase, 0,  Ahi, Alo, Bh);
    load_stage_gemm(sbase + 1 * STAGE_BYTES, tid, mBase, nBase, 64, Ahi, Alo, Bh);

    const int aRow = wm * 64 + (lane & 15);
    const int aK8  = (lane >> 4);
    const int bm   = lane >> 3;            // x4 matrix slot 0..3
    const int bRowIn = lane & 7;

    for (int c2 = 0; c2 < NC; ++c2) {
        if (c2 + 1 < NC) asm volatile("cp.async.wait_group 1;" ::: "memory");
        else             asm volatile("cp.async.wait_group 0;" ::: "memory");
        __syncthreads();

        if (c2 + 2 < NC)
            load_stage_gemm(sbase + ((c2 + 2) % 3) * STAGE_BYTES, tid,
                            mBase, nBase, (c2 + 2) * 64, Ahi, Alo, Bh);

        const uint32_t st   = sbase + (c2 % 3) * STAGE_BYTES;
        const uint32_t aHiB = st;
        const uint32_t aLoB = st + TILE_BYTES;
        const uint32_t bHiB = st + 2 * TILE_BYTES;

#pragma unroll
        for (int ks = 0; ks < 4; ks++) {
            uint32_t bh[4][2];
#pragma unroll
            for (int np = 0; np < 2; np++) {
                int nf2 = np * 2 + (bm >> 1);
                int brow = wn * 32 + nf2 * 8 + bRowIn;
                int dl = ks * 16 + (bm & 1) * 8;
                uint32_t sw = SWZ((uint32_t)(brow * 128 + dl * 2));
                uint32_t r4[4];
                ldmx4(r4, bHiB + sw);
                bh[np * 2][0] = r4[0];     bh[np * 2][1] = r4[1];
                bh[np * 2 + 1][0] = r4[2]; bh[np * 2 + 1][1] = r4[3];
            }
            const int ak = ks * 16 + aK8 * 8;
#pragma unroll
            for (int mt = 0; mt < 4; mt++) {
                uint32_t sw = SWZ((uint32_t)((aRow + mt * 16) * 128 + ak * 2));
                uint32_t ah[4];
                ldmx4(ah, aHiB + sw);
#pragma unroll
                for (int nt = 0; nt < 4; nt++)
                    mma16816h(acc[mt][nt], ah, bh[nt]);
                if (Alo) {
                    uint32_t al[4];
                    ldmx4(al, aLoB + sw);
#pragma unroll
                    for (int nt = 0; nt < 4; nt++)
                        mma16816h(acc[mt][nt], al, bh[nt]);
                }
            }
        }
    }

    const int row0 = wm * 64 + (lane >> 2);
    const int col0 = wn * 32 + (lane & 3) * 2;

    if (EMODE == 0) {
#pragma unroll
        for (int mt = 0; mt < 4; mt++)
#pragma unroll
            for (int half = 0; half < 2; half++) {
                int grow = mBase + row0 + mt * 16 + half * 8;
#pragma unroll
                for (int nt = 0; nt < 4; nt++) {
                    int gcol = nBase + col0 + nt * 8;
                    *reinterpret_cast<float2*>(C + (size_t)grow * N + gcol) =
                        make_float2(acc[mt][nt][half * 2], acc[mt][nt][half * 2 + 1]);
                }
            }
        return;
    }

    // stage accumulators to smem [128][SPAD]
    __syncthreads();
    float* stage = reinterpret_cast<float*>(smem_raw);
#pragma unroll
    for (int mt = 0; mt < 4; mt++)
#pragma unroll
        for (int half = 0; half < 2; half++) {
            int r = row0 + mt * 16 + half * 8;
#pragma unroll
            for (int nt = 0; nt < 4; nt++) {
                int c = col0 + nt * 8;
                stage[r * SPAD + c]     = acc[mt][nt][half * 2];
                stage[r * SPAD + c + 1] = acc[mt][nt][half * 2 + 1];
            }
        }
    __syncthreads();

    const int b = mBase >> 11;
    const int sBase = mBase & 2047;
    const int h = nBase >> 7;               // one head per 128-wide tile

    if (EMODE == 2 || EMODE == 4) {
        const size_t headBase = ((size_t)(b * nH + h) * S_LEN) * HDIM;
#pragma unroll
        for (int it = 0; it < 32; it++) {
            int pr = tid + it * 256;           // 0..8191
            int r = pr >> 6, dp = pr & 63;
            float x1 = stage[r * SPAD + dp];
            float x2 = stage[r * SPAD + dp + 64];
            int srow = sBase + r;
            float inv_freq = exp2f(-(float)dp * (13.287712379549449f / 64.0f));
            float ang = (float)srow * inv_freq;
            float c, sn;
            sincosf(ang, &sn, &c);
            float y1 = (x1 * c - x2 * sn) * ropeScale;
            float y2 = (x2 * c + x1 * sn) * ropeScale;
            size_t base = headBase + (size_t)srow * HDIM;
            if (EMODE == 2) {
                __half hh, ll;
                split1h(y1, hh, ll); Chi[base + dp] = hh;      Clo[base + dp] = ll;
                split1h(y2, hh, ll); Chi[base + dp + 64] = hh; Clo[base + dp + 64] = ll;
            } else {
                Chi[base + dp]      = __float2half_rn(y1);
                Chi[base + dp + 64] = __float2half_rn(y2);
            }
        }
        return;
    }

    // EMODE 3: transpose to Vt single fp16 [b,NKV,d,s] (tile = one head)
    {
        int s2 = (tid & 63) * 2;
        int g  = tid >> 6;                  // 0..3
#pragma unroll
        for (int it = 0; it < 32; it++) {
            int d = g * 32 + it;            // 0..127
            float f0 = stage[s2 * SPAD + d];
            float f1 = stage[(s2 + 1) * SPAD + d];
            size_t base = ((size_t)(b * NKV + h) * HDIM + d) * S_LEN + sBase + s2;
            *reinterpret_cast<__half2*>(g_Vt + base) =
                __halves2half2(__float2half_rn(f0), __float2half_rn(f1));
        }
    }
}

// ======== tensor-core flash attention (all single fp16, 1-pass) ============
// Stage = [K 16KB][Vt 16KB] = 32KB, 2 stages. Q (32KB) staged first.
#define AT_STAGE 32768
#define ATTN_SMEM 65536

__global__ void __launch_bounds__(256, 1) attn_mma_kernel()
{
    extern __shared__ __align__(1024) char smem_raw[];
    const uint32_t sb = smem_u32(smem_raw);
    const int tid = threadIdx.x, wid = tid >> 5, lane = tid & 31;
    const int qt = blockIdx.x, h = blockIdx.y, b = blockIdx.z;
    const int hk = h >> 2;
    const int q0 = qt * 128;
    const int bh = b * NHEADS + h, bhk = b * NKV + hk;

    const __half* Qg = g_Qb + ((size_t)bh * S_LEN + q0) * HDIM;
    const __half* Kg = g_Kb + (size_t)bhk * S_LEN * HDIM;
    const __half* Vg = g_Vt + (size_t)bhk * HDIM * S_LEN;

    // ---- stage Q (32KB: 2 subs of 16KB) ----
#pragma unroll
    for (int it = 0; it < 8; it++) {
        int u = tid + it * 256;               // 0..2047
        int r = u >> 4, c16 = u & 15;
        int sub = c16 >> 3;
        uint32_t off = (uint32_t)(sub * 16384 + r * 128 + (c16 & 7) * 16);
        cpasync16(sb + SWZ(off), Qg + (size_t)r * HDIM + c16 * 8);
    }
    asm volatile("cp.async.commit_group;" ::: "memory");
    asm volatile("cp.async.wait_group 0;" ::: "memory");
    __syncthreads();

    uint32_t qh[8][4];
    {
        int row = wid * 16 + (lane & 15);
        int k8 = lane >> 4;
#pragma unroll
        for (int kf = 0; kf < 8; kf++) {
            int sub = kf >> 2;
            uint32_t off = (uint32_t)(sub * 16384 + row * 128 + ((kf & 3) * 16 + k8 * 8) * 2);
            ldmx4(qh[kf], sb + SWZ(off));
        }
    }
    __syncthreads();

    float o[16][4];
#pragma unroll
    for (int nf = 0; nf < 16; nf++)
#pragma unroll
        for (int e = 0; e < 4; e++) o[nf][e] = 0.f;

    float m0 = -1e30f, m1 = -1e30f, l0 = 0.f, l1 = 0.f;
    const int g0row = q0 + wid * 16 + (lane >> 2);

    int kt_lo = 2 * qt - 8; if (kt_lo < 0) kt_lo = 0;
    const int nt = 2 * qt + 1 - kt_lo + 1;

    auto load_kv = [&](int stage, int kt) {
        const int k0 = kt * 64;
        const uint32_t stb = sb + (uint32_t)stage * AT_STAGE;
#pragma unroll
        for (int it = 0; it < 8; it++) {
            int u = tid + it * 256;            // 0..2047
            int buf = u >> 10;                 // 0 = K, 1 = Vt
            int w = u & 1023;
            int r = w >> 3, c16 = w & 7;
            uint32_t off = (uint32_t)(buf * 16384 + r * 128 + c16 * 16);
            const __half* g;
            if (buf == 0) {
                int key = r & 63, sub = r >> 6;
                g = Kg + (size_t)(k0 + key) * HDIM + sub * 64 + c16 * 8;
            } else {
                g = Vg + (size_t)r * S_LEN + k0 + c16 * 8;
            }
            cpasync16(stb + SWZ(off), g);
        }
        asm volatile("cp.async.commit_group;" ::: "memory");
    };

    load_kv(0, kt_lo);
    load_kv(1, kt_lo + 1);

    for (int i = 0; i < nt; i++) {
        const int kt = kt_lo + i;
        const int k0 = kt * 64;
        if (i + 1 < nt) asm volatile("cp.async.wait_group 1;" ::: "memory");
        else            asm volatile("cp.async.wait_group 0;" ::: "memory");
        __syncthreads();
        const uint32_t stb = sb + (uint32_t)(i & 1) * AT_STAGE;

        // ---- S = Q K^T (1-pass) ----
        float s[8][4];
#pragma unroll
        for (int nf = 0; nf < 8; nf++)
#pragma unroll
            for (int e = 0; e < 4; e++) s[nf][e] = 0.f;

#pragma unroll
        for (int kf = 0; kf < 8; kf++) {
            const int sub = kf >> 2;
            const int klocal = (kf & 3) * 16;
            uint32_t kb[8][2];
#pragma unroll
            for (int np = 0; np < 4; np++) {
                int m = lane >> 3;
                int nf2 = np * 2 + (m >> 1);
                int key = nf2 * 8 + (lane & 7);
                int dl = klocal + (m & 1) * 8;
                uint32_t off = (uint32_t)((sub * 64 + key) * 128 + dl * 2);
                uint32_t r4[4];
                ldmx4(r4, stb + SWZ(off));
                kb[np * 2][0] = r4[0]; kb[np * 2][1] = r4[1];
                kb[np * 2 + 1][0] = r4[2]; kb[np * 2 + 1][1] = r4[3];
            }
#pragma unroll
            for (int nf = 0; nf < 8; nf++)
                mma16816h(s[nf], qh[kf], kb[nf]);
        }

        if ((k0 + 63 > q0) || (q0 + 127 - k0 > WINDOW)) {
#pragma unroll
            for (int nf = 0; nf < 8; nf++)
#pragma unroll
                for (int e = 0; e < 4; e++) {
                    int row = g0row + ((e >= 2) ? 8 : 0);
                    int col = k0 + nf * 8 + (lane & 3) * 2 + (e & 1);
                    if (col > row || row - col > WINDOW) s[nf][e] = -1e30f;
                }
        }

        float mx0 = -1e30f, mx1 = -1e30f;
#pragma unroll
        for (int nf = 0; nf < 8; nf++) {
            mx0 = fmaxf(mx0, fmaxf(s[nf][0], s[nf][1]));
            mx1 = fmaxf(mx1, fmaxf(s[nf][2], s[nf][3]));
        }
        mx0 = fmaxf(mx0, __shfl_xor_sync(0xffffffffu, mx0, 1));
        mx0 = fmaxf(mx0, __shfl_xor_sync(0xffffffffu, mx0, 2));
        mx1 = fmaxf(mx1, __shfl_xor_sync(0xffffffffu, mx1, 1));
        mx1 = fmaxf(mx1, __shfl_xor_sync(0xffffffffu, mx1, 2));
        float mn0 = fmaxf(m0, mx0), mn1 = fmaxf(m1, mx1);
        float fac0 = fast_exp(m0 - mn0), fac1 = fast_exp(m1 - mn1);
        m0 = mn0; m1 = mn1;

        uint32_t ph[8][2];
        float ps0 = 0.f, ps1 = 0.f;
#pragma unroll
        for (int nf = 0; nf < 8; nf++) {
            float p0 = fast_exp(s[nf][0] - mn0);
            float p1 = fast_exp(s[nf][1] - mn0);
            float p2 = fast_exp(s[nf][2] - mn1);
            float p3 = fast_exp(s[nf][3] - mn1);
            ps0 += p0 + p1; ps1 += p2 + p3;
            __half2 t;
            t = __halves2half2(__float2half_rn(p0), __float2half_rn(p1));
            ph[nf][0] = *reinterpret_cast<uint32_t*>(&t);
            t = __halves2half2(__float2half_rn(p2), __float2half_rn(p3));
            ph[nf][1] = *reinterpret_cast<uint32_t*>(&t);
        }
        ps0 += __shfl_xor_sync(0xffffffffu, ps0, 1);
        ps0 += __shfl_xor_sync(0xffffffffu, ps0, 2);
        ps1 += __shfl_xor_sync(0xffffffffu, ps1, 1);
        ps1 += __shfl_xor_sync(0xffffffffu, ps1, 2);
        l0 = l0 * fac0 + ps0;
        l1 = l1 * fac1 + ps1;

#pragma unroll
        for (int nf = 0; nf < 16; nf++) {
            o[nf][0] *= fac0; o[nf][1] *= fac0;
            o[nf][2] *= fac1; o[nf][3] *= fac1;
        }

        // ---- O += P @ Vt (1-pass) ----
#pragma unroll
        for (int kf2 = 0; kf2 < 4; kf2++) {
            uint32_t pah[4] = { ph[2 * kf2][0], ph[2 * kf2][1],
                                ph[2 * kf2 + 1][0], ph[2 * kf2 + 1][1] };
#pragma unroll
            for (int np = 0; np < 8; np++) {
                int m = lane >> 3;
                int drow = (np * 2 + (m >> 1)) * 8 + (lane & 7);
                int kl = kf2 * 16 + (m & 1) * 8;
                uint32_t off = (uint32_t)(16384 + drow * 128 + kl * 2);
                uint32_t r4[4];
                ldmx4(r4, stb + SWZ(off));
                uint32_t vb0[2] = { r4[0], r4[1] }, vb1[2] = { r4[2], r4[3] };
                mma16816h(o[np * 2],     pah, vb0);
                mma16816h(o[np * 2 + 1], pah, vb1);
            }
        }
        __syncthreads();
        if (i + 2 < nt) load_kv(i & 1, kt + 2);
    }

    // ---- write O as fp16 hi/lo row-major [m, h*128+d] ----
    const float inv0 = 1.f / l0, inv1 = 1.f / l1;
    const int r0 = wid * 16 + (lane >> 2);
    const int c0 = (lane & 3) * 2;
    const size_t rowA = ((size_t)(b * S_LEN + q0 + r0)) * HID + h * HDIM;
    const size_t rowB = ((size_t)(b * S_LEN + q0 + r0 + 8)) * HID + h * HDIM;
#pragma unroll
    for (int nf = 0; nf < 16; nf++) {
        int d = nf * 8 + c0;
        __half h0h, l0h, h1h, l1h;
        split1h(o[nf][0] * inv0, h0h, l0h);
        split1h(o[nf][1] * inv0, h1h, l1h);
        *reinterpret_cast<__half2*>(g_Ohi + rowA + d) = __halves2half2(h0h, h1h);
        *reinterpret_cast<__half2*>(g_Olo + rowA + d) = __halves2half2(l0h, l1h);
        split1h(o[nf][2] * inv1, h0h, l0h);
        split1h(o[nf][3] * inv1, h1h, l1h);
        *reinterpret_cast<__half2*>(g_Ohi + rowB + d) = __halves2half2(h0h, h1h);
        *reinterpret_cast<__half2*>(g_Olo + rowB + d) = __halves2half2(l0h, l1h);
    }
}

// ---------------------------------------------------------------------------
extern "C" void kernel_launch(void* const* d_in, const int* in_sizes, int n_in,
                              void* d_out, int out_size)
{
    (void)in_sizes; (void)n_in; (void)out_size;
    const float* hidden = (const float*)d_in[0];
    const float* Wq     = (const float*)d_in[1];
    const float* Wk     = (const float*)d_in[2];
    const float* Wv     = (const float*)d_in[3];
    const float* Wo     = (const float*)d_in[4];
    float* out          = (float*)d_out;

    __half *xhi, *xlo, *wq, *wk, *wv, *wo, *ohi, *olo, *qb, *kb;
    cudaGetSymbolAddress((void**)&xhi, g_Xhi);  cudaGetSymbolAddress((void**)&xlo, g_Xlo);
    cudaGetSymbolAddress((void**)&wq, g_WqT);   cudaGetSymbolAddress((void**)&wk, g_WkT);
    cudaGetSymbolAddress((void**)&wv, g_WvT);   cudaGetSymbolAddress((void**)&wo, g_WoT);
    cudaGetSymbolAddress((void**)&ohi, g_Ohi);  cudaGetSymbolAddress((void**)&olo, g_Olo);
    cudaGetSymbolAddress((void**)&qb, g_Qb);    cudaGetSymbolAddress((void**)&kb, g_Kb);

    cudaFuncSetAttribute(mma_gemm_kernel,
                         cudaFuncAttributeMaxDynamicSharedMemorySize, GEMM_SMEM);
    cudaFuncSetAttribute(attn_mma_kernel,
                         cudaFuncAttributeMaxDynamicSharedMemorySize, ATTN_SMEM);

    static bool inited = false;
    static cudaStream_t s1, s2;
    static cudaEvent_t evRoot, evWq, evX, evK, evV;
    if (!inited) {
        cudaStreamCreateWithFlags(&s1, cudaStreamNonBlocking);
        cudaStreamCreateWithFlags(&s2, cudaStreamNonBlocking);
        cudaEventCreateWithFlags(&evRoot, cudaEventDisableTiming);
        cudaEventCreateWithFlags(&evWq,   cudaEventDisableTiming);
        cudaEventCreateWithFlags(&evX,    cudaEventDisableTiming);
        cudaEventCreateWithFlags(&evK,    cudaEventDisableTiming);
        cudaEventCreateWithFlags(&evV,    cudaEventDisableTiming);
        inited = true;
    }

    const float qscale = 1.0f / sqrtf((float)HDIM);

    cudaEventRecord(evRoot, 0);
    cudaStreamWaitEvent(s1, evRoot, 0);
    cudaStreamWaitEvent(s2, evRoot, 0);

    // s1: Wq transpose -> evWq ; Wk transpose
    {
        dim3 gq(HID / 32, HID / 32);
        transpose_half_kernel<<<gq, 256, 0, s1>>>(Wq, wq, HID, HID);
        cudaEventRecord(evWq, s1);
        dim3 gkv(KVDIM / 32, HID / 32);
        transpose_half_kernel<<<gkv, 256, 0, s1>>>(Wk, wk, HID, KVDIM);
    }
    // s2: Wv transpose ; Wo transpose
    {
        dim3 gkv(KVDIM / 32, HID / 32);
        transpose_half_kernel<<<gkv, 256, 0, s2>>>(Wv, wv, HID, KVDIM);
        dim3 go(HID / 32, HID / 32);
        transpose_half_kernel<<<go, 256, 0, s2>>>(Wo, wo, HID, HID);
    }
    // s0: split X -> evX
    {
        int n4 = (M_ROWS * HID) / 4;
        split_rowmajor_kernel<<<(n4 + 255) / 256, 256>>>(hidden, xhi, xlo, n4);
        cudaEventRecord(evX, 0);
    }
    // s0: Q projection (2-pass, EMODE 4: RoPE + scale + single fp16)
    {
        cudaStreamWaitEvent(0, evWq, 0);
        dim3 g(HID / 128, M_ROWS / 128);
        mma_gemm_kernel<<<g, 256, GEMM_SMEM>>>(xhi, xlo, wq,
                                               nullptr, qb, nullptr, qscale,
                                               HID, NHEADS, 4);
    }
    // s1: K projection (2-pass, EMODE 4: RoPE + single fp16)
    {
        cudaStreamWaitEvent(s1, evX, 0);
        dim3 g(KVDIM / 128, M_ROWS / 128);
        mma_gemm_kernel<<<g, 256, GEMM_SMEM, s1>>>(xhi, xlo, wk,
                                                   nullptr, kb, nullptr, 1.0f,
                                                   KVDIM, NKV, 4);
        cudaEventRecord(evK, s1);
    }
    // s2: V projection (1-pass: Alo=nullptr, EMODE 3: single fp16 Vt)
    {
        cudaStreamWaitEvent(s2, evX, 0);
        dim3 g(KVDIM / 128, M_ROWS / 128);
        mma_gemm_kernel<<<g, 256, GEMM_SMEM, s2>>>(xhi, nullptr, wv,
                                                   nullptr, nullptr, nullptr, 0.f,
                                                   KVDIM, NKV, 3);
        cudaEventRecord(evV, s2);
    }
    // s0: attention (all single fp16, 1-pass QK and PV)
    {
        cudaStreamWaitEvent(0, evK, 0);
        cudaStreamWaitEvent(0, evV, 0);
        dim3 g(S_LEN / 128, NHEADS, BATCH);
        attn_mma_kernel<<<g, 256, ATTN_SMEM>>>();
    }
    // s0: output projection (2-pass, O hi/lo)
    {
        dim3 go(HID / 128, M_ROWS / 128);
        mma_gemm_kernel<<<go, 256, GEMM_SMEM>>>(ohi, olo, wo,
                                                out, nullptr, nullptr, 0.f,
                                                HID, NHEADS, 0);
    }
}

// round 15
// speedup vs baseline: 2.1496x; 1.4568x over previous
#include <cuda_runtime.h>
#include <cuda_fp16.h>
#include <math.h>
#include <stdint.h>

#define S_LEN   2048
#define BATCH   2
#define NHEADS  32
#define NKV     8
#define HDIM    128
#define HID     4096
#define KVDIM   1024
#define M_ROWS  4096   // B*S
#define WINDOW  512    // SLIDING_WINDOW // 2
#define GK      4096   // GEMM K
#define NC      (GK/64)

// ======================== scratch buffers ==================================
__device__ __half g_X[(size_t)M_ROWS * HID];
__device__ __half g_WqT[(size_t)HID * HID];
__device__ __half g_WkT[(size_t)KVDIM * HID];
__device__ __half g_WvT[(size_t)KVDIM * HID];
__device__ __half g_WoT[(size_t)HID * HID];
__device__ __half g_O[(size_t)M_ROWS * HID];

// fp16 attention operands (RoPE'd), all single precision
__device__ __half g_Qb[(size_t)BATCH * NHEADS * S_LEN * HDIM];
__device__ __half g_Kb[(size_t)BATCH * NKV * S_LEN * HDIM];
__device__ __half g_Vt[(size_t)BATCH * NKV * HDIM * S_LEN];   // [b,hk,d,s]

// ======================= low-level helpers =================================
__device__ __forceinline__ uint32_t smem_u32(const void* p) {
    uint32_t a;
    asm("{ .reg .u64 t; cvta.to.shared.u64 t, %1; cvt.u32.u64 %0, t; }"
        : "=r"(a) : "l"(p));
    return a;
}
__device__ __forceinline__ void cpasync16(uint32_t saddr, const void* g) {
    asm volatile("cp.async.cg.shared.global [%0], [%1], 16;"
                 :: "r"(saddr), "l"(g) : "memory");
}
#define SWZ(o) ((o) ^ (((o) >> 3) & 0x70))

__device__ __forceinline__ void ldmx4(uint32_t* r, uint32_t addr) {
    asm volatile("ldmatrix.sync.aligned.m8n8.x4.shared.b16 {%0,%1,%2,%3}, [%4];"
                 : "=r"(r[0]), "=r"(r[1]), "=r"(r[2]), "=r"(r[3]) : "r"(addr));
}
__device__ __forceinline__ void mma16816h(float* d, const uint32_t* a, const uint32_t* b) {
    asm volatile("mma.sync.aligned.m16n8k16.row.col.f32.f16.f16.f32 "
                 "{%0,%1,%2,%3}, {%4,%5,%6,%7}, {%8,%9}, {%0,%1,%2,%3};"
                 : "+f"(d[0]), "+f"(d[1]), "+f"(d[2]), "+f"(d[3])
                 : "r"(a[0]), "r"(a[1]), "r"(a[2]), "r"(a[3]),
                   "r"(b[0]), "r"(b[1]));
}

// fast exp on FMA pipe
__device__ __forceinline__ float fast_exp(float x) {
    float y = x * 1.4426950408889634f;
    float r = rintf(y);
    float f = y - r;
    float p = 1.3697664e-3f;
    p = fmaf(p, f, 9.6784195e-3f);
    p = fmaf(p, f, 5.5503454e-2f);
    p = fmaf(p, f, 2.4022652e-1f);
    p = fmaf(p, f, 6.9314718e-1f);
    p = fmaf(p, f, 1.0f);
    int ri = (int)r;
    ri = ri < -126 ? -126 : (ri > 126 ? 126 : ri);
    float s = __int_as_float((uint32_t)(ri + 127) << 23);
    return p * s;
}

// ===================== convert / transpose preprocessing ====================
__global__ void convert_half_kernel(const float* __restrict__ X,
                                    __half* __restrict__ Y, int n4)
{
    int i = blockIdx.x * blockDim.x + threadIdx.x;
    if (i >= n4) return;
    float4 v = reinterpret_cast<const float4*>(X)[i];
    __half2* yp = reinterpret_cast<__half2*>(Y) + 2 * i;
    yp[0] = __halves2half2(__float2half_rn(v.x), __float2half_rn(v.y));
    yp[1] = __halves2half2(__float2half_rn(v.z), __float2half_rn(v.w));
}

// W [K, N] fp32 -> T [N, K] fp16
__global__ void transpose_half_kernel(const float* __restrict__ W,
                                      __half* __restrict__ T,
                                      int K, int N)
{
    __shared__ float t[32][33];
    int k0 = blockIdx.y * 32, n0 = blockIdx.x * 32;
    int c = threadIdx.x & 31, r = threadIdx.x >> 5;
#pragma unroll
    for (int p = 0; p < 32; p += 8)
        t[r + p][c] = W[(size_t)(k0 + r + p) * N + n0 + c];
    __syncthreads();
#pragma unroll
    for (int p = 0; p < 32; p += 8) {
        size_t o = (size_t)(n0 + r + p) * K + k0 + c;
        T[o] = __float2half_rn(t[c][r + p]);
    }
}

// ================= fp16 1-pass GEMM: C = A @ B^T ===========================
// CTA 128x128, 256 threads (8 warps 2x4), warp tile 64x32, K-chunk 64.
// 3-stage cp.async pipeline (32KB/stage), single sync per chunk.
// EMODE 0: C row-major fp32 [M,N].
// EMODE 3: transpose to Vt fp16 [b,NKV,d,s].  (tile = one head)
// EMODE 4: RoPE + scale + fp16, scatter to Ch [b,nH,s,d].
#define TILE_BYTES  16384
#define STAGE_BYTES (2 * TILE_BYTES)    // A, B
#define GEMM_SMEM   (3 * STAGE_BYTES)   // 96 KB
#define SPAD        132

__device__ __forceinline__ void load_stage_gemm(
    uint32_t stage_base, int tid, int mBase, int nBase, int kb,
    const __half* __restrict__ A, const __half* __restrict__ B)
{
#pragma unroll
    for (int u = 0; u < 4; ++u) {
        int unit = tid + u * 256;
        int r = unit >> 3, c16 = unit & 7;
        uint32_t sw = SWZ((uint32_t)(r * 128 + c16 * 16));
        size_t ga = (size_t)(mBase + r) * GK + kb + c16 * 8;
        size_t gb = (size_t)(nBase + r) * GK + kb + c16 * 8;
        cpasync16(stage_base + sw,              A + ga);
        cpasync16(stage_base + TILE_BYTES + sw, B + gb);
    }
    asm volatile("cp.async.commit_group;" ::: "memory");
}

__global__ void __launch_bounds__(256, 1) mma_gemm_kernel(
    const __half* __restrict__ A, const __half* __restrict__ B,
    float* __restrict__ C, __half* __restrict__ Ch,
    float ropeScale, int N, int nH, int EMODE)
{
    extern __shared__ __align__(1024) char smem_raw[];
    const uint32_t sbase = smem_u32(smem_raw);
    const int tid  = threadIdx.x;
    const int wid  = tid >> 5, lane = tid & 31;
    const int wm   = wid >> 2;            // 0..1 (64 rows)
    const int wn   = wid & 3;             // 0..3 (32 cols)
    const int mBase = blockIdx.y * 128;
    const int nBase = blockIdx.x * 128;

    float acc[4][4][4];
#pragma unroll
    for (int mt = 0; mt < 4; mt++)
#pragma unroll
        for (int nt = 0; nt < 4; nt++)
#pragma unroll
            for (int e = 0; e < 4; e++) acc[mt][nt][e] = 0.f;

    load_stage_gemm(sbase + 0 * STAGE_BYTES, tid, mBase, nBase, 0,  A, B);
    load_stage_gemm(sbase + 1 * STAGE_BYTES, tid, mBase, nBase, 64, A, B);

    const int aRow = wm * 64 + (lane & 15);
    const int aK8  = (lane >> 4);
    const int bm   = lane >> 3;            // x4 matrix slot 0..3
    const int bRowIn = lane & 7;

    for (int c2 = 0; c2 < NC; ++c2) {
        if (c2 + 1 < NC) asm volatile("cp.async.wait_group 1;" ::: "memory");
        else             asm volatile("cp.async.wait_group 0;" ::: "memory");
        __syncthreads();

        if (c2 + 2 < NC)
            load_stage_gemm(sbase + ((c2 + 2) % 3) * STAGE_BYTES, tid,
                            mBase, nBase, (c2 + 2) * 64, A, B);

        const uint32_t st  = sbase + (c2 % 3) * STAGE_BYTES;
        const uint32_t aB  = st;
        const uint32_t bB  = st + TILE_BYTES;

#pragma unroll
        for (int ks = 0; ks < 4; ks++) {
            uint32_t bh[4][2];
#pragma unroll
            for (int np = 0; np < 2; np++) {
                int nf2 = np * 2 + (bm >> 1);
                int brow = wn * 32 + nf2 * 8 + bRowIn;
                int dl = ks * 16 + (bm & 1) * 8;
                uint32_t sw = SWZ((uint32_t)(brow * 128 + dl * 2));
                uint32_t r4[4];
                ldmx4(r4, bB + sw);
                bh[np * 2][0] = r4[0];     bh[np * 2][1] = r4[1];
                bh[np * 2 + 1][0] = r4[2]; bh[np * 2 + 1][1] = r4[3];
            }
            const int ak = ks * 16 + aK8 * 8;
#pragma unroll
            for (int mt = 0; mt < 4; mt++) {
                uint32_t sw = SWZ((uint32_t)((aRow + mt * 16) * 128 + ak * 2));
                uint32_t ah[4];
                ldmx4(ah, aB + sw);
#pragma unroll
                for (int nt = 0; nt < 4; nt++)
                    mma16816h(acc[mt][nt], ah, bh[nt]);
            }
        }
    }

    const int row0 = wm * 64 + (lane >> 2);
    const int col0 = wn * 32 + (lane & 3) * 2;

    if (EMODE == 0) {
#pragma unroll
        for (int mt = 0; mt < 4; mt++)
#pragma unroll
            for (int half = 0; half < 2; half++) {
                int grow = mBase + row0 + mt * 16 + half * 8;
#pragma unroll
                for (int nt = 0; nt < 4; nt++) {
                    int gcol = nBase + col0 + nt * 8;
                    *reinterpret_cast<float2*>(C + (size_t)grow * N + gcol) =
                        make_float2(acc[mt][nt][half * 2], acc[mt][nt][half * 2 + 1]);
                }
            }
        return;
    }

    // stage accumulators to smem [128][SPAD]
    __syncthreads();
    float* stage = reinterpret_cast<float*>(smem_raw);
#pragma unroll
    for (int mt = 0; mt < 4; mt++)
#pragma unroll
        for (int half = 0; half < 2; half++) {
            int r = row0 + mt * 16 + half * 8;
#pragma unroll
            for (int nt = 0; nt < 4; nt++) {
                int c = col0 + nt * 8;
                stage[r * SPAD + c]     = acc[mt][nt][half * 2];
                stage[r * SPAD + c + 1] = acc[mt][nt][half * 2 + 1];
            }
        }
    __syncthreads();

    const int b = mBase >> 11;
    const int sBase = mBase & 2047;
    const int h = nBase >> 7;               // one head per 128-wide tile

    if (EMODE == 4) {
        const size_t headBase = ((size_t)(b * nH + h) * S_LEN) * HDIM;
#pragma unroll
        for (int it = 0; it < 32; it++) {
            int pr = tid + it * 256;           // 0..8191
            int r = pr >> 6, dp = pr & 63;
            float x1 = stage[r * SPAD + dp];
            float x2 = stage[r * SPAD + dp + 64];
            int srow = sBase + r;
            float inv_freq = exp2f(-(float)dp * (13.287712379549449f / 64.0f));
            float ang = (float)srow * inv_freq;
            float c, sn;
            sincosf(ang, &sn, &c);
            float y1 = (x1 * c - x2 * sn) * ropeScale;
            float y2 = (x2 * c + x1 * sn) * ropeScale;
            size_t base = headBase + (size_t)srow * HDIM;
            Ch[base + dp]      = __float2half_rn(y1);
            Ch[base + dp + 64] = __float2half_rn(y2);
        }
        return;
    }

    // EMODE 3: transpose to Vt fp16 [b,NKV,d,s] (tile = one head)
    {
        int s2 = (tid & 63) * 2;
        int g  = tid >> 6;                  // 0..3
#pragma unroll
        for (int it = 0; it < 32; it++) {
            int d = g * 32 + it;            // 0..127
            float f0 = stage[s2 * SPAD + d];
            float f1 = stage[(s2 + 1) * SPAD + d];
            size_t base = ((size_t)(b * NKV + h) * HDIM + d) * S_LEN + sBase + s2;
            *reinterpret_cast<__half2*>(g_Vt + base) =
                __halves2half2(__float2half_rn(f0), __float2half_rn(f1));
        }
    }
}

// ======== tensor-core flash attention (all single fp16, 1-pass) ============
#define AT_STAGE 32768
#define ATTN_SMEM 65536

__global__ void __launch_bounds__(256, 1) attn_mma_kernel()
{
    extern __shared__ __align__(1024) char smem_raw[];
    const uint32_t sb = smem_u32(smem_raw);
    const int tid = threadIdx.x, wid = tid >> 5, lane = tid & 31;
    const int qt = blockIdx.x, h = blockIdx.y, b = blockIdx.z;
    const int hk = h >> 2;
    const int q0 = qt * 128;
    const int bh = b * NHEADS + h, bhk = b * NKV + hk;

    const __half* Qg = g_Qb + ((size_t)bh * S_LEN + q0) * HDIM;
    const __half* Kg = g_Kb + (size_t)bhk * S_LEN * HDIM;
    const __half* Vg = g_Vt + (size_t)bhk * HDIM * S_LEN;

    // ---- stage Q (32KB: 2 subs of 16KB) ----
#pragma unroll
    for (int it = 0; it < 8; it++) {
        int u = tid + it * 256;
        int r = u >> 4, c16 = u & 15;
        int sub = c16 >> 3;
        uint32_t off = (uint32_t)(sub * 16384 + r * 128 + (c16 & 7) * 16);
        cpasync16(sb + SWZ(off), Qg + (size_t)r * HDIM + c16 * 8);
    }
    asm volatile("cp.async.commit_group;" ::: "memory");
    asm volatile("cp.async.wait_group 0;" ::: "memory");
    __syncthreads();

    uint32_t qh[8][4];
    {
        int row = wid * 16 + (lane & 15);
        int k8 = lane >> 4;
#pragma unroll
        for (int kf = 0; kf < 8; kf++) {
            int sub = kf >> 2;
            uint32_t off = (uint32_t)(sub * 16384 + row * 128 + ((kf & 3) * 16 + k8 * 8) * 2);
            ldmx4(qh[kf], sb + SWZ(off));
        }
    }
    __syncthreads();

    float o[16][4];
#pragma unroll
    for (int nf = 0; nf < 16; nf++)
#pragma unroll
        for (int e = 0; e < 4; e++) o[nf][e] = 0.f;

    float m0 = -1e30f, m1 = -1e30f, l0 = 0.f, l1 = 0.f;
    const int g0row = q0 + wid * 16 + (lane >> 2);

    int kt_lo = 2 * qt - 8; if (kt_lo < 0) kt_lo = 0;
    const int nt = 2 * qt + 1 - kt_lo + 1;

    auto load_kv = [&](int stage, int kt) {
        const int k0 = kt * 64;
        const uint32_t stb = sb + (uint32_t)stage * AT_STAGE;
#pragma unroll
        for (int it = 0; it < 8; it++) {
            int u = tid + it * 256;
            int buf = u >> 10;                 // 0 = K, 1 = Vt
            int w = u & 1023;
            int r = w >> 3, c16 = w & 7;
            uint32_t off = (uint32_t)(buf * 16384 + r * 128 + c16 * 16);
            const __half* g;
            if (buf == 0) {
                int key = r & 63, sub = r >> 6;
                g = Kg + (size_t)(k0 + key) * HDIM + sub * 64 + c16 * 8;
            } else {
                g = Vg + (size_t)r * S_LEN + k0 + c16 * 8;
            }
            cpasync16(stb + SWZ(off), g);
        }
        asm volatile("cp.async.commit_group;" ::: "memory");
    };

    load_kv(0, kt_lo);
    load_kv(1, kt_lo + 1);

    for (int i = 0; i < nt; i++) {
        const int kt = kt_lo + i;
        const int k0 = kt * 64;
        if (i + 1 < nt) asm volatile("cp.async.wait_group 1;" ::: "memory");
        else            asm volatile("cp.async.wait_group 0;" ::: "memory");
        __syncthreads();
        const uint32_t stb = sb + (uint32_t)(i & 1) * AT_STAGE;

        // ---- S = Q K^T (1-pass) ----
        float s[8][4];
#pragma unroll
        for (int nf = 0; nf < 8; nf++)
#pragma unroll
            for (int e = 0; e < 4; e++) s[nf][e] = 0.f;

#pragma unroll
        for (int kf = 0; kf < 8; kf++) {
            const int sub = kf >> 2;
            const int klocal = (kf & 3) * 16;
            uint32_t kb[8][2];
#pragma unroll
            for (int np = 0; np < 4; np++) {
                int m = lane >> 3;
                int nf2 = np * 2 + (m >> 1);
                int key = nf2 * 8 + (lane & 7);
                int dl = klocal + (m & 1) * 8;
                uint32_t off = (uint32_t)((sub * 64 + key) * 128 + dl * 2);
                uint32_t r4[4];
                ldmx4(r4, stb + SWZ(off));
                kb[np * 2][0] = r4[0]; kb[np * 2][1] = r4[1];
                kb[np * 2 + 1][0] = r4[2]; kb[np * 2 + 1][1] = r4[3];
            }
#pragma unroll
            for (int nf = 0; nf < 8; nf++)
                mma16816h(s[nf], qh[kf], kb[nf]);
        }

        if ((k0 + 63 > q0) || (q0 + 127 - k0 > WINDOW)) {
#pragma unroll
            for (int nf = 0; nf < 8; nf++)
#pragma unroll
                for (int e = 0; e < 4; e++) {
                    int row = g0row + ((e >= 2) ? 8 : 0);
                    int col = k0 + nf * 8 + (lane & 3) * 2 + (e & 1);
                    if (col > row || row - col > WINDOW) s[nf][e] = -1e30f;
                }
        }

        float mx0 = -1e30f, mx1 = -1e30f;
#pragma unroll
        for (int nf = 0; nf < 8; nf++) {
            mx0 = fmaxf(mx0, fmaxf(s[nf][0], s[nf][1]));
            mx1 = fmaxf(mx1, fmaxf(s[nf][2], s[nf][3]));
        }
        mx0 = fmaxf(mx0, __shfl_xor_sync(0xffffffffu, mx0, 1));
        mx0 = fmaxf(mx0, __shfl_xor_sync(0xffffffffu, mx0, 2));
        mx1 = fmaxf(mx1, __shfl_xor_sync(0xffffffffu, mx1, 1));
        mx1 = fmaxf(mx1, __shfl_xor_sync(0xffffffffu, mx1, 2));
        float mn0 = fmaxf(m0, mx0), mn1 = fmaxf(m1, mx1);
        float fac0 = fast_exp(m0 - mn0), fac1 = fast_exp(m1 - mn1);
        m0 = mn0; m1 = mn1;

        uint32_t ph[8][2];
        float ps0 = 0.f, ps1 = 0.f;
#pragma unroll
        for (int nf = 0; nf < 8; nf++) {
            float p0 = fast_exp(s[nf][0] - mn0);
            float p1 = fast_exp(s[nf][1] - mn0);
            float p2 = fast_exp(s[nf][2] - mn1);
            float p3 = fast_exp(s[nf][3] - mn1);
            ps0 += p0 + p1; ps1 += p2 + p3;
            __half2 t;
            t = __halves2half2(__float2half_rn(p0), __float2half_rn(p1));
            ph[nf][0] = *reinterpret_cast<uint32_t*>(&t);
            t = __halves2half2(__float2half_rn(p2), __float2half_rn(p3));
            ph[nf][1] = *reinterpret_cast<uint32_t*>(&t);
        }
        ps0 += __shfl_xor_sync(0xffffffffu, ps0, 1);
        ps0 += __shfl_xor_sync(0xffffffffu, ps0, 2);
        ps1 += __shfl_xor_sync(0xffffffffu, ps1, 1);
        ps1 += __shfl_xor_sync(0xffffffffu, ps1, 2);
        l0 = l0 * fac0 + ps0;
        l1 = l1 * fac1 + ps1;

#pragma unroll
        for (int nf = 0; nf < 16; nf++) {
            o[nf][0] *= fac0; o[nf][1] *= fac0;
            o[nf][2] *= fac1; o[nf][3] *= fac1;
        }

        // ---- O += P @ Vt (1-pass) ----
#pragma unroll
        for (int kf2 = 0; kf2 < 4; kf2++) {
            uint32_t pah[4] = { ph[2 * kf2][0], ph[2 * kf2][1],
                                ph[2 * kf2 + 1][0], ph[2 * kf2 + 1][1] };
#pragma unroll
            for (int np = 0; np < 8; np++) {
                int m = lane >> 3;
                int drow = (np * 2 + (m >> 1)) * 8 + (lane & 7);
                int kl = kf2 * 16 + (m & 1) * 8;
                uint32_t off = (uint32_t)(16384 + drow * 128 + kl * 2);
                uint32_t r4[4];
                ldmx4(r4, stb + SWZ(off));
                uint32_t vb0[2] = { r4[0], r4[1] }, vb1[2] = { r4[2], r4[3] };
                mma16816h(o[np * 2],     pah, vb0);
                mma16816h(o[np * 2 + 1], pah, vb1);
            }
        }
        __syncthreads();
        if (i + 2 < nt) load_kv(i & 1, kt + 2);
    }

    // ---- write O as single fp16 row-major [m, h*128+d] ----
    const float inv0 = 1.f / l0, inv1 = 1.f / l1;
    const int r0 = wid * 16 + (lane >> 2);
    const int c0 = (lane & 3) * 2;
    const size_t rowA = ((size_t)(b * S_LEN + q0 + r0)) * HID + h * HDIM;
    const size_t rowB = ((size_t)(b * S_LEN + q0 + r0 + 8)) * HID + h * HDIM;
#pragma unroll
    for (int nf = 0; nf < 16; nf++) {
        int d = nf * 8 + c0;
        *reinterpret_cast<__half2*>(g_O + rowA + d) =
            __halves2half2(__float2half_rn(o[nf][0] * inv0),
                           __float2half_rn(o[nf][1] * inv0));
        *reinterpret_cast<__half2*>(g_O + rowB + d) =
            __halves2half2(__float2half_rn(o[nf][2] * inv1),
                           __float2half_rn(o[nf][3] * inv1));
    }
}

// ---------------------------------------------------------------------------
extern "C" void kernel_launch(void* const* d_in, const int* in_sizes, int n_in,
                              void* d_out, int out_size)
{
    (void)in_sizes; (void)n_in; (void)out_size;
    const float* hidden = (const float*)d_in[0];
    const float* Wq     = (const float*)d_in[1];
    const float* Wk     = (const float*)d_in[2];
    const float* Wv     = (const float*)d_in[3];
    const float* Wo     = (const float*)d_in[4];
    float* out          = (float*)d_out;

    __half *x, *wq, *wk, *wv, *wo, *ob, *qb, *kb;
    cudaGetSymbolAddress((void**)&x, g_X);
    cudaGetSymbolAddress((void**)&wq, g_WqT);   cudaGetSymbolAddress((void**)&wk, g_WkT);
    cudaGetSymbolAddress((void**)&wv, g_WvT);   cudaGetSymbolAddress((void**)&wo, g_WoT);
    cudaGetSymbolAddress((void**)&ob, g_O);
    cudaGetSymbolAddress((void**)&qb, g_Qb);    cudaGetSymbolAddress((void**)&kb, g_Kb);

    cudaFuncSetAttribute(mma_gemm_kernel,
                         cudaFuncAttributeMaxDynamicSharedMemorySize, GEMM_SMEM);
    cudaFuncSetAttribute(attn_mma_kernel,
                         cudaFuncAttributeMaxDynamicSharedMemorySize, ATTN_SMEM);

    static bool inited = false;
    static cudaStream_t s1, s2;
    static cudaEvent_t evRoot, evWq, evX, evK, evV;
    if (!inited) {
        cudaStreamCreateWithFlags(&s1, cudaStreamNonBlocking);
        cudaStreamCreateWithFlags(&s2, cudaStreamNonBlocking);
        cudaEventCreateWithFlags(&evRoot, cudaEventDisableTiming);
        cudaEventCreateWithFlags(&evWq,   cudaEventDisableTiming);
        cudaEventCreateWithFlags(&evX,    cudaEventDisableTiming);
        cudaEventCreateWithFlags(&evK,    cudaEventDisableTiming);
        cudaEventCreateWithFlags(&evV,    cudaEventDisableTiming);
        inited = true;
    }

    const float qscale = 1.0f / sqrtf((float)HDIM);

    cudaEventRecord(evRoot, 0);
    cudaStreamWaitEvent(s1, evRoot, 0);
    cudaStreamWaitEvent(s2, evRoot, 0);

    // s1: Wq transpose -> evWq ; Wk transpose
    {
        dim3 gq(HID / 32, HID / 32);
        transpose_half_kernel<<<gq, 256, 0, s1>>>(Wq, wq, HID, HID);
        cudaEventRecord(evWq, s1);
        dim3 gkv(KVDIM / 32, HID / 32);
        transpose_half_kernel<<<gkv, 256, 0, s1>>>(Wk, wk, HID, KVDIM);
    }
    // s2: Wv transpose ; Wo transpose
    {
        dim3 gkv(KVDIM / 32, HID / 32);
        transpose_half_kernel<<<gkv, 256, 0, s2>>>(Wv, wv, HID, KVDIM);
        dim3 go(HID / 32, HID / 32);
        transpose_half_kernel<<<go, 256, 0, s2>>>(Wo, wo, HID, HID);
    }
    // s0: convert X -> evX
    {
        int n4 = (M_ROWS * HID) / 4;
        convert_half_kernel<<<(n4 + 255) / 256, 256>>>(hidden, x, n4);
        cudaEventRecord(evX, 0);
    }
    // s0: Q projection (EMODE 4: RoPE + scale + fp16)
    {
        cudaStreamWaitEvent(0, evWq, 0);
        dim3 g(HID / 128, M_ROWS / 128);
        mma_gemm_kernel<<<g, 256, GEMM_SMEM>>>(x, wq, nullptr, qb,
                                               qscale, HID, NHEADS, 4);
    }
    // s1: K projection (EMODE 4: RoPE + fp16)
    {
        cudaStreamWaitEvent(s1, evX, 0);
        dim3 g(KVDIM / 128, M_ROWS / 128);
        mma_gemm_kernel<<<g, 256, GEMM_SMEM, s1>>>(x, wk, nullptr, kb,
                                                   1.0f, KVDIM, NKV, 4);
        cudaEventRecord(evK, s1);
    }
    // s2: V projection (EMODE 3: fp16 Vt)
    {
        cudaStreamWaitEvent(s2, evX, 0);
        dim3 g(KVDIM / 128, M_ROWS / 128);
        mma_gemm_kernel<<<g, 256, GEMM_SMEM, s2>>>(x, wv, nullptr, nullptr,
                                                   0.f, KVDIM, NKV, 3);
        cudaEventRecord(evV, s2);
    }
    // s0: attention
    {
        cudaStreamWaitEvent(0, evK, 0);
        cudaStreamWaitEvent(0, evV, 0);
        dim3 g(S_LEN / 128, NHEADS, BATCH);
        attn_mma_kernel<<<g, 256, ATTN_SMEM>>>();
    }
    // s0: output projection (EMODE 0: fp32 out)
    {
        dim3 go(HID / 128, M_ROWS / 128);
        mma_gemm_kernel<<<go, 256, GEMM_SMEM>>>(ob, wo, out, nullptr,
                                                0.f, HID, NHEADS, 0);
    }
}

// round 16
// speedup vs baseline: 2.5516x; 1.1870x over previous
#include <cuda_runtime.h>
#include <cuda_fp16.h>
#include <math.h>
#include <stdint.h>

#define S_LEN   2048
#define BATCH   2
#define NHEADS  32
#define NKV     8
#define HDIM    128
#define HID     4096
#define KVDIM   1024
#define M_ROWS  4096   // B*S
#define WINDOW  512    // SLIDING_WINDOW // 2
#define GK      4096   // GEMM K
#define NC      (GK/64)

// ======================== scratch buffers ==================================
__device__ __half g_X[(size_t)M_ROWS * HID];
__device__ __half g_WqT[(size_t)HID * HID];
__device__ __half g_WkT[(size_t)KVDIM * HID];
__device__ __half g_WvT[(size_t)KVDIM * HID];
__device__ __half g_WoT[(size_t)HID * HID];
__device__ __half g_O[(size_t)M_ROWS * HID];

// fp16 attention operands (RoPE'd), all single precision
__device__ __half g_Qb[(size_t)BATCH * NHEADS * S_LEN * HDIM];
__device__ __half g_Kb[(size_t)BATCH * NKV * S_LEN * HDIM];
__device__ __half g_Vt[(size_t)BATCH * NKV * HDIM * S_LEN];   // [b,hk,d,s]

// ======================= low-level helpers =================================
__device__ __forceinline__ uint32_t smem_u32(const void* p) {
    uint32_t a;
    asm("{ .reg .u64 t; cvta.to.shared.u64 t, %1; cvt.u32.u64 %0, t; }"
        : "=r"(a) : "l"(p));
    return a;
}
__device__ __forceinline__ void cpasync16(uint32_t saddr, const void* g) {
    asm volatile("cp.async.cg.shared.global [%0], [%1], 16;"
                 :: "r"(saddr), "l"(g) : "memory");
}
#define SWZ(o) ((o) ^ (((o) >> 3) & 0x70))

__device__ __forceinline__ void ldmx4(uint32_t* r, uint32_t addr) {
    asm volatile("ldmatrix.sync.aligned.m8n8.x4.shared.b16 {%0,%1,%2,%3}, [%4];"
                 : "=r"(r[0]), "=r"(r[1]), "=r"(r[2]), "=r"(r[3]) : "r"(addr));
}
__device__ __forceinline__ void mma16816h(float* d, const uint32_t* a, const uint32_t* b) {
    asm volatile("mma.sync.aligned.m16n8k16.row.col.f32.f16.f16.f32 "
                 "{%0,%1,%2,%3}, {%4,%5,%6,%7}, {%8,%9}, {%0,%1,%2,%3};"
                 : "+f"(d[0]), "+f"(d[1]), "+f"(d[2]), "+f"(d[3])
                 : "r"(a[0]), "r"(a[1]), "r"(a[2]), "r"(a[3]),
                   "r"(b[0]), "r"(b[1]));
}

// fast exp on FMA pipe
__device__ __forceinline__ float fast_exp(float x) {
    float y = x * 1.4426950408889634f;
    float r = rintf(y);
    float f = y - r;
    float p = 1.3697664e-3f;
    p = fmaf(p, f, 9.6784195e-3f);
    p = fmaf(p, f, 5.5503454e-2f);
    p = fmaf(p, f, 2.4022652e-1f);
    p = fmaf(p, f, 6.9314718e-1f);
    p = fmaf(p, f, 1.0f);
    int ri = (int)r;
    ri = ri < -126 ? -126 : (ri > 126 ? 126 : ri);
    float s = __int_as_float((uint32_t)(ri + 127) << 23);
    return p * s;
}

// ===================== convert / transpose preprocessing ====================
__global__ void convert_half_kernel(const float* __restrict__ X,
                                    __half* __restrict__ Y, int n4)
{
    int i = blockIdx.x * blockDim.x + threadIdx.x;
    if (i >= n4) return;
    float4 v = reinterpret_cast<const float4*>(X)[i];
    __half2* yp = reinterpret_cast<__half2*>(Y) + 2 * i;
    yp[0] = __halves2half2(__float2half_rn(v.x), __float2half_rn(v.y));
    yp[1] = __halves2half2(__float2half_rn(v.z), __float2half_rn(v.w));
}

// W [K, N] fp32 -> T [N, K] fp16
__global__ void transpose_half_kernel(const float* __restrict__ W,
                                      __half* __restrict__ T,
                                      int K, int N)
{
    __shared__ float t[32][33];
    int k0 = blockIdx.y * 32, n0 = blockIdx.x * 32;
    int c = threadIdx.x & 31, r = threadIdx.x >> 5;
#pragma unroll
    for (int p = 0; p < 32; p += 8)
        t[r + p][c] = W[(size_t)(k0 + r + p) * N + n0 + c];
    __syncthreads();
#pragma unroll
    for (int p = 0; p < 32; p += 8) {
        size_t o = (size_t)(n0 + r + p) * K + k0 + c;
        T[o] = __float2half_rn(t[c][r + p]);
    }
}

// ================= fp16 1-pass GEMM: C = A @ B^T ===========================
// CTA 128x128, 256 threads (8 warps 2x4), warp tile 64x32, K-chunk 64.
// 3-stage cp.async pipeline (32KB/stage), single sync per chunk.
// 2 CTAs per SM (launch_bounds minBlocks=2; regs capped at 128) so a
// co-resident CTA fills each chunk-boundary barrier drain.
// EMODE 0: C row-major fp32 [M,N].
// EMODE 3: transpose to Vt fp16 [b,NKV,d,s].  (tile = one head)
// EMODE 4: RoPE + scale + fp16, scatter to Ch [b,nH,s,d].
#define TILE_BYTES  16384
#define STAGE_BYTES (2 * TILE_BYTES)    // A, B
#define GEMM_SMEM   (3 * STAGE_BYTES)   // 96 KB
#define SPAD        132

__device__ __forceinline__ void load_stage_gemm(
    uint32_t stage_base, int tid, int mBase, int nBase, int kb,
    const __half* __restrict__ A, const __half* __restrict__ B)
{
#pragma unroll
    for (int u = 0; u < 4; ++u) {
        int unit = tid + u * 256;
        int r = unit >> 3, c16 = unit & 7;
        uint32_t sw = SWZ((uint32_t)(r * 128 + c16 * 16));
        size_t ga = (size_t)(mBase + r) * GK + kb + c16 * 8;
        size_t gb = (size_t)(nBase + r) * GK + kb + c16 * 8;
        cpasync16(stage_base + sw,              A + ga);
        cpasync16(stage_base + TILE_BYTES + sw, B + gb);
    }
    asm volatile("cp.async.commit_group;" ::: "memory");
}

__global__ void __launch_bounds__(256, 2) mma_gemm_kernel(
    const __half* __restrict__ A, const __half* __restrict__ B,
    float* __restrict__ C, __half* __restrict__ Ch,
    float ropeScale, int N, int nH, int EMODE)
{
    extern __shared__ __align__(1024) char smem_raw[];
    const uint32_t sbase = smem_u32(smem_raw);
    const int tid  = threadIdx.x;
    const int wid  = tid >> 5, lane = tid & 31;
    const int wm   = wid >> 2;            // 0..1 (64 rows)
    const int wn   = wid & 3;             // 0..3 (32 cols)
    const int mBase = blockIdx.y * 128;
    const int nBase = blockIdx.x * 128;

    float acc[4][4][4];
#pragma unroll
    for (int mt = 0; mt < 4; mt++)
#pragma unroll
        for (int nt = 0; nt < 4; nt++)
#pragma unroll
            for (int e = 0; e < 4; e++) acc[mt][nt][e] = 0.f;

    load_stage_gemm(sbase + 0 * STAGE_BYTES, tid, mBase, nBase, 0,  A, B);
    load_stage_gemm(sbase + 1 * STAGE_BYTES, tid, mBase, nBase, 64, A, B);

    const int aRow = wm * 64 + (lane & 15);
    const int aK8  = (lane >> 4);
    const int bm   = lane >> 3;            // x4 matrix slot 0..3
    const int bRowIn = lane & 7;

    for (int c2 = 0; c2 < NC; ++c2) {
        if (c2 + 1 < NC) asm volatile("cp.async.wait_group 1;" ::: "memory");
        else             asm volatile("cp.async.wait_group 0;" ::: "memory");
        __syncthreads();

        if (c2 + 2 < NC)
            load_stage_gemm(sbase + ((c2 + 2) % 3) * STAGE_BYTES, tid,
                            mBase, nBase, (c2 + 2) * 64, A, B);

        const uint32_t st  = sbase + (c2 % 3) * STAGE_BYTES;
        const uint32_t aB  = st;
        const uint32_t bB  = st + TILE_BYTES;

#pragma unroll
        for (int ks = 0; ks < 4; ks++) {
            uint32_t bh[4][2];
#pragma unroll
            for (int np = 0; np < 2; np++) {
                int nf2 = np * 2 + (bm >> 1);
                int brow = wn * 32 + nf2 * 8 + bRowIn;
                int dl = ks * 16 + (bm & 1) * 8;
                uint32_t sw = SWZ((uint32_t)(brow * 128 + dl * 2));
                uint32_t r4[4];
                ldmx4(r4, bB + sw);
                bh[np * 2][0] = r4[0];     bh[np * 2][1] = r4[1];
                bh[np * 2 + 1][0] = r4[2]; bh[np * 2 + 1][1] = r4[3];
            }
            const int ak = ks * 16 + aK8 * 8;
#pragma unroll
            for (int mt = 0; mt < 4; mt++) {
                uint32_t sw = SWZ((uint32_t)((aRow + mt * 16) * 128 + ak * 2));
                uint32_t ah[4];
                ldmx4(ah, aB + sw);
#pragma unroll
                for (int nt = 0; nt < 4; nt++)
                    mma16816h(acc[mt][nt], ah, bh[nt]);
            }
        }
    }

    const int row0 = wm * 64 + (lane >> 2);
    const int col0 = wn * 32 + (lane & 3) * 2;

    if (EMODE == 0) {
#pragma unroll
        for (int mt = 0; mt < 4; mt++)
#pragma unroll
            for (int half = 0; half < 2; half++) {
                int grow = mBase + row0 + mt * 16 + half * 8;
#pragma unroll
                for (int nt = 0; nt < 4; nt++) {
                    int gcol = nBase + col0 + nt * 8;
                    *reinterpret_cast<float2*>(C + (size_t)grow * N + gcol) =
                        make_float2(acc[mt][nt][half * 2], acc[mt][nt][half * 2 + 1]);
                }
            }
        return;
    }

    // stage accumulators to smem [128][SPAD]
    __syncthreads();
    float* stage = reinterpret_cast<float*>(smem_raw);
#pragma unroll
    for (int mt = 0; mt < 4; mt++)
#pragma unroll
        for (int half = 0; half < 2; half++) {
            int r = row0 + mt * 16 + half * 8;
#pragma unroll
            for (int nt = 0; nt < 4; nt++) {
                int c = col0 + nt * 8;
                stage[r * SPAD + c]     = acc[mt][nt][half * 2];
                stage[r * SPAD + c + 1] = acc[mt][nt][half * 2 + 1];
            }
        }
    __syncthreads();

    const int b = mBase >> 11;
    const int sBase = mBase & 2047;
    const int h = nBase >> 7;               // one head per 128-wide tile

    if (EMODE == 4) {
        const size_t headBase = ((size_t)(b * nH + h) * S_LEN) * HDIM;
#pragma unroll
        for (int it = 0; it < 32; it++) {
            int pr = tid + it * 256;           // 0..8191
            int r = pr >> 6, dp = pr & 63;
            float x1 = stage[r * SPAD + dp];
            float x2 = stage[r * SPAD + dp + 64];
            int srow = sBase + r;
            float inv_freq = exp2f(-(float)dp * (13.287712379549449f / 64.0f));
            float ang = (float)srow * inv_freq;
            float c, sn;
            sincosf(ang, &sn, &c);
            float y1 = (x1 * c - x2 * sn) * ropeScale;
            float y2 = (x2 * c + x1 * sn) * ropeScale;
            size_t base = headBase + (size_t)srow * HDIM;
            Ch[base + dp]      = __float2half_rn(y1);
            Ch[base + dp + 64] = __float2half_rn(y2);
        }
        return;
    }

    // EMODE 3: transpose to Vt fp16 [b,NKV,d,s] (tile = one head)
    {
        int s2 = (tid & 63) * 2;
        int g  = tid >> 6;                  // 0..3
#pragma unroll
        for (int it = 0; it < 32; it++) {
            int d = g * 32 + it;            // 0..127
            float f0 = stage[s2 * SPAD + d];
            float f1 = stage[(s2 + 1) * SPAD + d];
            size_t base = ((size_t)(b * NKV + h) * HDIM + d) * S_LEN + sBase + s2;
            *reinterpret_cast<__half2*>(g_Vt + base) =
                __halves2half2(__float2half_rn(f0), __float2half_rn(f1));
        }
    }
}

// ======== tensor-core flash attention (all single fp16, 1-pass) ============
#define AT_STAGE 32768
#define ATTN_SMEM 65536

__global__ void __launch_bounds__(256, 1) attn_mma_kernel()
{
    extern __shared__ __align__(1024) char smem_raw[];
    const uint32_t sb = smem_u32(smem_raw);
    const int tid = threadIdx.x, wid = tid >> 5, lane = tid & 31;
    const int qt = blockIdx.x, h = blockIdx.y, b = blockIdx.z;
    const int hk = h >> 2;
    const int q0 = qt * 128;
    const int bh = b * NHEADS + h, bhk = b * NKV + hk;

    const __half* Qg = g_Qb + ((size_t)bh * S_LEN + q0) * HDIM;
    const __half* Kg = g_Kb + (size_t)bhk * S_LEN * HDIM;
    const __half* Vg = g_Vt + (size_t)bhk * HDIM * S_LEN;

    // ---- stage Q (32KB: 2 subs of 16KB) ----
#pragma unroll
    for (int it = 0; it < 8; it++) {
        int u = tid + it * 256;
        int r = u >> 4, c16 = u & 15;
        int sub = c16 >> 3;
        uint32_t off = (uint32_t)(sub * 16384 + r * 128 + (c16 & 7) * 16);
        cpasync16(sb + SWZ(off), Qg + (size_t)r * HDIM + c16 * 8);
    }
    asm volatile("cp.async.commit_group;" ::: "memory");
    asm volatile("cp.async.wait_group 0;" ::: "memory");
    __syncthreads();

    uint32_t qh[8][4];
    {
        int row = wid * 16 + (lane & 15);
        int k8 = lane >> 4;
#pragma unroll
        for (int kf = 0; kf < 8; kf++) {
            int sub = kf >> 2;
            uint32_t off = (uint32_t)(sub * 16384 + row * 128 + ((kf & 3) * 16 + k8 * 8) * 2);
            ldmx4(qh[kf], sb + SWZ(off));
        }
    }
    __syncthreads();

    float o[16][4];
#pragma unroll
    for (int nf = 0; nf < 16; nf++)
#pragma unroll
        for (int e = 0; e < 4; e++) o[nf][e] = 0.f;

    float m0 = -1e30f, m1 = -1e30f, l0 = 0.f, l1 = 0.f;
    const int g0row = q0 + wid * 16 + (lane >> 2);

    int kt_lo = 2 * qt - 8; if (kt_lo < 0) kt_lo = 0;
    const int nt = 2 * qt + 1 - kt_lo + 1;

    auto load_kv = [&](int stage, int kt) {
        const int k0 = kt * 64;
        const uint32_t stb = sb + (uint32_t)stage * AT_STAGE;
#pragma unroll
        for (int it = 0; it < 8; it++) {
            int u = tid + it * 256;
            int buf = u >> 10;                 // 0 = K, 1 = Vt
            int w = u & 1023;
            int r = w >> 3, c16 = w & 7;
            uint32_t off = (uint32_t)(buf * 16384 + r * 128 + c16 * 16);
            const __half* g;
            if (buf == 0) {
                int key = r & 63, sub = r >> 6;
                g = Kg + (size_t)(k0 + key) * HDIM + sub * 64 + c16 * 8;
            } else {
                g = Vg + (size_t)r * S_LEN + k0 + c16 * 8;
            }
            cpasync16(stb + SWZ(off), g);
        }
        asm volatile("cp.async.commit_group;" ::: "memory");
    };

    load_kv(0, kt_lo);
    load_kv(1, kt_lo + 1);

    for (int i = 0; i < nt; i++) {
        const int kt = kt_lo + i;
        const int k0 = kt * 64;
        if (i + 1 < nt) asm volatile("cp.async.wait_group 1;" ::: "memory");
        else            asm volatile("cp.async.wait_group 0;" ::: "memory");
        __syncthreads();
        const uint32_t stb = sb + (uint32_t)(i & 1) * AT_STAGE;

        // ---- S = Q K^T (1-pass) ----
        float s[8][4];
#pragma unroll
        for (int nf = 0; nf < 8; nf++)
#pragma unroll
            for (int e = 0; e < 4; e++) s[nf][e] = 0.f;

#pragma unroll
        for (int kf = 0; kf < 8; kf++) {
            const int sub = kf >> 2;
            const int klocal = (kf & 3) * 16;
            uint32_t kb[8][2];
#pragma unroll
            for (int np = 0; np < 4; np++) {
                int m = lane >> 3;
                int nf2 = np * 2 + (m >> 1);
                int key = nf2 * 8 + (lane & 7);
                int dl = klocal + (m & 1) * 8;
                uint32_t off = (uint32_t)((sub * 64 + key) * 128 + dl * 2);
                uint32_t r4[4];
                ldmx4(r4, stb + SWZ(off));
                kb[np * 2][0] = r4[0]; kb[np * 2][1] = r4[1];
                kb[np * 2 + 1][0] = r4[2]; kb[np * 2 + 1][1] = r4[3];
            }
#pragma unroll
            for (int nf = 0; nf < 8; nf++)
                mma16816h(s[nf], qh[kf], kb[nf]);
        }

        if ((k0 + 63 > q0) || (q0 + 127 - k0 > WINDOW)) {
#pragma unroll
            for (int nf = 0; nf < 8; nf++)
#pragma unroll
                for (int e = 0; e < 4; e++) {
                    int row = g0row + ((e >= 2) ? 8 : 0);
                    int col = k0 + nf * 8 + (lane & 3) * 2 + (e & 1);
                    if (col > row || row - col > WINDOW) s[nf][e] = -1e30f;
                }
        }

        float mx0 = -1e30f, mx1 = -1e30f;
#pragma unroll
        for (int nf = 0; nf < 8; nf++) {
            mx0 = fmaxf(mx0, fmaxf(s[nf][0], s[nf][1]));
            mx1 = fmaxf(mx1, fmaxf(s[nf][2], s[nf][3]));
        }
        mx0 = fmaxf(mx0, __shfl_xor_sync(0xffffffffu, mx0, 1));
        mx0 = fmaxf(mx0, __shfl_xor_sync(0xffffffffu, mx0, 2));
        mx1 = fmaxf(mx1, __shfl_xor_sync(0xffffffffu, mx1, 1));
        mx1 = fmaxf(mx1, __shfl_xor_sync(0xffffffffu, mx1, 2));
        float mn0 = fmaxf(m0, mx0), mn1 = fmaxf(m1, mx1);
        float fac0 = fast_exp(m0 - mn0), fac1 = fast_exp(m1 - mn1);
        m0 = mn0; m1 = mn1;

        uint32_t ph[8][2];
        float ps0 = 0.f, ps1 = 0.f;
#pragma unroll
        for (int nf = 0; nf < 8; nf++) {
            float p0 = fast_exp(s[nf][0] - mn0);
            float p1 = fast_exp(s[nf][1] - mn0);
            float p2 = fast_exp(s[nf][2] - mn1);
            float p3 = fast_exp(s[nf][3] - mn1);
            ps0 += p0 + p1; ps1 += p2 + p3;
            __half2 t;
            t = __halves2half2(__float2half_rn(p0), __float2half_rn(p1));
            ph[nf][0] = *reinterpret_cast<uint32_t*>(&t);
            t = __halves2half2(__float2half_rn(p2), __float2half_rn(p3));
            ph[nf][1] = *reinterpret_cast<uint32_t*>(&t);
        }
        ps0 += __shfl_xor_sync(0xffffffffu, ps0, 1);
        ps0 += __shfl_xor_sync(0xffffffffu, ps0, 2);
        ps1 += __shfl_xor_sync(0xffffffffu, ps1, 1);
        ps1 += __shfl_xor_sync(0xffffffffu, ps1, 2);
        l0 = l0 * fac0 + ps0;
        l1 = l1 * fac1 + ps1;

#pragma unroll
        for (int nf = 0; nf < 16; nf++) {
            o[nf][0] *= fac0; o[nf][1] *= fac0;
            o[nf][2] *= fac1; o[nf][3] *= fac1;
        }

        // ---- O += P @ Vt (1-pass) ----
#pragma unroll
        for (int kf2 = 0; kf2 < 4; kf2++) {
            uint32_t pah[4] = { ph[2 * kf2][0], ph[2 * kf2][1],
                                ph[2 * kf2 + 1][0], ph[2 * kf2 + 1][1] };
#pragma unroll
            for (int np = 0; np < 8; np++) {
                int m = lane >> 3;
                int drow = (np * 2 + (m >> 1)) * 8 + (lane & 7);
                int kl = kf2 * 16 + (m & 1) * 8;
                uint32_t off = (uint32_t)(16384 + drow * 128 + kl * 2);
                uint32_t r4[4];
                ldmx4(r4, stb + SWZ(off));
                uint32_t vb0[2] = { r4[0], r4[1] }, vb1[2] = { r4[2], r4[3] };
                mma16816h(o[np * 2],     pah, vb0);
                mma16816h(o[np * 2 + 1], pah, vb1);
            }
        }
        __syncthreads();
        if (i + 2 < nt) load_kv(i & 1, kt + 2);
    }

    // ---- write O as single fp16 row-major [m, h*128+d] ----
    const float inv0 = 1.f / l0, inv1 = 1.f / l1;
    const int r0 = wid * 16 + (lane >> 2);
    const int c0 = (lane & 3) * 2;
    const size_t rowA = ((size_t)(b * S_LEN + q0 + r0)) * HID + h * HDIM;
    const size_t rowB = ((size_t)(b * S_LEN + q0 + r0 + 8)) * HID + h * HDIM;
#pragma unroll
    for (int nf = 0; nf < 16; nf++) {
        int d = nf * 8 + c0;
        *reinterpret_cast<__half2*>(g_O + rowA + d) =
            __halves2half2(__float2half_rn(o[nf][0] * inv0),
                           __float2half_rn(o[nf][1] * inv0));
        *reinterpret_cast<__half2*>(g_O + rowB + d) =
            __halves2half2(__float2half_rn(o[nf][2] * inv1),
                           __float2half_rn(o[nf][3] * inv1));
    }
}

// ---------------------------------------------------------------------------
extern "C" void kernel_launch(void* const* d_in, const int* in_sizes, int n_in,
                              void* d_out, int out_size)
{
    (void)in_sizes; (void)n_in; (void)out_size;
    const float* hidden = (const float*)d_in[0];
    const float* Wq     = (const float*)d_in[1];
    const float* Wk     = (const float*)d_in[2];
    const float* Wv     = (const float*)d_in[3];
    const float* Wo     = (const float*)d_in[4];
    float* out          = (float*)d_out;

    __half *x, *wq, *wk, *wv, *wo, *ob, *qb, *kb;
    cudaGetSymbolAddress((void**)&x, g_X);
    cudaGetSymbolAddress((void**)&wq, g_WqT);   cudaGetSymbolAddress((void**)&wk, g_WkT);
    cudaGetSymbolAddress((void**)&wv, g_WvT);   cudaGetSymbolAddress((void**)&wo, g_WoT);
    cudaGetSymbolAddress((void**)&ob, g_O);
    cudaGetSymbolAddress((void**)&qb, g_Qb);    cudaGetSymbolAddress((void**)&kb, g_Kb);

    cudaFuncSetAttribute(mma_gemm_kernel,
                         cudaFuncAttributeMaxDynamicSharedMemorySize, GEMM_SMEM);
    cudaFuncSetAttribute(attn_mma_kernel,
                         cudaFuncAttributeMaxDynamicSharedMemorySize, ATTN_SMEM);

    static bool inited = false;
    static cudaStream_t s1, s2;
    static cudaEvent_t evRoot, evWq, evX, evK, evV;
    if (!inited) {
        cudaStreamCreateWithFlags(&s1, cudaStreamNonBlocking);
        cudaStreamCreateWithFlags(&s2, cudaStreamNonBlocking);
        cudaEventCreateWithFlags(&evRoot, cudaEventDisableTiming);
        cudaEventCreateWithFlags(&evWq,   cudaEventDisableTiming);
        cudaEventCreateWithFlags(&evX,    cudaEventDisableTiming);
        cudaEventCreateWithFlags(&evK,    cudaEventDisableTiming);
        cudaEventCreateWithFlags(&evV,    cudaEventDisableTiming);
        inited = true;
    }

    const float qscale = 1.0f / sqrtf((float)HDIM);

    cudaEventRecord(evRoot, 0);
    cudaStreamWaitEvent(s1, evRoot, 0);
    cudaStreamWaitEvent(s2, evRoot, 0);

    // s1: Wq transpose -> evWq ; Wk transpose
    {
        dim3 gq(HID / 32, HID / 32);
        transpose_half_kernel<<<gq, 256, 0, s1>>>(Wq, wq, HID, HID);
        cudaEventRecord(evWq, s1);
        dim3 gkv(KVDIM / 32, HID / 32);
        transpose_half_kernel<<<gkv, 256, 0, s1>>>(Wk, wk, HID, KVDIM);
    }
    // s2: Wv transpose ; Wo transpose
    {
        dim3 gkv(KVDIM / 32, HID / 32);
        transpose_half_kernel<<<gkv, 256, 0, s2>>>(Wv, wv, HID, KVDIM);
        dim3 go(HID / 32, HID / 32);
        transpose_half_kernel<<<go, 256, 0, s2>>>(Wo, wo, HID, HID);
    }
    // s0: convert X -> evX
    {
        int n4 = (M_ROWS * HID) / 4;
        convert_half_kernel<<<(n4 + 255) / 256, 256>>>(hidden, x, n4);
        cudaEventRecord(evX, 0);
    }
    // s0: Q projection (EMODE 4: RoPE + scale + fp16)
    {
        cudaStreamWaitEvent(0, evWq, 0);
        dim3 g(HID / 128, M_ROWS / 128);
        mma_gemm_kernel<<<g, 256, GEMM_SMEM>>>(x, wq, nullptr, qb,
                                               qscale, HID, NHEADS, 4);
    }
    // s1: K projection (EMODE 4: RoPE + fp16)
    {
        cudaStreamWaitEvent(s1, evX, 0);
        dim3 g(KVDIM / 128, M_ROWS / 128);
        mma_gemm_kernel<<<g, 256, GEMM_SMEM, s1>>>(x, wk, nullptr, kb,
                                                   1.0f, KVDIM, NKV, 4);
        cudaEventRecord(evK, s1);
    }
    // s2: V projection (EMODE 3: fp16 Vt)
    {
        cudaStreamWaitEvent(s2, evX, 0);
        dim3 g(KVDIM / 128, M_ROWS / 128);
        mma_gemm_kernel<<<g, 256, GEMM_SMEM, s2>>>(x, wv, nullptr, nullptr,
                                                   0.f, KVDIM, NKV, 3);
        cudaEventRecord(evV, s2);
    }
    // s0: attention
    {
        cudaStreamWaitEvent(0, evK, 0);
        cudaStreamWaitEvent(0, evV, 0);
        dim3 g(S_LEN / 128, NHEADS, BATCH);
        attn_mma_kernel<<<g, 256, ATTN_SMEM>>>();
    }
    // s0: output projection (EMODE 0: fp32 out)
    {
        dim3 go(HID / 128, M_ROWS / 128);
        mma_gemm_kernel<<<go, 256, GEMM_SMEM>>>(ob, wo, out, nullptr,
                                                0.f, HID, NHEADS, 0);
    }
}